// round 1
// baseline (speedup 1.0000x reference)
#include <cuda_runtime.h>
#include <cuda_bf16.h>
#include <cstdint>

// ---------------- problem constants ----------------
#define BATCH 16
#define CDIM  512
#define HH    56
#define WW    56
#define NTOK  3136          // 56*56
#define HEADS 8
#define HDIM  64
#define AGENT 49
#define MALL  (BATCH*NTOK)  // 50176

// ---------------- scratch (static device memory; no allocation) ----------------
__device__ float g_q[MALL*CDIM];
__device__ float g_k[MALL*CDIM];
__device__ float g_v[MALL*CDIM];
__device__ float g_o[MALL*CDIM];
__device__ float g_logits[BATCH*HEADS*AGENT*NTOK];
__device__ float g_agent[BATCH*AGENT*CDIM];
__device__ float g_agentv[BATCH*HEADS*AGENT*HDIM];
__device__ float g_pb[HEADS*AGENT*NTOK];
__device__ float g_ab[HEADS*NTOK*AGENT];

// ---------------- SGEMM: C[m,n] = sum_k A[m,k]*W[n,k] (+bias[n]) ----------------
// A: M x K row-major,  W: N x K row-major (i.e. computes A @ W^T)
// 128x128 tile, BK=8, 256 threads, 8x8 per thread in 4+4 split (conflict-free frags)
__global__ __launch_bounds__(256) void sgemm_nt(
    const float* __restrict__ A, const float* __restrict__ W,
    float* __restrict__ C, int M, int N, int K, const float* __restrict__ bias)
{
    __shared__ __align__(16) float As[8][128];
    __shared__ __align__(16) float Ws[8][128];
    const int bm = blockIdx.x * 128;
    const int bn = blockIdx.y * 128;
    const int tid = threadIdx.x;
    const int lrow = tid >> 1;
    const int lcol = (tid & 1) * 4;
    const int tm = (tid >> 4) * 4;
    const int tn = (tid & 15) * 4;

    float acc[2][2][4][4];
#pragma unroll
    for (int pm = 0; pm < 2; pm++)
#pragma unroll
        for (int pn = 0; pn < 2; pn++)
#pragma unroll
            for (int i = 0; i < 4; i++)
#pragma unroll
                for (int j = 0; j < 4; j++) acc[pm][pn][i][j] = 0.f;

    const float* Aptr = A + (size_t)(bm + lrow) * K + lcol;
    const float* Wptr = W + (size_t)(bn + lrow) * K + lcol;

    for (int k0 = 0; k0 < K; k0 += 8) {
        float4 av = *(const float4*)(Aptr + k0);
        float4 wv = *(const float4*)(Wptr + k0);
        __syncthreads();
        As[lcol + 0][lrow] = av.x; As[lcol + 1][lrow] = av.y;
        As[lcol + 2][lrow] = av.z; As[lcol + 3][lrow] = av.w;
        Ws[lcol + 0][lrow] = wv.x; Ws[lcol + 1][lrow] = wv.y;
        Ws[lcol + 2][lrow] = wv.z; Ws[lcol + 3][lrow] = wv.w;
        __syncthreads();
#pragma unroll
        for (int kk = 0; kk < 8; kk++) {
            float a0[4], a1[4], b0[4], b1[4];
            *(float4*)a0 = *(const float4*)&As[kk][tm];
            *(float4*)a1 = *(const float4*)&As[kk][tm + 64];
            *(float4*)b0 = *(const float4*)&Ws[kk][tn];
            *(float4*)b1 = *(const float4*)&Ws[kk][tn + 64];
#pragma unroll
            for (int i = 0; i < 4; i++)
#pragma unroll
                for (int j = 0; j < 4; j++) {
                    acc[0][0][i][j] += a0[i] * b0[j];
                    acc[0][1][i][j] += a0[i] * b1[j];
                    acc[1][0][i][j] += a1[i] * b0[j];
                    acc[1][1][i][j] += a1[i] * b1[j];
                }
        }
    }

#pragma unroll
    for (int pm = 0; pm < 2; pm++)
#pragma unroll
        for (int i = 0; i < 4; i++) {
            size_t m = (size_t)(bm + pm * 64 + tm + i);
#pragma unroll
            for (int pn = 0; pn < 2; pn++) {
                int ncol = bn + pn * 64 + tn;
                float4 v;
                v.x = acc[pm][pn][i][0]; v.y = acc[pm][pn][i][1];
                v.z = acc[pm][pn][i][2]; v.w = acc[pm][pn][i][3];
                if (bias) {
                    v.x += bias[ncol]; v.y += bias[ncol + 1];
                    v.z += bias[ncol + 2]; v.w += bias[ncol + 3];
                }
                *(float4*)&C[m * N + ncol] = v;
            }
        }
}

// ---------------- agent token pooling: mean over 8x8 spatial blocks of q ----------------
__global__ __launch_bounds__(512) void pool_kernel(const float* __restrict__ q,
                                                   float* __restrict__ ag)
{
    int c = threadIdx.x;
    int b = blockIdx.x / AGENT;
    int a = blockIdx.x % AGENT;
    int p1 = a / 7, p2 = a % 7;
    float s = 0.f;
#pragma unroll
    for (int i = 0; i < 8; i++)
#pragma unroll
        for (int j = 0; j < 8; j++)
            s += q[((size_t)b * NTOK + (p1 * 8 + i) * WW + (p2 * 8 + j)) * CDIM + c];
    ag[((size_t)b * AGENT + a) * CDIM + c] = s * (1.0f / 64.0f);
}

// ---------------- bias precompute: bilinear(7x7 -> 56x56, jax half-pixel) + axis biases --
__global__ __launch_bounds__(256) void bias_kernel(
    const float* __restrict__ an, const float* __restrict__ na,
    const float* __restrict__ ahb, const float* __restrict__ awb,
    const float* __restrict__ hab, const float* __restrict__ wab,
    float* __restrict__ pb, float* __restrict__ ab)
{
    int h = blockIdx.x / AGENT;
    int a = blockIdx.x % AGENT;
    __shared__ float ans[49], nas[49];
    int tid = threadIdx.x;
    if (tid < 49) {
        ans[tid] = an[((size_t)h * AGENT + a) * 49 + tid];
        nas[tid] = na[((size_t)h * AGENT + a) * 49 + tid];
    }
    __syncthreads();
    for (int n = tid; n < NTOK; n += 256) {
        int y = n / WW, x = n % WW;
        float fy = (y + 0.5f) * 0.125f - 0.5f;
        float fx = (x + 0.5f) * 0.125f - 0.5f;
        int iy = (int)floorf(fy); float ty = fy - iy;
        int ix = (int)floorf(fx); float tx = fx - ix;
        float wy0 = 1.f - ty, wy1 = ty;
        int y0 = iy, y1 = iy + 1;
        if (y0 < 0) { wy0 = 0.f; y0 = 0; }
        if (y1 > 6) { wy1 = 0.f; y1 = 6; }
        float sy = wy0 + wy1; wy0 /= sy; wy1 /= sy;
        float wx0 = 1.f - tx, wx1 = tx;
        int x0 = ix, x1 = ix + 1;
        if (x0 < 0) { wx0 = 0.f; x0 = 0; }
        if (x1 > 6) { wx1 = 0.f; x1 = 6; }
        float sx = wx0 + wx1; wx0 /= sx; wx1 /= sx;

        float bi_an = wy0 * (wx0 * ans[y0 * 7 + x0] + wx1 * ans[y0 * 7 + x1]) +
                      wy1 * (wx0 * ans[y1 * 7 + x0] + wx1 * ans[y1 * 7 + x1]);
        float bi_na = wy0 * (wx0 * nas[y0 * 7 + x0] + wx1 * nas[y0 * 7 + x1]) +
                      wy1 * (wx0 * nas[y1 * 7 + x0] + wx1 * nas[y1 * 7 + x1]);

        pb[((size_t)h * AGENT + a) * NTOK + n] =
            bi_an + ahb[((size_t)h * AGENT + a) * 56 + y] + awb[((size_t)h * AGENT + a) * 56 + x];
        ab[((size_t)h * NTOK + n) * AGENT + a] =
            bi_na + hab[((size_t)h * 56 + y) * AGENT + a] + wab[((size_t)h * 56 + x) * AGENT + a];
    }
}

// ---------------- agent logits: (ah*scale) @ kh^T + pb  ->  g_logits[bh][a][n] ------------
__global__ __launch_bounds__(256) void agent_logits_kernel(
    const float* __restrict__ ag, const float* __restrict__ kmat,
    const float* __restrict__ pb, float* __restrict__ lg)
{
    int bh = blockIdx.y; int b = bh >> 3, h = bh & 7;
    int n0 = blockIdx.x * 64;
    __shared__ __align__(16) float ahs[49][64];
    __shared__ __align__(16) float ks[64][65];
    int tid = threadIdx.x;
    for (int i = tid; i < 49 * 64; i += 256) {
        int a = i >> 6, d = i & 63;
        ahs[a][d] = ag[((size_t)b * AGENT + a) * CDIM + h * 64 + d] * 0.125f;
    }
    for (int i = tid; i < 64 * 16; i += 256) {
        int n = i >> 4, d4 = (i & 15) * 4;
        float4 v = *(const float4*)&kmat[((size_t)b * NTOK + n0 + n) * CDIM + h * 64 + d4];
        ks[n][d4] = v.x; ks[n][d4 + 1] = v.y; ks[n][d4 + 2] = v.z; ks[n][d4 + 3] = v.w;
    }
    __syncthreads();
    int nl = tid & 63;
    int abase = tid >> 6;
    float acc[13];
#pragma unroll
    for (int i = 0; i < 13; i++) acc[i] = 0.f;
#pragma unroll 8
    for (int d = 0; d < 64; d++) {
        float kd = ks[nl][d];
        int a = abase;
#pragma unroll
        for (int i = 0; i < 13; i++) { if (a < 49) acc[i] += ahs[a][d] * kd; a += 4; }
    }
    int a = abase;
#pragma unroll
    for (int i = 0; i < 13; i++) {
        if (a < 49)
            lg[((size_t)bh * AGENT + a) * NTOK + n0 + nl] =
                acc[i] + pb[((size_t)h * AGENT + a) * NTOK + n0 + nl];
        a += 4;
    }
}

// ---------------- softmax over n=3136 for each of 6272 rows --------------------------------
__global__ __launch_bounds__(256) void softmax_kernel(float* __restrict__ lg)
{
    float* p = lg + (size_t)blockIdx.x * NTOK;
    int tid = threadIdx.x;
    float vals[13];
    float m = -1e30f;
#pragma unroll
    for (int j = 0; j < 13; j++) {
        int i = tid + j * 256;
        vals[j] = (i < NTOK) ? p[i] : -1e30f;
        m = fmaxf(m, vals[j]);
    }
    __shared__ float red[256];
    red[tid] = m; __syncthreads();
    for (int s = 128; s > 0; s >>= 1) { if (tid < s) red[tid] = fmaxf(red[tid], red[tid + s]); __syncthreads(); }
    m = red[0]; __syncthreads();
    float sum = 0.f;
#pragma unroll
    for (int j = 0; j < 13; j++) { vals[j] = __expf(vals[j] - m); sum += vals[j]; }
    red[tid] = sum; __syncthreads();
    for (int s = 128; s > 0; s >>= 1) { if (tid < s) red[tid] += red[tid + s]; __syncthreads(); }
    float inv = 1.0f / red[0];
#pragma unroll
    for (int j = 0; j < 13; j++) {
        int i = tid + j * 256;
        if (i < NTOK) p[i] = vals[j] * inv;
    }
}

// ---------------- agent_v = attn @ vh : per (b,h) 49x64 output, K=3136 ---------------------
__global__ __launch_bounds__(256) void agent_v_kernel(
    const float* __restrict__ lg, const float* __restrict__ vmat, float* __restrict__ av)
{
    int bh = blockIdx.x; int b = bh >> 3, h = bh & 7;
    __shared__ __align__(16) float ps[49][64];
    __shared__ __align__(16) float vs[64][65];
    int tid = threadIdx.x;
    int d = tid & 63, abase = tid >> 6;
    float acc[13];
#pragma unroll
    for (int i = 0; i < 13; i++) acc[i] = 0.f;
    for (int n0 = 0; n0 < NTOK; n0 += 64) {
        __syncthreads();
        for (int i = tid; i < 49 * 64; i += 256) {
            int a = i >> 6, nn = i & 63;
            ps[a][nn] = lg[((size_t)bh * AGENT + a) * NTOK + n0 + nn];
        }
        for (int i = tid; i < 64 * 16; i += 256) {
            int nn = i >> 4, d4 = (i & 15) * 4;
            float4 v = *(const float4*)&vmat[((size_t)b * NTOK + n0 + nn) * CDIM + h * 64 + d4];
            vs[nn][d4] = v.x; vs[nn][d4 + 1] = v.y; vs[nn][d4 + 2] = v.z; vs[nn][d4 + 3] = v.w;
        }
        __syncthreads();
#pragma unroll 8
        for (int nn = 0; nn < 64; nn++) {
            float vd = vs[nn][d];
            int a = abase;
#pragma unroll
            for (int i = 0; i < 13; i++) { if (a < 49) acc[i] += ps[a][nn] * vd; a += 4; }
        }
    }
    int a = abase;
#pragma unroll
    for (int i = 0; i < 13; i++) {
        if (a < 49) av[((size_t)bh * AGENT + a) * HDIM + d] = acc[i];
        a += 4;
    }
}

// ---------------- q attention (fused logits+softmax+out), per token ------------------------
__global__ __launch_bounds__(224) void qattn_kernel(
    const float* __restrict__ qmat, const float* __restrict__ ag,
    const float* __restrict__ av, const float* __restrict__ ab, float* __restrict__ o)
{
    int bh = blockIdx.y; int b = bh >> 3, h = bh & 7;
    int tid = threadIdx.x;
    int n = blockIdx.x * 224 + tid;
    __shared__ __align__(16) float ahs[49][64];
    __shared__ __align__(16) float avs[49][64];
    for (int i = tid; i < 49 * 16; i += 224) {
        int a = i >> 4, d4 = (i & 15) * 4;
        *(float4*)&ahs[a][d4] = *(const float4*)&ag[((size_t)b * AGENT + a) * CDIM + h * 64 + d4];
        *(float4*)&avs[a][d4] = *(const float4*)&av[((size_t)bh * AGENT + a) * HDIM + d4];
    }
    __syncthreads();

    float4 qv[16];
    const float4* qrow = (const float4*)&qmat[((size_t)b * NTOK + n) * CDIM + h * 64];
#pragma unroll
    for (int i = 0; i < 16; i++) qv[i] = qrow[i];

    float l[49];
    const float* abrow = &ab[((size_t)h * NTOK + n) * AGENT];
#pragma unroll
    for (int a = 0; a < 49; a++) {
        float s = 0.f;
#pragma unroll
        for (int i = 0; i < 16; i++) {
            float4 hv = *(const float4*)&ahs[a][i * 4];
            s += qv[i].x * hv.x + qv[i].y * hv.y + qv[i].z * hv.z + qv[i].w * hv.w;
        }
        l[a] = s * 0.125f + abrow[a];
    }
    float m = -1e30f;
#pragma unroll
    for (int a = 0; a < 49; a++) m = fmaxf(m, l[a]);
    float sum = 0.f;
#pragma unroll
    for (int a = 0; a < 49; a++) { l[a] = __expf(l[a] - m); sum += l[a]; }
    float inv = 1.0f / sum;
#pragma unroll
    for (int a = 0; a < 49; a++) l[a] *= inv;

    float* orow = &o[((size_t)b * NTOK + n) * CDIM + h * 64];
#pragma unroll
    for (int i = 0; i < 16; i++) {
        float4 acc = {0.f, 0.f, 0.f, 0.f};
#pragma unroll
        for (int a = 0; a < 49; a++) {
            float4 hv = *(const float4*)&avs[a][i * 4];
            acc.x += l[a] * hv.x; acc.y += l[a] * hv.y;
            acc.z += l[a] * hv.z; acc.w += l[a] * hv.w;
        }
        *(float4*)&orow[i * 4] = acc;
    }
}

// ---------------- depthwise 3x3 conv on v (channels-last), accumulate into o ---------------
__global__ __launch_bounds__(512) void dwc_kernel(
    const float* __restrict__ v, const float* __restrict__ w,
    const float* __restrict__ bias, float* __restrict__ o)
{
    int c = threadIdx.x;
    int n = blockIdx.x;
    int b = blockIdx.y;
    int y = n / WW, x = n % WW;
    float acc = bias[c];
#pragma unroll
    for (int dy = -1; dy <= 1; dy++) {
        int yy = y + dy; if (yy < 0 || yy >= HH) continue;
#pragma unroll
        for (int dx = -1; dx <= 1; dx++) {
            int xx = x + dx; if (xx < 0 || xx >= WW) continue;
            acc += v[((size_t)b * NTOK + yy * WW + xx) * CDIM + c] *
                   w[c * 9 + (dy + 1) * 3 + (dx + 1)];
        }
    }
    o[((size_t)b * NTOK + n) * CDIM + c] += acc;
}

// ---------------- launch ----------------
extern "C" void kernel_launch(void* const* d_in, const int* in_sizes, int n_in,
                              void* d_out, int out_size)
{
    const float* x      = (const float*)d_in[0];
    // d_in[1]=H, d_in[2]=W (ints, fixed)
    const float* q_w    = (const float*)d_in[3];
    const float* kv_w   = (const float*)d_in[4];
    const float* proj_w = (const float*)d_in[5];
    const float* proj_b = (const float*)d_in[6];
    const float* dwc_w  = (const float*)d_in[7];
    const float* dwc_b  = (const float*)d_in[8];
    const float* an_b   = (const float*)d_in[9];
    const float* na_b   = (const float*)d_in[10];
    const float* ah_b   = (const float*)d_in[11];
    const float* aw_b   = (const float*)d_in[12];
    const float* ha_b   = (const float*)d_in[13];
    const float* wa_b   = (const float*)d_in[14];
    float* out = (float*)d_out;

    float *qp, *kp, *vp, *op, *lg, *agp, *avp, *pbp, *abp;
    cudaGetSymbolAddress((void**)&qp,  g_q);
    cudaGetSymbolAddress((void**)&kp,  g_k);
    cudaGetSymbolAddress((void**)&vp,  g_v);
    cudaGetSymbolAddress((void**)&op,  g_o);
    cudaGetSymbolAddress((void**)&lg,  g_logits);
    cudaGetSymbolAddress((void**)&agp, g_agent);
    cudaGetSymbolAddress((void**)&avp, g_agentv);
    cudaGetSymbolAddress((void**)&pbp, g_pb);
    cudaGetSymbolAddress((void**)&abp, g_ab);

    dim3 gproj(MALL / 128, CDIM / 128);
    // q / k / v projections (kv_w rows [0,512) -> k, [512,1024) -> v)
    sgemm_nt<<<gproj, 256>>>(x, q_w, qp, MALL, CDIM, CDIM, nullptr);
    sgemm_nt<<<gproj, 256>>>(x, kv_w, kp, MALL, CDIM, CDIM, nullptr);
    sgemm_nt<<<gproj, 256>>>(x, kv_w + CDIM * CDIM, vp, MALL, CDIM, CDIM, nullptr);

    pool_kernel<<<BATCH * AGENT, CDIM>>>(qp, agp);
    bias_kernel<<<HEADS * AGENT, 256>>>(an_b, na_b, ah_b, aw_b, ha_b, wa_b, pbp, abp);

    agent_logits_kernel<<<dim3(NTOK / 64, BATCH * HEADS), 256>>>(agp, kp, pbp, lg);
    softmax_kernel<<<BATCH * HEADS * AGENT, 256>>>(lg);
    agent_v_kernel<<<BATCH * HEADS, 256>>>(lg, vp, avp);

    qattn_kernel<<<dim3(NTOK / 224, BATCH * HEADS), 224>>>(qp, agp, avp, abp, op);
    dwc_kernel<<<dim3(NTOK, BATCH), CDIM>>>(vp, dwc_w, dwc_b, op);

    // final projection + bias, straight into d_out (raw reshape)
    sgemm_nt<<<gproj, 256>>>(op, proj_w, out, MALL, CDIM, CDIM, proj_b);
}

// round 4
// speedup vs baseline: 1.3458x; 1.3458x over previous
#include <cuda_runtime.h>
#include <cuda_bf16.h>
#include <cstdint>

// ---------------- problem constants ----------------
#define BATCH 16
#define CDIM  512
#define HH    56
#define WW    56
#define NTOK  3136          // 56*56
#define HEADS 8
#define HDIM  64
#define AGENT 49
#define MALL  (BATCH*NTOK)  // 50176

// ---------------- scratch (static device memory; no allocation) ----------------
__device__ float g_q[MALL*CDIM];
__device__ float g_k[MALL*CDIM];
__device__ float g_v[MALL*CDIM];
__device__ float g_o[MALL*CDIM];
__device__ float g_logits[BATCH*HEADS*AGENT*NTOK];
__device__ float g_agent[BATCH*AGENT*CDIM];
__device__ float g_agentv[BATCH*HEADS*AGENT*HDIM];
__device__ float g_pb[HEADS*AGENT*NTOK];
__device__ float g_ab[HEADS*NTOK*AGENT];

// ================= tf32 helpers =================
__device__ __forceinline__ uint32_t f2tf32(float f) {
    uint32_t u;
    asm("cvt.rna.tf32.f32 %0, %1;" : "=r"(u) : "f"(f));
    return u;
}

__device__ __forceinline__ void mma_16x8x8(float* d, const uint32_t* a, const uint32_t* b) {
    asm volatile(
        "mma.sync.aligned.m16n8k8.row.col.f32.tf32.tf32.f32 "
        "{%0,%1,%2,%3}, {%4,%5,%6,%7}, {%8,%9}, {%0,%1,%2,%3};"
        : "+f"(d[0]), "+f"(d[1]), "+f"(d[2]), "+f"(d[3])
        : "r"(a[0]), "r"(a[1]), "r"(a[2]), "r"(a[3]), "r"(b[0]), "r"(b[1]));
}

// ======= tf32 tensor-core GEMM: C[m,n] = sum_k A[m,k]*W[n,k] (+bias[n]) =======
// A: M x 512 row-major.  W: 512 x 512 row-major (computes A @ W^T).  M % 128 == 0.
// Block tile 128x128, BK=32, 256 threads (8 warps 2x4, warp tile 64x32).
#define BK 32
#define LDT 36                      // BK + 4 pad: conflict-free frag loads
#define TILE_WORDS (128 * LDT)      // one operand tile
#define GEMM_SMEM (4 * TILE_WORDS * 4)  // 2 stages x (A,B) = 73728 bytes

__global__ __launch_bounds__(256) void mma_gemm(
    const float* __restrict__ A, const float* __restrict__ W,
    float* __restrict__ C, const float* __restrict__ bias)
{
    extern __shared__ float sm[];
    float* As[2] = { sm,                  sm + 2 * TILE_WORDS };
    float* Bs[2] = { sm + TILE_WORDS,     sm + 3 * TILE_WORDS };

    const int tid  = threadIdx.x;
    const int wid  = tid >> 5;
    const int lane = tid & 31;
    const int wm   = (wid >> 2) * 64;    // warp m offset within block tile
    const int wn   = (wid & 3) * 32;     // warp n offset
    const int g    = lane >> 2;          // group id 0..7
    const int tg   = lane & 3;           // thread in group 0..3
    const int bm = blockIdx.y * 128;
    const int bn = blockIdx.x * 128;

    // global load geometry: 4 float4 per operand per BK-chunk
    const float* aP[4];
    const float* wP[4];
    int sr[4], sc[4];
#pragma unroll
    for (int i = 0; i < 4; i++) {
        int id = i * 256 + tid;          // 0..1023 float4 slots
        int r = id >> 3, c4 = id & 7;    // row 0..127, col4 0..7
        aP[i] = A + (size_t)(bm + r) * 512 + c4 * 4;
        wP[i] = W + (size_t)(bn + r) * 512 + c4 * 4;
        sr[i] = r; sc[i] = c4 * 4;
    }

    float acc[4][4][4];
#pragma unroll
    for (int mi = 0; mi < 4; mi++)
#pragma unroll
        for (int ni = 0; ni < 4; ni++)
#pragma unroll
            for (int j = 0; j < 4; j++) acc[mi][ni][j] = 0.f;

    float4 ra[4], rb[4];
#pragma unroll
    for (int i = 0; i < 4; i++) { ra[i] = *(const float4*)aP[i]; rb[i] = *(const float4*)wP[i]; }

    int s = 0;
    for (int kc = 0; kc < 16; kc++) {
        // convert + stage into smem
#pragma unroll
        for (int i = 0; i < 4; i++) {
            float* a = &As[s][sr[i] * LDT + sc[i]];
            a[0] = __uint_as_float(f2tf32(ra[i].x));
            a[1] = __uint_as_float(f2tf32(ra[i].y));
            a[2] = __uint_as_float(f2tf32(ra[i].z));
            a[3] = __uint_as_float(f2tf32(ra[i].w));
            float* b = &Bs[s][sr[i] * LDT + sc[i]];
            b[0] = __uint_as_float(f2tf32(rb[i].x));
            b[1] = __uint_as_float(f2tf32(rb[i].y));
            b[2] = __uint_as_float(f2tf32(rb[i].z));
            b[3] = __uint_as_float(f2tf32(rb[i].w));
        }
        __syncthreads();
        if (kc + 1 < 16) {
            int koff = (kc + 1) * BK;
#pragma unroll
            for (int i = 0; i < 4; i++) {
                ra[i] = *(const float4*)(aP[i] + koff);
                rb[i] = *(const float4*)(wP[i] + koff);
            }
        }
        const float* Af = As[s];
        const float* Bf = Bs[s];
#pragma unroll
        for (int ks = 0; ks < 4; ks++) {
            const int kb = ks * 8 + tg;
            uint32_t af[4][4], bf[4][2];
#pragma unroll
            for (int mi = 0; mi < 4; mi++) {
                int r0 = wm + mi * 16 + g;
                af[mi][0] = __float_as_uint(Af[r0 * LDT + kb]);
                af[mi][1] = __float_as_uint(Af[(r0 + 8) * LDT + kb]);
                af[mi][2] = __float_as_uint(Af[r0 * LDT + kb + 4]);
                af[mi][3] = __float_as_uint(Af[(r0 + 8) * LDT + kb + 4]);
            }
#pragma unroll
            for (int ni = 0; ni < 4; ni++) {
                int n0 = wn + ni * 8 + g;
                bf[ni][0] = __float_as_uint(Bf[n0 * LDT + kb]);
                bf[ni][1] = __float_as_uint(Bf[n0 * LDT + kb + 4]);
            }
#pragma unroll
            for (int mi = 0; mi < 4; mi++)
#pragma unroll
                for (int ni = 0; ni < 4; ni++)
                    mma_16x8x8(acc[mi][ni], af[mi], bf[ni]);
        }
        __syncthreads();
        s ^= 1;
    }

    // epilogue
#pragma unroll
    for (int mi = 0; mi < 4; mi++) {
        int row = bm + wm + mi * 16 + g;
#pragma unroll
        for (int ni = 0; ni < 4; ni++) {
            int col = bn + wn + ni * 8 + 2 * tg;
            float b0 = 0.f, b1 = 0.f;
            if (bias) { b0 = bias[col]; b1 = bias[col + 1]; }
            float2 v0 = { acc[mi][ni][0] + b0, acc[mi][ni][1] + b1 };
            float2 v1 = { acc[mi][ni][2] + b0, acc[mi][ni][3] + b1 };
            *(float2*)&C[(size_t)row * 512 + col] = v0;
            *(float2*)&C[(size_t)(row + 8) * 512 + col] = v1;
        }
    }
}

// ---------------- agent token pooling: mean over 8x8 spatial blocks of q ----------------
__global__ __launch_bounds__(512) void pool_kernel(const float* __restrict__ q,
                                                   float* __restrict__ ag)
{
    int c = threadIdx.x;
    int b = blockIdx.x / AGENT;
    int a = blockIdx.x % AGENT;
    int p1 = a / 7, p2 = a % 7;
    float s = 0.f;
#pragma unroll
    for (int i = 0; i < 8; i++)
#pragma unroll
        for (int j = 0; j < 8; j++)
            s += q[((size_t)b * NTOK + (p1 * 8 + i) * WW + (p2 * 8 + j)) * CDIM + c];
    ag[((size_t)b * AGENT + a) * CDIM + c] = s * (1.0f / 64.0f);
}

// ---------------- bias precompute: bilinear(7x7 -> 56x56, jax half-pixel) + axis biases --
__global__ __launch_bounds__(256) void bias_kernel(
    const float* __restrict__ an, const float* __restrict__ na,
    const float* __restrict__ ahb, const float* __restrict__ awb,
    const float* __restrict__ hab, const float* __restrict__ wab,
    float* __restrict__ pb, float* __restrict__ ab)
{
    int h = blockIdx.x / AGENT;
    int a = blockIdx.x % AGENT;
    __shared__ float ans[49], nas[49];
    int tid = threadIdx.x;
    if (tid < 49) {
        ans[tid] = an[((size_t)h * AGENT + a) * 49 + tid];
        nas[tid] = na[((size_t)h * AGENT + a) * 49 + tid];
    }
    __syncthreads();
    for (int n = tid; n < NTOK; n += 256) {
        int y = n / WW, x = n % WW;
        float fy = (y + 0.5f) * 0.125f - 0.5f;
        float fx = (x + 0.5f) * 0.125f - 0.5f;
        int iy = (int)floorf(fy); float ty = fy - iy;
        int ix = (int)floorf(fx); float tx = fx - ix;
        float wy0 = 1.f - ty, wy1 = ty;
        int y0 = iy, y1 = iy + 1;
        if (y0 < 0) { wy0 = 0.f; y0 = 0; }
        if (y1 > 6) { wy1 = 0.f; y1 = 6; }
        float sy = wy0 + wy1; wy0 /= sy; wy1 /= sy;
        float wx0 = 1.f - tx, wx1 = tx;
        int x0 = ix, x1 = ix + 1;
        if (x0 < 0) { wx0 = 0.f; x0 = 0; }
        if (x1 > 6) { wx1 = 0.f; x1 = 6; }
        float sx = wx0 + wx1; wx0 /= sx; wx1 /= sx;

        float bi_an = wy0 * (wx0 * ans[y0 * 7 + x0] + wx1 * ans[y0 * 7 + x1]) +
                      wy1 * (wx0 * ans[y1 * 7 + x0] + wx1 * ans[y1 * 7 + x1]);
        float bi_na = wy0 * (wx0 * nas[y0 * 7 + x0] + wx1 * nas[y0 * 7 + x1]) +
                      wy1 * (wx0 * nas[y1 * 7 + x0] + wx1 * nas[y1 * 7 + x1]);

        pb[((size_t)h * AGENT + a) * NTOK + n] =
            bi_an + ahb[((size_t)h * AGENT + a) * 56 + y] + awb[((size_t)h * AGENT + a) * 56 + x];
        ab[((size_t)h * NTOK + n) * AGENT + a] =
            bi_na + hab[((size_t)h * 56 + y) * AGENT + a] + wab[((size_t)h * 56 + x) * AGENT + a];
    }
}

// ---------------- agent logits: (ah*scale) @ kh^T + pb  ->  g_logits[bh][a][n] ------------
__global__ __launch_bounds__(256) void agent_logits_kernel(
    const float* __restrict__ ag, const float* __restrict__ kmat,
    const float* __restrict__ pb, float* __restrict__ lg)
{
    int bh = blockIdx.y; int b = bh >> 3, h = bh & 7;
    int n0 = blockIdx.x * 64;
    __shared__ __align__(16) float ahs[49][64];
    __shared__ __align__(16) float ks[64][65];
    int tid = threadIdx.x;
    for (int i = tid; i < 49 * 64; i += 256) {
        int a = i >> 6, d = i & 63;
        ahs[a][d] = ag[((size_t)b * AGENT + a) * CDIM + h * 64 + d] * 0.125f;
    }
    for (int i = tid; i < 64 * 16; i += 256) {
        int n = i >> 4, d4 = (i & 15) * 4;
        float4 v = *(const float4*)&kmat[((size_t)b * NTOK + n0 + n) * CDIM + h * 64 + d4];
        ks[n][d4] = v.x; ks[n][d4 + 1] = v.y; ks[n][d4 + 2] = v.z; ks[n][d4 + 3] = v.w;
    }
    __syncthreads();
    int nl = tid & 63;
    int abase = tid >> 6;
    float acc[13];
#pragma unroll
    for (int i = 0; i < 13; i++) acc[i] = 0.f;
#pragma unroll 8
    for (int d = 0; d < 64; d++) {
        float kd = ks[nl][d];
        int a = abase;
#pragma unroll
        for (int i = 0; i < 13; i++) { if (a < 49) acc[i] += ahs[a][d] * kd; a += 4; }
    }
    int a = abase;
#pragma unroll
    for (int i = 0; i < 13; i++) {
        if (a < 49)
            lg[((size_t)bh * AGENT + a) * NTOK + n0 + nl] =
                acc[i] + pb[((size_t)h * AGENT + a) * NTOK + n0 + nl];
        a += 4;
    }
}

// ---------------- softmax over n=3136 for each of 6272 rows --------------------------------
__global__ __launch_bounds__(256) void softmax_kernel(float* __restrict__ lg)
{
    float* p = lg + (size_t)blockIdx.x * NTOK;
    int tid = threadIdx.x;
    float vals[13];
    float m = -1e30f;
#pragma unroll
    for (int j = 0; j < 13; j++) {
        int i = tid + j * 256;
        vals[j] = (i < NTOK) ? p[i] : -1e30f;
        m = fmaxf(m, vals[j]);
    }
    __shared__ float red[256];
    red[tid] = m; __syncthreads();
    for (int s = 128; s > 0; s >>= 1) { if (tid < s) red[tid] = fmaxf(red[tid], red[tid + s]); __syncthreads(); }
    m = red[0]; __syncthreads();
    float sum = 0.f;
#pragma unroll
    for (int j = 0; j < 13; j++) { vals[j] = __expf(vals[j] - m); sum += vals[j]; }
    red[tid] = sum; __syncthreads();
    for (int s = 128; s > 0; s >>= 1) { if (tid < s) red[tid] += red[tid + s]; __syncthreads(); }
    float inv = 1.0f / red[0];
#pragma unroll
    for (int j = 0; j < 13; j++) {
        int i = tid + j * 256;
        if (i < NTOK) p[i] = vals[j] * inv;
    }
}

// ---------------- agent_v = attn @ vh : per (b,h) 49x64 output, K=3136 ---------------------
__global__ __launch_bounds__(256) void agent_v_kernel(
    const float* __restrict__ lg, const float* __restrict__ vmat, float* __restrict__ av)
{
    int bh = blockIdx.x; int b = bh >> 3, h = bh & 7;
    __shared__ __align__(16) float ps[49][64];
    __shared__ __align__(16) float vs[64][65];
    int tid = threadIdx.x;
    int d = tid & 63, abase = tid >> 6;
    float acc[13];
#pragma unroll
    for (int i = 0; i < 13; i++) acc[i] = 0.f;
    for (int n0 = 0; n0 < NTOK; n0 += 64) {
        __syncthreads();
        for (int i = tid; i < 49 * 64; i += 256) {
            int a = i >> 6, nn = i & 63;
            ps[a][nn] = lg[((size_t)bh * AGENT + a) * NTOK + n0 + nn];
        }
        for (int i = tid; i < 64 * 16; i += 256) {
            int nn = i >> 4, d4 = (i & 15) * 4;
            float4 v = *(const float4*)&vmat[((size_t)b * NTOK + n0 + nn) * CDIM + h * 64 + d4];
            vs[nn][d4] = v.x; vs[nn][d4 + 1] = v.y; vs[nn][d4 + 2] = v.z; vs[nn][d4 + 3] = v.w;
        }
        __syncthreads();
#pragma unroll 8
        for (int nn = 0; nn < 64; nn++) {
            float vd = vs[nn][d];
            int a = abase;
#pragma unroll
            for (int i = 0; i < 13; i++) { if (a < 49) acc[i] += ps[a][nn] * vd; a += 4; }
        }
    }
    int a = abase;
#pragma unroll
    for (int i = 0; i < 13; i++) {
        if (a < 49) av[((size_t)bh * AGENT + a) * HDIM + d] = acc[i];
        a += 4;
    }
}

// ---------------- q attention (fused logits+softmax+out), per token ------------------------
__global__ __launch_bounds__(224) void qattn_kernel(
    const float* __restrict__ qmat, const float* __restrict__ ag,
    const float* __restrict__ av, const float* __restrict__ ab, float* __restrict__ o)
{
    int bh = blockIdx.y; int b = bh >> 3, h = bh & 7;
    int tid = threadIdx.x;
    int n = blockIdx.x * 224 + tid;
    __shared__ __align__(16) float ahs[49][64];
    __shared__ __align__(16) float avs[49][64];
    for (int i = tid; i < 49 * 16; i += 224) {
        int a = i >> 4, d4 = (i & 15) * 4;
        *(float4*)&ahs[a][d4] = *(const float4*)&ag[((size_t)b * AGENT + a) * CDIM + h * 64 + d4];
        *(float4*)&avs[a][d4] = *(const float4*)&av[((size_t)bh * AGENT + a) * HDIM + d4];
    }
    __syncthreads();

    float4 qv[16];
    const float4* qrow = (const float4*)&qmat[((size_t)b * NTOK + n) * CDIM + h * 64];
#pragma unroll
    for (int i = 0; i < 16; i++) qv[i] = qrow[i];

    float l[49];
    const float* abrow = &ab[((size_t)h * NTOK + n) * AGENT];
#pragma unroll
    for (int a = 0; a < 49; a++) {
        float s = 0.f;
#pragma unroll
        for (int i = 0; i < 16; i++) {
            float4 hv = *(const float4*)&ahs[a][i * 4];
            s += qv[i].x * hv.x + qv[i].y * hv.y + qv[i].z * hv.z + qv[i].w * hv.w;
        }
        l[a] = s * 0.125f + abrow[a];
    }
    float m = -1e30f;
#pragma unroll
    for (int a = 0; a < 49; a++) m = fmaxf(m, l[a]);
    float sum = 0.f;
#pragma unroll
    for (int a = 0; a < 49; a++) { l[a] = __expf(l[a] - m); sum += l[a]; }
    float inv = 1.0f / sum;
#pragma unroll
    for (int a = 0; a < 49; a++) l[a] *= inv;

    float* orow = &o[((size_t)b * NTOK + n) * CDIM + h * 64];
#pragma unroll
    for (int i = 0; i < 16; i++) {
        float4 acc = {0.f, 0.f, 0.f, 0.f};
#pragma unroll
        for (int a = 0; a < 49; a++) {
            float4 hv = *(const float4*)&avs[a][i * 4];
            acc.x += l[a] * hv.x; acc.y += l[a] * hv.y;
            acc.z += l[a] * hv.z; acc.w += l[a] * hv.w;
        }
        *(float4*)&orow[i * 4] = acc;
    }
}

// ---------------- depthwise 3x3 conv on v (channels-last), accumulate into o ---------------
__global__ __launch_bounds__(512) void dwc_kernel(
    const float* __restrict__ v, const float* __restrict__ w,
    const float* __restrict__ bias, float* __restrict__ o)
{
    int c = threadIdx.x;
    int n = blockIdx.x;
    int b = blockIdx.y;
    int y = n / WW, x = n % WW;
    float acc = bias[c];
#pragma unroll
    for (int dy = -1; dy <= 1; dy++) {
        int yy = y + dy; if (yy < 0 || yy >= HH) continue;
#pragma unroll
        for (int dx = -1; dx <= 1; dx++) {
            int xx = x + dx; if (xx < 0 || xx >= WW) continue;
            acc += v[((size_t)b * NTOK + yy * WW + xx) * CDIM + c] *
                   w[c * 9 + (dy + 1) * 3 + (dx + 1)];
        }
    }
    o[((size_t)b * NTOK + n) * CDIM + c] += acc;
}

// ---------------- launch ----------------
extern "C" void kernel_launch(void* const* d_in, const int* in_sizes, int n_in,
                              void* d_out, int out_size)
{
    const float* x      = (const float*)d_in[0];
    const float* q_w    = (const float*)d_in[3];
    const float* kv_w   = (const float*)d_in[4];
    const float* proj_w = (const float*)d_in[5];
    const float* proj_b = (const float*)d_in[6];
    const float* dwc_w  = (const float*)d_in[7];
    const float* dwc_b  = (const float*)d_in[8];
    const float* an_b   = (const float*)d_in[9];
    const float* na_b   = (const float*)d_in[10];
    const float* ah_b   = (const float*)d_in[11];
    const float* aw_b   = (const float*)d_in[12];
    const float* ha_b   = (const float*)d_in[13];
    const float* wa_b   = (const float*)d_in[14];
    float* out = (float*)d_out;

    float *qp, *kp, *vp, *op, *lg, *agp, *avp, *pbp, *abp;
    cudaGetSymbolAddress((void**)&qp,  g_q);
    cudaGetSymbolAddress((void**)&kp,  g_k);
    cudaGetSymbolAddress((void**)&vp,  g_v);
    cudaGetSymbolAddress((void**)&op,  g_o);
    cudaGetSymbolAddress((void**)&lg,  g_logits);
    cudaGetSymbolAddress((void**)&agp, g_agent);
    cudaGetSymbolAddress((void**)&avp, g_agentv);
    cudaGetSymbolAddress((void**)&pbp, g_pb);
    cudaGetSymbolAddress((void**)&abp, g_ab);

    cudaFuncSetAttribute(mma_gemm, cudaFuncAttributeMaxDynamicSharedMemorySize, GEMM_SMEM);

    dim3 ggrid(CDIM / 128, MALL / 128);   // x = N tiles, y = M tiles
    mma_gemm<<<ggrid, 256, GEMM_SMEM>>>(x, q_w, qp, nullptr);
    mma_gemm<<<ggrid, 256, GEMM_SMEM>>>(x, kv_w, kp, nullptr);
    mma_gemm<<<ggrid, 256, GEMM_SMEM>>>(x, kv_w + CDIM * CDIM, vp, nullptr);

    pool_kernel<<<BATCH * AGENT, CDIM>>>(qp, agp);
    bias_kernel<<<HEADS * AGENT, 256>>>(an_b, na_b, ah_b, aw_b, ha_b, wa_b, pbp, abp);

    agent_logits_kernel<<<dim3(NTOK / 64, BATCH * HEADS), 256>>>(agp, kp, pbp, lg);
    softmax_kernel<<<BATCH * HEADS * AGENT, 256>>>(lg);
    agent_v_kernel<<<BATCH * HEADS, 256>>>(lg, vp, avp);

    qattn_kernel<<<dim3(NTOK / 224, BATCH * HEADS), 224>>>(qp, agp, avp, abp, op);
    dwc_kernel<<<dim3(NTOK, BATCH), CDIM>>>(vp, dwc_w, dwc_b, op);

    mma_gemm<<<ggrid, 256, GEMM_SMEM>>>(op, proj_w, out, proj_b);
}

// round 6
// speedup vs baseline: 1.5340x; 1.1398x over previous
#include <cuda_runtime.h>
#include <cuda_bf16.h>
#include <cstdint>

// ---------------- problem constants ----------------
#define BATCH 16
#define CDIM  512
#define HH    56
#define WW    56
#define NTOK  3136          // 56*56
#define HEADS 8
#define HDIM  64
#define AGENT 49
#define MALL  (BATCH*NTOK)  // 50176
#define SPLITS 7
#define NSPL  448           // NTOK / SPLITS

// ---------------- scratch (static device memory; no allocation) ----------------
__device__ float g_q[MALL*CDIM];
__device__ float g_k[MALL*CDIM];
__device__ float g_v[MALL*CDIM];
__device__ float g_o[MALL*CDIM];
__device__ float g_part[SPLITS*BATCH*HEADS*AGENT*(HDIM+2) + 1024]; // partial acc + (m,s)
__device__ float g_agent[BATCH*AGENT*CDIM];
__device__ float g_agentv[BATCH*HEADS*AGENT*HDIM];
__device__ float g_pb[HEADS*AGENT*NTOK];
__device__ float g_ab[HEADS*NTOK*AGENT];

// ================= tf32 helpers =================
__device__ __forceinline__ uint32_t f2tf32(float f) {
    uint32_t u;
    asm("cvt.rna.tf32.f32 %0, %1;" : "=r"(u) : "f"(f));
    return u;
}

__device__ __forceinline__ void mma_16x8x8(float* d, const uint32_t* a, const uint32_t* b) {
    asm volatile(
        "mma.sync.aligned.m16n8k8.row.col.f32.tf32.tf32.f32 "
        "{%0,%1,%2,%3}, {%4,%5,%6,%7}, {%8,%9}, {%0,%1,%2,%3};"
        : "+f"(d[0]), "+f"(d[1]), "+f"(d[2]), "+f"(d[3])
        : "r"(a[0]), "r"(a[1]), "r"(a[2]), "r"(a[3]), "r"(b[0]), "r"(b[1]));
}

// ======= tf32 tensor-core GEMM: C[m,n] = sum_k A[m,k]*W[n,k] (+bias[n]) =======
// Block tile 128x128, BK=32, 256 threads (8 warps 2x4, warp tile 64x32).
// Smem: XOR-swizzled, row stride 32 words, float4 column group xored with row&7.
#define BK 32
#define TILE_WORDS (128 * 32)
#define GEMM_SMEM (4 * TILE_WORDS * 4)  // 2 stages x (A,B) = 65536 bytes

__global__ __launch_bounds__(256) void mma_gemm(
    const float* __restrict__ A, const float* __restrict__ W,
    float* __restrict__ C, const float* __restrict__ bias)
{
    extern __shared__ float sm[];
    float* As[2] = { sm,                  sm + 2 * TILE_WORDS };
    float* Bs[2] = { sm + TILE_WORDS,     sm + 3 * TILE_WORDS };

    const int tid  = threadIdx.x;
    const int wid  = tid >> 5;
    const int lane = tid & 31;
    const int wm   = (wid >> 2) * 64;    // warp m offset
    const int wn   = (wid & 3) * 32;     // warp n offset
    const int g    = lane >> 2;          // 0..7
    const int tg   = lane & 3;           // 0..3
    const int bm = blockIdx.y * 128;
    const int bn = blockIdx.x * 128;

    // global load geometry: 4 float4 per operand per BK-chunk
    const float* aP[4];
    const float* wP[4];
    int soff[4];
#pragma unroll
    for (int i = 0; i < 4; i++) {
        int id = i * 256 + tid;          // 0..1023 float4 slots
        int r = id >> 3, c4 = id & 7;    // row 0..127, col-group 0..7
        aP[i] = A + (size_t)(bm + r) * 512 + c4 * 4;
        wP[i] = W + (size_t)(bn + r) * 512 + c4 * 4;
        soff[i] = r * 32 + ((c4 ^ (r & 7)) << 2);   // swizzled word offset
    }

    float acc[4][4][4];
#pragma unroll
    for (int mi = 0; mi < 4; mi++)
#pragma unroll
        for (int ni = 0; ni < 4; ni++)
#pragma unroll
            for (int j = 0; j < 4; j++) acc[mi][ni][j] = 0.f;

    float4 ra[4], rb[4];
#pragma unroll
    for (int i = 0; i < 4; i++) { ra[i] = *(const float4*)aP[i]; rb[i] = *(const float4*)wP[i]; }

    int s = 0;
    for (int kc = 0; kc < 16; kc++) {
        // convert + stage into smem (vectorized, swizzled)
#pragma unroll
        for (int i = 0; i < 4; i++) {
            uint4 ua, ub;
            ua.x = f2tf32(ra[i].x); ua.y = f2tf32(ra[i].y);
            ua.z = f2tf32(ra[i].z); ua.w = f2tf32(ra[i].w);
            ub.x = f2tf32(rb[i].x); ub.y = f2tf32(rb[i].y);
            ub.z = f2tf32(rb[i].z); ub.w = f2tf32(rb[i].w);
            *(uint4*)&As[s][soff[i]] = ua;
            *(uint4*)&Bs[s][soff[i]] = ub;
        }
        __syncthreads();
        if (kc + 1 < 16) {
            int koff = (kc + 1) * BK;
#pragma unroll
            for (int i = 0; i < 4; i++) {
                ra[i] = *(const float4*)(aP[i] + koff);
                rb[i] = *(const float4*)(wP[i] + koff);
            }
        }
        const float* Af = As[s];
        const float* Bf = Bs[s];
#pragma unroll
        for (int ks = 0; ks < 4; ks++) {
            const int x0 = (((2 * ks)     ^ g) << 2) + tg;
            const int x1 = (((2 * ks + 1) ^ g) << 2) + tg;
            uint32_t af[4][4], bf[4][2];
#pragma unroll
            for (int mi = 0; mi < 4; mi++) {
                int r0 = wm + mi * 16 + g;
                af[mi][0] = __float_as_uint(Af[r0 * 32 + x0]);
                af[mi][1] = __float_as_uint(Af[(r0 + 8) * 32 + x0]);
                af[mi][2] = __float_as_uint(Af[r0 * 32 + x1]);
                af[mi][3] = __float_as_uint(Af[(r0 + 8) * 32 + x1]);
            }
#pragma unroll
            for (int ni = 0; ni < 4; ni++) {
                int n0 = wn + ni * 8 + g;
                bf[ni][0] = __float_as_uint(Bf[n0 * 32 + x0]);
                bf[ni][1] = __float_as_uint(Bf[n0 * 32 + x1]);
            }
#pragma unroll
            for (int mi = 0; mi < 4; mi++)
#pragma unroll
                for (int ni = 0; ni < 4; ni++)
                    mma_16x8x8(acc[mi][ni], af[mi], bf[ni]);
        }
        __syncthreads();
        s ^= 1;
    }

    // epilogue
#pragma unroll
    for (int mi = 0; mi < 4; mi++) {
        int row = bm + wm + mi * 16 + g;
#pragma unroll
        for (int ni = 0; ni < 4; ni++) {
            int col = bn + wn + ni * 8 + 2 * tg;
            float b0 = 0.f, b1 = 0.f;
            if (bias) { b0 = bias[col]; b1 = bias[col + 1]; }
            float2 v0 = { acc[mi][ni][0] + b0, acc[mi][ni][1] + b1 };
            float2 v1 = { acc[mi][ni][2] + b0, acc[mi][ni][3] + b1 };
            *(float2*)&C[(size_t)row * 512 + col] = v0;
            *(float2*)&C[(size_t)(row + 8) * 512 + col] = v1;
        }
    }
}

// ---------------- agent token pooling: mean over 8x8 spatial blocks of q ----------------
__global__ __launch_bounds__(512) void pool_kernel(const float* __restrict__ q,
                                                   float* __restrict__ ag)
{
    int c = threadIdx.x;
    int b = blockIdx.x / AGENT;
    int a = blockIdx.x % AGENT;
    int p1 = a / 7, p2 = a % 7;
    float s = 0.f;
#pragma unroll
    for (int i = 0; i < 8; i++)
#pragma unroll
        for (int j = 0; j < 8; j++)
            s += q[((size_t)b * NTOK + (p1 * 8 + i) * WW + (p2 * 8 + j)) * CDIM + c];
    ag[((size_t)b * AGENT + a) * CDIM + c] = s * (1.0f / 64.0f);
}

// ---------------- bias precompute: bilinear(7x7 -> 56x56, jax half-pixel) + axis biases --
__global__ __launch_bounds__(256) void bias_kernel(
    const float* __restrict__ an, const float* __restrict__ na,
    const float* __restrict__ ahb, const float* __restrict__ awb,
    const float* __restrict__ hab, const float* __restrict__ wab,
    float* __restrict__ pb, float* __restrict__ ab)
{
    int h = blockIdx.x / AGENT;
    int a = blockIdx.x % AGENT;
    __shared__ float ans[49], nas[49];
    int tid = threadIdx.x;
    if (tid < 49) {
        ans[tid] = an[((size_t)h * AGENT + a) * 49 + tid];
        nas[tid] = na[((size_t)h * AGENT + a) * 49 + tid];
    }
    __syncthreads();
    for (int n = tid; n < NTOK; n += 256) {
        int y = n / WW, x = n % WW;
        float fy = (y + 0.5f) * 0.125f - 0.5f;
        float fx = (x + 0.5f) * 0.125f - 0.5f;
        int iy = (int)floorf(fy); float ty = fy - iy;
        int ix = (int)floorf(fx); float tx = fx - ix;
        float wy0 = 1.f - ty, wy1 = ty;
        int y0 = iy, y1 = iy + 1;
        if (y0 < 0) { wy0 = 0.f; y0 = 0; }
        if (y1 > 6) { wy1 = 0.f; y1 = 6; }
        float sy = wy0 + wy1; wy0 /= sy; wy1 /= sy;
        float wx0 = 1.f - tx, wx1 = tx;
        int x0 = ix, x1 = ix + 1;
        if (x0 < 0) { wx0 = 0.f; x0 = 0; }
        if (x1 > 6) { wx1 = 0.f; x1 = 6; }
        float sx = wx0 + wx1; wx0 /= sx; wx1 /= sx;

        float bi_an = wy0 * (wx0 * ans[y0 * 7 + x0] + wx1 * ans[y0 * 7 + x1]) +
                      wy1 * (wx0 * ans[y1 * 7 + x0] + wx1 * ans[y1 * 7 + x1]);
        float bi_na = wy0 * (wx0 * nas[y0 * 7 + x0] + wx1 * nas[y0 * 7 + x1]) +
                      wy1 * (wx0 * nas[y1 * 7 + x0] + wx1 * nas[y1 * 7 + x1]);

        pb[((size_t)h * AGENT + a) * NTOK + n] =
            bi_an + ahb[((size_t)h * AGENT + a) * 56 + y] + awb[((size_t)h * AGENT + a) * 56 + x];
        ab[((size_t)h * NTOK + n) * AGENT + a] =
            bi_na + hab[((size_t)h * 56 + y) * AGENT + a] + wab[((size_t)h * 56 + x) * AGENT + a];
    }
}

// ============ fused agent attention: logits + softmax + attn@V, split over n ============
// grid (SPLITS, B*H), 256 threads. Per CTA: n-range [s*448, s*448+448).
// Writes partial acc[49][64] and per-a (max, sum) to g_part.
#define AF_SMEM ((AGENT*HDIM + HDIM*65 + AGENT*NSPL) * 4)   // 3136+4160+21952 words

__global__ __launch_bounds__(256) void agent_fused_kernel(
    const float* __restrict__ ag, const float* __restrict__ kmat,
    const float* __restrict__ vmat, const float* __restrict__ pb,
    float* __restrict__ part)
{
    extern __shared__ float smf[];
    float* ahs = smf;                    // [49][64]
    float* kvb = ahs + AGENT * HDIM;     // [64][65] staging (k, then v)
    float* L   = kvb + HDIM * 65;        // [49][448] logits -> exp values
    __shared__ float sm_m[AGENT], sm_s[AGENT];

    const int s  = blockIdx.x;
    const int bh = blockIdx.y;
    const int b = bh >> 3, h = bh & 7;
    const int tid = threadIdx.x;
    const int nl = tid & 63, abase = tid >> 6;
    const int n0base = s * NSPL;

    for (int i = tid; i < AGENT * HDIM; i += 256) {
        int a = i >> 6, d = i & 63;
        ahs[i] = ag[((size_t)b * AGENT + a) * CDIM + h * 64 + d] * 0.125f;
    }

    // ---- Phase 1: logits into smem L ----
    for (int c = 0; c < 7; c++) {
        int n0 = n0base + c * 64;
        __syncthreads();
        for (int i = tid; i < 64 * 16; i += 256) {
            int nn = i >> 4, d4 = (i & 15) * 4;
            float4 v = *(const float4*)&kmat[((size_t)b * NTOK + n0 + nn) * CDIM + h * 64 + d4];
            kvb[nn * 65 + d4] = v.x; kvb[nn * 65 + d4 + 1] = v.y;
            kvb[nn * 65 + d4 + 2] = v.z; kvb[nn * 65 + d4 + 3] = v.w;
        }
        __syncthreads();
        float acc[13];
#pragma unroll
        for (int i = 0; i < 13; i++) acc[i] = 0.f;
#pragma unroll 8
        for (int d = 0; d < 64; d++) {
            float kd = kvb[nl * 65 + d];
            int a = abase;
#pragma unroll
            for (int i = 0; i < 13; i++) { if (a < 49) acc[i] += ahs[a * 64 + d] * kd; a += 4; }
        }
        int a = abase;
#pragma unroll
        for (int i = 0; i < 13; i++) {
            if (a < 49)
                L[a * NSPL + c * 64 + nl] = acc[i] + pb[((size_t)h * AGENT + a) * NTOK + n0 + nl];
            a += 4;
        }
    }
    __syncthreads();

    // ---- Phase 2: per-a max & sum over this split; L <- exp(L - m) ----
    {
        int w = tid >> 5, lane = tid & 31;
        for (int a = w; a < AGENT; a += 8) {
            float m = -1e30f;
            for (int j = lane; j < NSPL; j += 32) m = fmaxf(m, L[a * NSPL + j]);
#pragma unroll
            for (int o = 16; o > 0; o >>= 1) m = fmaxf(m, __shfl_xor_sync(0xffffffffu, m, o));
            float sum = 0.f;
            for (int j = lane; j < NSPL; j += 32) {
                float e = __expf(L[a * NSPL + j] - m);
                L[a * NSPL + j] = e;
                sum += e;
            }
#pragma unroll
            for (int o = 16; o > 0; o >>= 1) sum += __shfl_xor_sync(0xffffffffu, sum, o);
            if (lane == 0) { sm_m[a] = m; sm_s[a] = sum; }
        }
    }
    __syncthreads();

    // ---- Phase 3: partial acc[a][d] = sum_n expL * v[n][d] ----
    float acc[13];
#pragma unroll
    for (int i = 0; i < 13; i++) acc[i] = 0.f;
    const int d = nl;
    for (int c = 0; c < 7; c++) {
        int n0 = n0base + c * 64;
        __syncthreads();
        for (int i = tid; i < 64 * 16; i += 256) {
            int nn = i >> 4, d4 = (i & 15) * 4;
            float4 v = *(const float4*)&vmat[((size_t)b * NTOK + n0 + nn) * CDIM + h * 64 + d4];
            kvb[nn * 65 + d4] = v.x; kvb[nn * 65 + d4 + 1] = v.y;
            kvb[nn * 65 + d4 + 2] = v.z; kvb[nn * 65 + d4 + 3] = v.w;
        }
        __syncthreads();
#pragma unroll 8
        for (int nn = 0; nn < 64; nn++) {
            float vd = kvb[nn * 65 + d];
            int a = abase;
#pragma unroll
            for (int i = 0; i < 13; i++) { if (a < 49) acc[i] += L[a * NSPL + c * 64 + nn] * vd; a += 4; }
        }
    }

    // ---- write partials: layout acc [s][bh][49][64], then (m,s) pairs appended ----
    float* pacc = part;
    float* pms  = part + (size_t)SPLITS * 128 * AGENT * HDIM;
    {
        int a = abase;
#pragma unroll
        for (int i = 0; i < 13; i++) {
            if (a < 49) pacc[(((size_t)s * 128 + bh) * AGENT + a) * HDIM + d] = acc[i];
            a += 4;
        }
    }
    if (tid < AGENT) {
        pms[(((size_t)s * 128 + bh) * AGENT + tid) * 2 + 0] = sm_m[tid];
        pms[(((size_t)s * 128 + bh) * AGENT + tid) * 2 + 1] = sm_s[tid];
    }
}

// ---- combine splits: g_agentv[bh][a][d] = sum_s acc_s*exp(m_s-m*) / sum_s s_s*exp(m_s-m*) --
__global__ __launch_bounds__(256) void agent_combine_kernel(
    const float* __restrict__ part, float* __restrict__ av)
{
    const int bh = blockIdx.x;
    const int tid = threadIdx.x;
    const int d = tid & 63, abase = tid >> 6;
    const float* pacc = part;
    const float* pms  = part + (size_t)SPLITS * 128 * AGENT * HDIM;

    int a = abase;
#pragma unroll
    for (int i = 0; i < 13; i++) {
        if (a < 49) {
            float mstar = -1e30f;
            float ms[SPLITS], ss[SPLITS];
#pragma unroll
            for (int s = 0; s < SPLITS; s++) {
                ms[s] = pms[(((size_t)s * 128 + bh) * AGENT + a) * 2 + 0];
                ss[s] = pms[(((size_t)s * 128 + bh) * AGENT + a) * 2 + 1];
                mstar = fmaxf(mstar, ms[s]);
            }
            float S = 0.f, o = 0.f;
#pragma unroll
            for (int s = 0; s < SPLITS; s++) {
                float f = __expf(ms[s] - mstar);
                S += ss[s] * f;
                o += pacc[(((size_t)s * 128 + bh) * AGENT + a) * HDIM + d] * f;
            }
            av[((size_t)bh * AGENT + a) * HDIM + d] = o / S;
        }
        a += 4;
    }
}

// ---------------- q attention (fused logits+softmax+out), per token ------------------------
__global__ __launch_bounds__(224) void qattn_kernel(
    const float* __restrict__ qmat, const float* __restrict__ ag,
    const float* __restrict__ av, const float* __restrict__ ab, float* __restrict__ o)
{
    int bh = blockIdx.y; int b = bh >> 3, h = bh & 7;
    int tid = threadIdx.x;
    int n = blockIdx.x * 224 + tid;
    __shared__ __align__(16) float ahs[49][64];
    __shared__ __align__(16) float avs[49][64];
    for (int i = tid; i < 49 * 16; i += 224) {
        int a = i >> 4, d4 = (i & 15) * 4;
        *(float4*)&ahs[a][d4] = *(const float4*)&ag[((size_t)b * AGENT + a) * CDIM + h * 64 + d4];
        *(float4*)&avs[a][d4] = *(const float4*)&av[((size_t)bh * AGENT + a) * HDIM + d4];
    }
    __syncthreads();

    float4 qv[16];
    const float4* qrow = (const float4*)&qmat[((size_t)b * NTOK + n) * CDIM + h * 64];
#pragma unroll
    for (int i = 0; i < 16; i++) qv[i] = qrow[i];

    float l[49];
    const float* abrow = &ab[((size_t)h * NTOK + n) * AGENT];
#pragma unroll
    for (int a = 0; a < 49; a++) {
        float s = 0.f;
#pragma unroll
        for (int i = 0; i < 16; i++) {
            float4 hv = *(const float4*)&ahs[a][i * 4];
            s += qv[i].x * hv.x + qv[i].y * hv.y + qv[i].z * hv.z + qv[i].w * hv.w;
        }
        l[a] = s * 0.125f + abrow[a];
    }
    float m = -1e30f;
#pragma unroll
    for (int a = 0; a < 49; a++) m = fmaxf(m, l[a]);
    float sum = 0.f;
#pragma unroll
    for (int a = 0; a < 49; a++) { l[a] = __expf(l[a] - m); sum += l[a]; }
    float inv = 1.0f / sum;
#pragma unroll
    for (int a = 0; a < 49; a++) l[a] *= inv;

    float* orow = &o[((size_t)b * NTOK + n) * CDIM + h * 64];
#pragma unroll
    for (int i = 0; i < 16; i++) {
        float4 acc = {0.f, 0.f, 0.f, 0.f};
#pragma unroll
        for (int a = 0; a < 49; a++) {
            float4 hv = *(const float4*)&avs[a][i * 4];
            acc.x += l[a] * hv.x; acc.y += l[a] * hv.y;
            acc.z += l[a] * hv.z; acc.w += l[a] * hv.w;
        }
        *(float4*)&orow[i * 4] = acc;
    }
}

// ---------------- depthwise 3x3 conv on v (channels-last), accumulate into o ---------------
__global__ __launch_bounds__(512) void dwc_kernel(
    const float* __restrict__ v, const float* __restrict__ w,
    const float* __restrict__ bias, float* __restrict__ o)
{
    int c = threadIdx.x;
    int n = blockIdx.x;
    int b = blockIdx.y;
    int y = n / WW, x = n % WW;
    float acc = bias[c];
#pragma unroll
    for (int dy = -1; dy <= 1; dy++) {
        int yy = y + dy; if (yy < 0 || yy >= HH) continue;
#pragma unroll
        for (int dx = -1; dx <= 1; dx++) {
            int xx = x + dx; if (xx < 0 || xx >= WW) continue;
            acc += v[((size_t)b * NTOK + yy * WW + xx) * CDIM + c] *
                   w[c * 9 + (dy + 1) * 3 + (dx + 1)];
        }
    }
    o[((size_t)b * NTOK + n) * CDIM + c] += acc;
}

// ---------------- launch ----------------
extern "C" void kernel_launch(void* const* d_in, const int* in_sizes, int n_in,
                              void* d_out, int out_size)
{
    const float* x      = (const float*)d_in[0];
    const float* q_w    = (const float*)d_in[3];
    const float* kv_w   = (const float*)d_in[4];
    const float* proj_w = (const float*)d_in[5];
    const float* proj_b = (const float*)d_in[6];
    const float* dwc_w  = (const float*)d_in[7];
    const float* dwc_b  = (const float*)d_in[8];
    const float* an_b   = (const float*)d_in[9];
    const float* na_b   = (const float*)d_in[10];
    const float* ah_b   = (const float*)d_in[11];
    const float* aw_b   = (const float*)d_in[12];
    const float* ha_b   = (const float*)d_in[13];
    const float* wa_b   = (const float*)d_in[14];
    float* out = (float*)d_out;

    float *qp, *kp, *vp, *op, *prt, *agp, *avp, *pbp, *abp;
    cudaGetSymbolAddress((void**)&qp,  g_q);
    cudaGetSymbolAddress((void**)&kp,  g_k);
    cudaGetSymbolAddress((void**)&vp,  g_v);
    cudaGetSymbolAddress((void**)&op,  g_o);
    cudaGetSymbolAddress((void**)&prt, g_part);
    cudaGetSymbolAddress((void**)&agp, g_agent);
    cudaGetSymbolAddress((void**)&avp, g_agentv);
    cudaGetSymbolAddress((void**)&pbp, g_pb);
    cudaGetSymbolAddress((void**)&abp, g_ab);

    cudaFuncSetAttribute(mma_gemm, cudaFuncAttributeMaxDynamicSharedMemorySize, GEMM_SMEM);
    cudaFuncSetAttribute(agent_fused_kernel, cudaFuncAttributeMaxDynamicSharedMemorySize, AF_SMEM);

    dim3 ggrid(CDIM / 128, MALL / 128);   // x = N tiles, y = M tiles

    // Launch order keeps the GEMM at the profiler's capture slot (index 3).
    mma_gemm<<<ggrid, 256, GEMM_SMEM>>>(x, q_w, qp, nullptr);                       // 0
    pool_kernel<<<BATCH * AGENT, CDIM>>>(qp, agp);                                   // 1
    bias_kernel<<<HEADS * AGENT, 256>>>(an_b, na_b, ah_b, aw_b, ha_b, wa_b, pbp, abp); // 2
    mma_gemm<<<ggrid, 256, GEMM_SMEM>>>(x, kv_w, kp, nullptr);                       // 3 (profiled)
    mma_gemm<<<ggrid, 256, GEMM_SMEM>>>(x, kv_w + CDIM * CDIM, vp, nullptr);         // 4

    agent_fused_kernel<<<dim3(SPLITS, BATCH * HEADS), 256, AF_SMEM>>>(agp, kp, vp, pbp, prt); // 5
    agent_combine_kernel<<<BATCH * HEADS, 256>>>(prt, avp);                          // 6

    qattn_kernel<<<dim3(NTOK / 224, BATCH * HEADS), 224>>>(qp, agp, avp, abp, op);   // 7
    dwc_kernel<<<dim3(NTOK, BATCH), CDIM>>>(vp, dwc_w, dwc_b, op);                   // 8

    mma_gemm<<<ggrid, 256, GEMM_SMEM>>>(op, proj_w, out, proj_b);                    // 9
}

// round 7
// speedup vs baseline: 1.5838x; 1.0324x over previous
#include <cuda_runtime.h>
#include <cuda_bf16.h>
#include <cstdint>

// ---------------- problem constants ----------------
#define BATCH 16
#define CDIM  512
#define HH    56
#define WW    56
#define NTOK  3136          // 56*56
#define HEADS 8
#define HDIM  64
#define AGENT 49
#define MALL  (BATCH*NTOK)  // 50176
#define SPLITS 7
#define NSPL  448           // NTOK / SPLITS

// ---------------- scratch (static device memory; no allocation) ----------------
__device__ float g_q[MALL*CDIM];
__device__ float g_k[MALL*CDIM];
__device__ float g_v[MALL*CDIM];
__device__ float g_o[MALL*CDIM];
__device__ float g_part[SPLITS*BATCH*HEADS*AGENT*(HDIM+2) + 1024]; // partial acc + (m,s)
__device__ float g_agent[BATCH*AGENT*CDIM];
__device__ float g_agentv[BATCH*HEADS*AGENT*HDIM];
__device__ float g_pb[HEADS*AGENT*NTOK];
__device__ float g_ab[HEADS*NTOK*AGENT];

// ================= tf32 helpers =================
__device__ __forceinline__ uint32_t f2tf32(float f) {
    uint32_t u;
    asm("cvt.rna.tf32.f32 %0, %1;" : "=r"(u) : "f"(f));
    return u;
}

__device__ __forceinline__ void mma_16x8x8(float* d, const uint32_t* a, const uint32_t* b) {
    asm volatile(
        "mma.sync.aligned.m16n8k8.row.col.f32.tf32.tf32.f32 "
        "{%0,%1,%2,%3}, {%4,%5,%6,%7}, {%8,%9}, {%0,%1,%2,%3};"
        : "+f"(d[0]), "+f"(d[1]), "+f"(d[2]), "+f"(d[3])
        : "r"(a[0]), "r"(a[1]), "r"(a[2]), "r"(a[3]), "r"(b[0]), "r"(b[1]));
}

// ======= tf32 tensor-core GEMM: C[m,n] = sum_k A[m,k]*W[n,k] (+bias[n]) =======
// Block tile 128x128, BK=32, 512 threads (16 warps 4x4, warp tile 32x32).
// Smem: XOR-swizzled, row stride 32 words, float4 column group xored with row&7.
#define BK 32
#define TILE_WORDS (128 * 32)
#define GEMM_SMEM (4 * TILE_WORDS * 4)  // 2 stages x (A,B) = 65536 bytes

__global__ __launch_bounds__(512) void mma_gemm(
    const float* __restrict__ A, const float* __restrict__ W,
    float* __restrict__ C, const float* __restrict__ bias)
{
    extern __shared__ float sm[];
    float* As[2] = { sm,                  sm + 2 * TILE_WORDS };
    float* Bs[2] = { sm + TILE_WORDS,     sm + 3 * TILE_WORDS };

    const int tid  = threadIdx.x;
    const int wid  = tid >> 5;
    const int lane = tid & 31;
    const int wm   = (wid >> 2) * 32;    // warp m offset (4 warp-rows)
    const int wn   = (wid & 3) * 32;     // warp n offset (4 warp-cols)
    const int g    = lane >> 2;          // 0..7
    const int tg   = lane & 3;           // 0..3
    const int bm = blockIdx.y * 128;
    const int bn = blockIdx.x * 128;

    // global load geometry: 2 float4 per operand per BK-chunk
    const float* aP[2];
    const float* wP[2];
    int soff[2];
#pragma unroll
    for (int i = 0; i < 2; i++) {
        int id = i * 512 + tid;          // 0..1023 float4 slots
        int r = id >> 3, c4 = id & 7;    // row 0..127, col-group 0..7
        aP[i] = A + (size_t)(bm + r) * 512 + c4 * 4;
        wP[i] = W + (size_t)(bn + r) * 512 + c4 * 4;
        soff[i] = r * 32 + ((c4 ^ (r & 7)) << 2);   // swizzled word offset
    }

    float acc[2][4][4];
#pragma unroll
    for (int mi = 0; mi < 2; mi++)
#pragma unroll
        for (int ni = 0; ni < 4; ni++)
#pragma unroll
            for (int j = 0; j < 4; j++) acc[mi][ni][j] = 0.f;

    float4 ra[2], rb[2];
#pragma unroll
    for (int i = 0; i < 2; i++) { ra[i] = *(const float4*)aP[i]; rb[i] = *(const float4*)wP[i]; }

    int s = 0;
    for (int kc = 0; kc < 16; kc++) {
        // convert + stage into smem (vectorized, swizzled)
#pragma unroll
        for (int i = 0; i < 2; i++) {
            uint4 ua, ub;
            ua.x = f2tf32(ra[i].x); ua.y = f2tf32(ra[i].y);
            ua.z = f2tf32(ra[i].z); ua.w = f2tf32(ra[i].w);
            ub.x = f2tf32(rb[i].x); ub.y = f2tf32(rb[i].y);
            ub.z = f2tf32(rb[i].z); ub.w = f2tf32(rb[i].w);
            *(uint4*)&As[s][soff[i]] = ua;
            *(uint4*)&Bs[s][soff[i]] = ub;
        }
        __syncthreads();   // single barrier per K-chunk: guards buffer s readiness;
                           // next staging targets s^1 so no WAR hazard with mma(s).
        if (kc + 1 < 16) {
            int koff = (kc + 1) * BK;
#pragma unroll
            for (int i = 0; i < 2; i++) {
                ra[i] = *(const float4*)(aP[i] + koff);
                rb[i] = *(const float4*)(wP[i] + koff);
            }
        }
        const float* Af = As[s];
        const float* Bf = Bs[s];
#pragma unroll
        for (int ks = 0; ks < 4; ks++) {
            const int x0 = (((2 * ks)     ^ g) << 2) + tg;
            const int x1 = (((2 * ks + 1) ^ g) << 2) + tg;
            uint32_t af[2][4], bf[4][2];
#pragma unroll
            for (int mi = 0; mi < 2; mi++) {
                int r0 = wm + mi * 16 + g;
                af[mi][0] = __float_as_uint(Af[r0 * 32 + x0]);
                af[mi][1] = __float_as_uint(Af[(r0 + 8) * 32 + x0]);
                af[mi][2] = __float_as_uint(Af[r0 * 32 + x1]);
                af[mi][3] = __float_as_uint(Af[(r0 + 8) * 32 + x1]);
            }
#pragma unroll
            for (int ni = 0; ni < 4; ni++) {
                int n0 = wn + ni * 8 + g;
                bf[ni][0] = __float_as_uint(Bf[n0 * 32 + x0]);
                bf[ni][1] = __float_as_uint(Bf[n0 * 32 + x1]);
            }
#pragma unroll
            for (int mi = 0; mi < 2; mi++)
#pragma unroll
                for (int ni = 0; ni < 4; ni++)
                    mma_16x8x8(acc[mi][ni], af[mi], bf[ni]);
        }
        s ^= 1;
    }

    // epilogue
#pragma unroll
    for (int mi = 0; mi < 2; mi++) {
        int row = bm + wm + mi * 16 + g;
#pragma unroll
        for (int ni = 0; ni < 4; ni++) {
            int col = bn + wn + ni * 8 + 2 * tg;
            float b0 = 0.f, b1 = 0.f;
            if (bias) { b0 = bias[col]; b1 = bias[col + 1]; }
            float2 v0 = { acc[mi][ni][0] + b0, acc[mi][ni][1] + b1 };
            float2 v1 = { acc[mi][ni][2] + b0, acc[mi][ni][3] + b1 };
            *(float2*)&C[(size_t)row * 512 + col] = v0;
            *(float2*)&C[(size_t)(row + 8) * 512 + col] = v1;
        }
    }
}

// ---------------- agent token pooling: mean over 8x8 spatial blocks of q ----------------
__global__ __launch_bounds__(512) void pool_kernel(const float* __restrict__ q,
                                                   float* __restrict__ ag)
{
    int c = threadIdx.x;
    int b = blockIdx.x / AGENT;
    int a = blockIdx.x % AGENT;
    int p1 = a / 7, p2 = a % 7;
    float s = 0.f;
#pragma unroll
    for (int i = 0; i < 8; i++)
#pragma unroll
        for (int j = 0; j < 8; j++)
            s += q[((size_t)b * NTOK + (p1 * 8 + i) * WW + (p2 * 8 + j)) * CDIM + c];
    ag[((size_t)b * AGENT + a) * CDIM + c] = s * (1.0f / 64.0f);
}

// ---------------- bias precompute: bilinear(7x7 -> 56x56, jax half-pixel) + axis biases --
__global__ __launch_bounds__(256) void bias_kernel(
    const float* __restrict__ an, const float* __restrict__ na,
    const float* __restrict__ ahb, const float* __restrict__ awb,
    const float* __restrict__ hab, const float* __restrict__ wab,
    float* __restrict__ pb, float* __restrict__ ab)
{
    int h = blockIdx.x / AGENT;
    int a = blockIdx.x % AGENT;
    __shared__ float ans[49], nas[49];
    int tid = threadIdx.x;
    if (tid < 49) {
        ans[tid] = an[((size_t)h * AGENT + a) * 49 + tid];
        nas[tid] = na[((size_t)h * AGENT + a) * 49 + tid];
    }
    __syncthreads();
    for (int n = tid; n < NTOK; n += 256) {
        int y = n / WW, x = n % WW;
        float fy = (y + 0.5f) * 0.125f - 0.5f;
        float fx = (x + 0.5f) * 0.125f - 0.5f;
        int iy = (int)floorf(fy); float ty = fy - iy;
        int ix = (int)floorf(fx); float tx = fx - ix;
        float wy0 = 1.f - ty, wy1 = ty;
        int y0 = iy, y1 = iy + 1;
        if (y0 < 0) { wy0 = 0.f; y0 = 0; }
        if (y1 > 6) { wy1 = 0.f; y1 = 6; }
        float sy = wy0 + wy1; wy0 /= sy; wy1 /= sy;
        float wx0 = 1.f - tx, wx1 = tx;
        int x0 = ix, x1 = ix + 1;
        if (x0 < 0) { wx0 = 0.f; x0 = 0; }
        if (x1 > 6) { wx1 = 0.f; x1 = 6; }
        float sx = wx0 + wx1; wx0 /= sx; wx1 /= sx;

        float bi_an = wy0 * (wx0 * ans[y0 * 7 + x0] + wx1 * ans[y0 * 7 + x1]) +
                      wy1 * (wx0 * ans[y1 * 7 + x0] + wx1 * ans[y1 * 7 + x1]);
        float bi_na = wy0 * (wx0 * nas[y0 * 7 + x0] + wx1 * nas[y0 * 7 + x1]) +
                      wy1 * (wx0 * nas[y1 * 7 + x0] + wx1 * nas[y1 * 7 + x1]);

        pb[((size_t)h * AGENT + a) * NTOK + n] =
            bi_an + ahb[((size_t)h * AGENT + a) * 56 + y] + awb[((size_t)h * AGENT + a) * 56 + x];
        ab[((size_t)h * NTOK + n) * AGENT + a] =
            bi_na + hab[((size_t)h * 56 + y) * AGENT + a] + wab[((size_t)h * 56 + x) * AGENT + a];
    }
}

// ============ fused agent attention: logits + softmax + attn@V, split over n ============
#define AF_SMEM ((AGENT*HDIM + HDIM*65 + AGENT*NSPL) * 4)

__global__ __launch_bounds__(256) void agent_fused_kernel(
    const float* __restrict__ ag, const float* __restrict__ kmat,
    const float* __restrict__ vmat, const float* __restrict__ pb,
    float* __restrict__ part)
{
    extern __shared__ float smf[];
    float* ahs = smf;                    // [49][64]
    float* kvb = ahs + AGENT * HDIM;     // [64][65] staging (k, then v)
    float* L   = kvb + HDIM * 65;        // [49][448] logits -> exp values
    __shared__ float sm_m[AGENT], sm_s[AGENT];

    const int s  = blockIdx.x;
    const int bh = blockIdx.y;
    const int b = bh >> 3, h = bh & 7;
    const int tid = threadIdx.x;
    const int nl = tid & 63, abase = tid >> 6;
    const int n0base = s * NSPL;

    for (int i = tid; i < AGENT * HDIM; i += 256) {
        int a = i >> 6, d = i & 63;
        ahs[i] = ag[((size_t)b * AGENT + a) * CDIM + h * 64 + d] * 0.125f;
    }

    // ---- Phase 1: logits into smem L ----
    for (int c = 0; c < 7; c++) {
        int n0 = n0base + c * 64;
        __syncthreads();
        for (int i = tid; i < 64 * 16; i += 256) {
            int nn = i >> 4, d4 = (i & 15) * 4;
            float4 v = *(const float4*)&kmat[((size_t)b * NTOK + n0 + nn) * CDIM + h * 64 + d4];
            kvb[nn * 65 + d4] = v.x; kvb[nn * 65 + d4 + 1] = v.y;
            kvb[nn * 65 + d4 + 2] = v.z; kvb[nn * 65 + d4 + 3] = v.w;
        }
        __syncthreads();
        float acc[13];
#pragma unroll
        for (int i = 0; i < 13; i++) acc[i] = 0.f;
#pragma unroll 8
        for (int d = 0; d < 64; d++) {
            float kd = kvb[nl * 65 + d];
            int a = abase;
#pragma unroll
            for (int i = 0; i < 13; i++) { if (a < 49) acc[i] += ahs[a * 64 + d] * kd; a += 4; }
        }
        int a = abase;
#pragma unroll
        for (int i = 0; i < 13; i++) {
            if (a < 49)
                L[a * NSPL + c * 64 + nl] = acc[i] + pb[((size_t)h * AGENT + a) * NTOK + n0 + nl];
            a += 4;
        }
    }
    __syncthreads();

    // ---- Phase 2: per-a max & sum over this split; L <- exp(L - m) ----
    {
        int w = tid >> 5, lane = tid & 31;
        for (int a = w; a < AGENT; a += 8) {
            float m = -1e30f;
            for (int j = lane; j < NSPL; j += 32) m = fmaxf(m, L[a * NSPL + j]);
#pragma unroll
            for (int o = 16; o > 0; o >>= 1) m = fmaxf(m, __shfl_xor_sync(0xffffffffu, m, o));
            float sum = 0.f;
            for (int j = lane; j < NSPL; j += 32) {
                float e = __expf(L[a * NSPL + j] - m);
                L[a * NSPL + j] = e;
                sum += e;
            }
#pragma unroll
            for (int o = 16; o > 0; o >>= 1) sum += __shfl_xor_sync(0xffffffffu, sum, o);
            if (lane == 0) { sm_m[a] = m; sm_s[a] = sum; }
        }
    }
    __syncthreads();

    // ---- Phase 3: partial acc[a][d] = sum_n expL * v[n][d] ----
    float acc[13];
#pragma unroll
    for (int i = 0; i < 13; i++) acc[i] = 0.f;
    const int d = nl;
    for (int c = 0; c < 7; c++) {
        int n0 = n0base + c * 64;
        __syncthreads();
        for (int i = tid; i < 64 * 16; i += 256) {
            int nn = i >> 4, d4 = (i & 15) * 4;
            float4 v = *(const float4*)&vmat[((size_t)b * NTOK + n0 + nn) * CDIM + h * 64 + d4];
            kvb[nn * 65 + d4] = v.x; kvb[nn * 65 + d4 + 1] = v.y;
            kvb[nn * 65 + d4 + 2] = v.z; kvb[nn * 65 + d4 + 3] = v.w;
        }
        __syncthreads();
#pragma unroll 8
        for (int nn = 0; nn < 64; nn++) {
            float vd = kvb[nn * 65 + d];
            int a = abase;
#pragma unroll
            for (int i = 0; i < 13; i++) { if (a < 49) acc[i] += L[a * NSPL + c * 64 + nn] * vd; a += 4; }
        }
    }

    float* pacc = part;
    float* pms  = part + (size_t)SPLITS * 128 * AGENT * HDIM;
    {
        int a = abase;
#pragma unroll
        for (int i = 0; i < 13; i++) {
            if (a < 49) pacc[(((size_t)s * 128 + bh) * AGENT + a) * HDIM + d] = acc[i];
            a += 4;
        }
    }
    if (tid < AGENT) {
        pms[(((size_t)s * 128 + bh) * AGENT + tid) * 2 + 0] = sm_m[tid];
        pms[(((size_t)s * 128 + bh) * AGENT + tid) * 2 + 1] = sm_s[tid];
    }
}

// ---- combine splits ----
__global__ __launch_bounds__(256) void agent_combine_kernel(
    const float* __restrict__ part, float* __restrict__ av)
{
    const int bh = blockIdx.x;
    const int tid = threadIdx.x;
    const int d = tid & 63, abase = tid >> 6;
    const float* pacc = part;
    const float* pms  = part + (size_t)SPLITS * 128 * AGENT * HDIM;

    int a = abase;
#pragma unroll
    for (int i = 0; i < 13; i++) {
        if (a < 49) {
            float mstar = -1e30f;
            float ms[SPLITS], ss[SPLITS];
#pragma unroll
            for (int s = 0; s < SPLITS; s++) {
                ms[s] = pms[(((size_t)s * 128 + bh) * AGENT + a) * 2 + 0];
                ss[s] = pms[(((size_t)s * 128 + bh) * AGENT + a) * 2 + 1];
                mstar = fmaxf(mstar, ms[s]);
            }
            float S = 0.f, o = 0.f;
#pragma unroll
            for (int s = 0; s < SPLITS; s++) {
                float f = __expf(ms[s] - mstar);
                S += ss[s] * f;
                o += pacc[(((size_t)s * 128 + bh) * AGENT + a) * HDIM + d] * f;
            }
            av[((size_t)bh * AGENT + a) * HDIM + d] = o / S;
        }
        a += 4;
    }
}

// ---------------- q attention (fused logits+softmax+out), per token ------------------------
__global__ __launch_bounds__(224) void qattn_kernel(
    const float* __restrict__ qmat, const float* __restrict__ ag,
    const float* __restrict__ av, const float* __restrict__ ab, float* __restrict__ o)
{
    int bh = blockIdx.y; int b = bh >> 3, h = bh & 7;
    int tid = threadIdx.x;
    int n = blockIdx.x * 224 + tid;
    __shared__ __align__(16) float ahs[49][64];
    __shared__ __align__(16) float avs[49][64];
    for (int i = tid; i < 49 * 16; i += 224) {
        int a = i >> 4, d4 = (i & 15) * 4;
        *(float4*)&ahs[a][d4] = *(const float4*)&ag[((size_t)b * AGENT + a) * CDIM + h * 64 + d4];
        *(float4*)&avs[a][d4] = *(const float4*)&av[((size_t)bh * AGENT + a) * HDIM + d4];
    }
    __syncthreads();

    float4 qv[16];
    const float4* qrow = (const float4*)&qmat[((size_t)b * NTOK + n) * CDIM + h * 64];
#pragma unroll
    for (int i = 0; i < 16; i++) qv[i] = qrow[i];

    float l[49];
    const float* abrow = &ab[((size_t)h * NTOK + n) * AGENT];
#pragma unroll
    for (int a = 0; a < 49; a++) {
        float s = 0.f;
#pragma unroll
        for (int i = 0; i < 16; i++) {
            float4 hv = *(const float4*)&ahs[a][i * 4];
            s += qv[i].x * hv.x + qv[i].y * hv.y + qv[i].z * hv.z + qv[i].w * hv.w;
        }
        l[a] = s * 0.125f + abrow[a];
    }
    float m = -1e30f;
#pragma unroll
    for (int a = 0; a < 49; a++) m = fmaxf(m, l[a]);
    float sum = 0.f;
#pragma unroll
    for (int a = 0; a < 49; a++) { l[a] = __expf(l[a] - m); sum += l[a]; }
    float inv = 1.0f / sum;
#pragma unroll
    for (int a = 0; a < 49; a++) l[a] *= inv;

    float* orow = &o[((size_t)b * NTOK + n) * CDIM + h * 64];
#pragma unroll
    for (int i = 0; i < 16; i++) {
        float4 acc = {0.f, 0.f, 0.f, 0.f};
#pragma unroll
        for (int a = 0; a < 49; a++) {
            float4 hv = *(const float4*)&avs[a][i * 4];
            acc.x += l[a] * hv.x; acc.y += l[a] * hv.y;
            acc.z += l[a] * hv.z; acc.w += l[a] * hv.w;
        }
        *(float4*)&orow[i * 4] = acc;
    }
}

// ---------------- depthwise 3x3 conv on v (channels-last), accumulate into o ---------------
__global__ __launch_bounds__(512) void dwc_kernel(
    const float* __restrict__ v, const float* __restrict__ w,
    const float* __restrict__ bias, float* __restrict__ o)
{
    int c = threadIdx.x;
    int n = blockIdx.x;
    int b = blockIdx.y;
    int y = n / WW, x = n % WW;
    float acc = bias[c];
#pragma unroll
    for (int dy = -1; dy <= 1; dy++) {
        int yy = y + dy; if (yy < 0 || yy >= HH) continue;
#pragma unroll
        for (int dx = -1; dx <= 1; dx++) {
            int xx = x + dx; if (xx < 0 || xx >= WW) continue;
            acc += v[((size_t)b * NTOK + yy * WW + xx) * CDIM + c] *
                   w[c * 9 + (dy + 1) * 3 + (dx + 1)];
        }
    }
    o[((size_t)b * NTOK + n) * CDIM + c] += acc;
}

// ---------------- launch ----------------
extern "C" void kernel_launch(void* const* d_in, const int* in_sizes, int n_in,
                              void* d_out, int out_size)
{
    const float* x      = (const float*)d_in[0];
    const float* q_w    = (const float*)d_in[3];
    const float* kv_w   = (const float*)d_in[4];
    const float* proj_w = (const float*)d_in[5];
    const float* proj_b = (const float*)d_in[6];
    const float* dwc_w  = (const float*)d_in[7];
    const float* dwc_b  = (const float*)d_in[8];
    const float* an_b   = (const float*)d_in[9];
    const float* na_b   = (const float*)d_in[10];
    const float* ah_b   = (const float*)d_in[11];
    const float* aw_b   = (const float*)d_in[12];
    const float* ha_b   = (const float*)d_in[13];
    const float* wa_b   = (const float*)d_in[14];
    float* out = (float*)d_out;

    float *qp, *kp, *vp, *op, *prt, *agp, *avp, *pbp, *abp;
    cudaGetSymbolAddress((void**)&qp,  g_q);
    cudaGetSymbolAddress((void**)&kp,  g_k);
    cudaGetSymbolAddress((void**)&vp,  g_v);
    cudaGetSymbolAddress((void**)&op,  g_o);
    cudaGetSymbolAddress((void**)&prt, g_part);
    cudaGetSymbolAddress((void**)&agp, g_agent);
    cudaGetSymbolAddress((void**)&avp, g_agentv);
    cudaGetSymbolAddress((void**)&pbp, g_pb);
    cudaGetSymbolAddress((void**)&abp, g_ab);

    cudaFuncSetAttribute(mma_gemm, cudaFuncAttributeMaxDynamicSharedMemorySize, GEMM_SMEM);
    cudaFuncSetAttribute(agent_fused_kernel, cudaFuncAttributeMaxDynamicSharedMemorySize, AF_SMEM);

    dim3 ggrid(CDIM / 128, MALL / 128);   // x = N tiles, y = M tiles

    // Launch order keeps a GEMM at the profiler's capture slot (index 3).
    mma_gemm<<<ggrid, 512, GEMM_SMEM>>>(x, q_w, qp, nullptr);                        // 0
    pool_kernel<<<BATCH * AGENT, CDIM>>>(qp, agp);                                   // 1
    bias_kernel<<<HEADS * AGENT, 256>>>(an_b, na_b, ah_b, aw_b, ha_b, wa_b, pbp, abp); // 2
    mma_gemm<<<ggrid, 512, GEMM_SMEM>>>(x, kv_w, kp, nullptr);                       // 3 (profiled)
    mma_gemm<<<ggrid, 512, GEMM_SMEM>>>(x, kv_w + CDIM * CDIM, vp, nullptr);         // 4

    agent_fused_kernel<<<dim3(SPLITS, BATCH * HEADS), 256, AF_SMEM>>>(agp, kp, vp, pbp, prt); // 5
    agent_combine_kernel<<<BATCH * HEADS, 256>>>(prt, avp);                          // 6

    qattn_kernel<<<dim3(NTOK / 224, BATCH * HEADS), 224>>>(qp, agp, avp, abp, op);   // 7
    dwc_kernel<<<dim3(NTOK, BATCH), CDIM>>>(vp, dwc_w, dwc_b, op);                   // 8

    mma_gemm<<<ggrid, 512, GEMM_SMEM>>>(op, proj_w, out, proj_b);                    // 9
}

// round 8
// speedup vs baseline: 2.1428x; 1.3530x over previous
#include <cuda_runtime.h>
#include <cuda_bf16.h>
#include <cstdint>

// ---------------- problem constants ----------------
#define BATCH 16
#define CDIM  512
#define HH    56
#define WW    56
#define NTOK  3136          // 56*56
#define HEADS 8
#define HDIM  64
#define AGENT 49
#define MALL  (BATCH*NTOK)  // 50176
#define SPLITS 7
#define NSPL  448           // NTOK / SPLITS

// ---------------- scratch (static device memory; no allocation) ----------------
__device__ float g_q[MALL*CDIM];
__device__ float g_k[MALL*CDIM];
__device__ float g_v[MALL*CDIM];
__device__ float g_o[MALL*CDIM];
__device__ float g_xc[MALL*CDIM];      // x pre-converted to tf32
__device__ float g_oc[MALL*CDIM];      // (o + dwc) pre-converted to tf32
__device__ float g_wc[4*CDIM*CDIM];    // q_w | k_w | v_w | proj_w, tf32
__device__ float g_part[SPLITS*BATCH*HEADS*AGENT*(HDIM+2) + 1024];
__device__ float g_agent[BATCH*AGENT*CDIM];
__device__ float g_agentv[BATCH*HEADS*AGENT*HDIM];
__device__ float g_pb[HEADS*AGENT*NTOK];
__device__ float g_ab[HEADS*NTOK*AGENT];

// ================= helpers =================
__device__ __forceinline__ uint32_t f2tf32(float f) {
    uint32_t u;
    asm("cvt.rna.tf32.f32 %0, %1;" : "=r"(u) : "f"(f));
    return u;
}
__device__ __forceinline__ uint32_t smem_u32(const void* p) {
    uint32_t a;
    asm("{ .reg .u64 t; cvta.to.shared.u64 t, %1; cvt.u32.u64 %0, t; }" : "=r"(a) : "l"(p));
    return a;
}
__device__ __forceinline__ void mma_16x8x8(float* d, const uint32_t* a, const uint32_t* b) {
    asm volatile(
        "mma.sync.aligned.m16n8k8.row.col.f32.tf32.tf32.f32 "
        "{%0,%1,%2,%3}, {%4,%5,%6,%7}, {%8,%9}, {%0,%1,%2,%3};"
        : "+f"(d[0]), "+f"(d[1]), "+f"(d[2]), "+f"(d[3])
        : "r"(a[0]), "r"(a[1]), "r"(a[2]), "r"(a[3]), "r"(b[0]), "r"(b[1]));
}
#define LDSM_X4(r, addr) \
    asm volatile("ldmatrix.sync.aligned.m8n8.x4.shared.b16 {%0,%1,%2,%3}, [%4];" \
        : "=r"((r)[0]), "=r"((r)[1]), "=r"((r)[2]), "=r"((r)[3]) : "r"(addr))
#define CP_ASYNC16(dst, src) \
    asm volatile("cp.async.cg.shared.global [%0], [%1], 16;" :: "r"(dst), "l"(src))

// ---------------- tf32 pre-conversion (elementwise, float4) ----------------
__global__ __launch_bounds__(256) void tf32_conv_kernel(
    const float* __restrict__ in, float* __restrict__ out, int n4)
{
    int i = blockIdx.x * 256 + threadIdx.x;
    if (i < n4) {
        float4 v = ((const float4*)in)[i];
        uint4 u;
        u.x = f2tf32(v.x); u.y = f2tf32(v.y); u.z = f2tf32(v.z); u.w = f2tf32(v.w);
        ((uint4*)out)[i] = u;
    }
}

// ======= tf32 tensor-core GEMM: C[m,n] = sum_k A[m,k]*W[n,k] (+bias[n]) =======
// Inputs A, W are PRE-CONVERTED tf32 (bit patterns in float). 128x128 tile, BK=32.
// 256 threads, 8 warps 2x4 (warp tile 64x32). cp.async 3-stage + ldmatrix frags.
#define GSTG 3
#define TILEW (128*32)                 // words per operand tile
#define STG_WORDS (2*TILEW)            // A + B per stage
#define GEMM_SMEM (GSTG*STG_WORDS*4)   // 98304 bytes

__global__ void __launch_bounds__(256, 2) mma_gemm(
    const float* __restrict__ A, const float* __restrict__ W,
    float* __restrict__ C, const float* __restrict__ bias)
{
    extern __shared__ float sm[];
    const int tid = threadIdx.x;
    const int wid = tid >> 5, lane = tid & 31;
    const int wm = (wid >> 2) * 64;     // 2 warp-rows
    const int wn = (wid & 3) * 32;      // 4 warp-cols
    const int g = lane >> 2, tg = lane & 3;
    const int bm = blockIdx.y * 128, bn = blockIdx.x * 128;
    const uint32_t smBase = smem_u32(sm);

    // cp.async geometry: 4 x 16B per operand per thread per K-chunk
    const float* aSrc[4];
    const float* wSrc[4];
    uint32_t dOff[4];
#pragma unroll
    for (int i = 0; i < 4; i++) {
        int id = i * 256 + tid;
        int r = id >> 3, c4 = id & 7;
        aSrc[i] = A + (size_t)(bm + r) * 512 + c4 * 4;
        wSrc[i] = W + (size_t)(bn + r) * 512 + c4 * 4;
        dOff[i] = (uint32_t)(r * 32 + ((c4 ^ (r & 7)) << 2)) * 4;  // byte offset
    }

    // ldmatrix lane geometry
    const int mA = lane >> 3;
    const int rowA_base = wm + ((mA & 1) << 3) + (lane & 7);   // + mi*16
    const int c4bA = mA >> 1;                                   // 0=k-lo, 1=k-hi
    const int rowB_base = wn + ((lane >> 4) << 3) + (lane & 7); // + p*16
    const int c4bB = (lane >> 3) & 1;

    float acc[4][4][4];
#pragma unroll
    for (int mi = 0; mi < 4; mi++)
#pragma unroll
        for (int ni = 0; ni < 4; ni++)
#pragma unroll
            for (int j = 0; j < 4; j++) acc[mi][ni][j] = 0.f;

    // prologue: stage 0, 1
#pragma unroll
    for (int kc = 0; kc < 2; kc++) {
        uint32_t sA = smBase + (uint32_t)(kc % GSTG) * STG_WORDS * 4;
        uint32_t sB = sA + TILEW * 4;
        int koff = kc * 32;
#pragma unroll
        for (int i = 0; i < 4; i++) {
            CP_ASYNC16(sA + dOff[i], aSrc[i] + koff);
            CP_ASYNC16(sB + dOff[i], wSrc[i] + koff);
        }
        asm volatile("cp.async.commit_group;");
    }

    for (int kc = 0; kc < 16; kc++) {
        if (kc < 15) asm volatile("cp.async.wait_group 1;");
        else         asm volatile("cp.async.wait_group 0;");
        __syncthreads();
        if (kc + 2 < 16) {   // issue stage kc+2 (buffer (kc+2)%3, mma'd at kc-1 — safe post-barrier)
            uint32_t sA = smBase + (uint32_t)((kc + 2) % GSTG) * STG_WORDS * 4;
            uint32_t sB = sA + TILEW * 4;
            int koff = (kc + 2) * 32;
#pragma unroll
            for (int i = 0; i < 4; i++) {
                CP_ASYNC16(sA + dOff[i], aSrc[i] + koff);
                CP_ASYNC16(sB + dOff[i], wSrc[i] + koff);
            }
            asm volatile("cp.async.commit_group;");
        }
        const uint32_t sA = smBase + (uint32_t)(kc % GSTG) * STG_WORDS * 4;
        const uint32_t sB = sA + TILEW * 4;
#pragma unroll
        for (int ks = 0; ks < 4; ks++) {
            uint32_t aF[4][4], bF[2][4];
#pragma unroll
            for (int mi = 0; mi < 4; mi++) {
                int row = rowA_base + mi * 16;
                int c4 = (2 * ks) | c4bA;
                uint32_t off = (uint32_t)(row * 32 + ((c4 ^ (row & 7)) << 2)) * 4;
                LDSM_X4(aF[mi], sA + off);
            }
#pragma unroll
            for (int p = 0; p < 2; p++) {
                int row = rowB_base + p * 16;
                int c4 = (2 * ks) | c4bB;
                uint32_t off = (uint32_t)(row * 32 + ((c4 ^ (row & 7)) << 2)) * 4;
                LDSM_X4(bF[p], sB + off);
            }
#pragma unroll
            for (int mi = 0; mi < 4; mi++)
#pragma unroll
                for (int p = 0; p < 2; p++) {
                    mma_16x8x8(acc[mi][2 * p],     aF[mi], &bF[p][0]);
                    mma_16x8x8(acc[mi][2 * p + 1], aF[mi], &bF[p][2]);
                }
        }
    }

    // epilogue
#pragma unroll
    for (int mi = 0; mi < 4; mi++) {
        int row = bm + wm + mi * 16 + g;
#pragma unroll
        for (int ni = 0; ni < 4; ni++) {
            int col = bn + wn + ni * 8 + 2 * tg;
            float b0 = 0.f, b1 = 0.f;
            if (bias) { b0 = bias[col]; b1 = bias[col + 1]; }
            float2 v0 = { acc[mi][ni][0] + b0, acc[mi][ni][1] + b1 };
            float2 v1 = { acc[mi][ni][2] + b0, acc[mi][ni][3] + b1 };
            *(float2*)&C[(size_t)row * 512 + col] = v0;
            *(float2*)&C[(size_t)(row + 8) * 512 + col] = v1;
        }
    }
}

// ---------------- agent token pooling: mean over 8x8 spatial blocks of q ----------------
__global__ __launch_bounds__(512) void pool_kernel(const float* __restrict__ q,
                                                   float* __restrict__ ag)
{
    int c = threadIdx.x;
    int b = blockIdx.x / AGENT;
    int a = blockIdx.x % AGENT;
    int p1 = a / 7, p2 = a % 7;
    float s = 0.f;
#pragma unroll
    for (int i = 0; i < 8; i++)
#pragma unroll
        for (int j = 0; j < 8; j++)
            s += q[((size_t)b * NTOK + (p1 * 8 + i) * WW + (p2 * 8 + j)) * CDIM + c];
    ag[((size_t)b * AGENT + a) * CDIM + c] = s * (1.0f / 64.0f);
}

// ---------------- bias precompute: bilinear(7x7 -> 56x56, jax half-pixel) + axis biases --
__global__ __launch_bounds__(256) void bias_kernel(
    const float* __restrict__ an, const float* __restrict__ na,
    const float* __restrict__ ahb, const float* __restrict__ awb,
    const float* __restrict__ hab, const float* __restrict__ wab,
    float* __restrict__ pb, float* __restrict__ ab)
{
    int h = blockIdx.x / AGENT;
    int a = blockIdx.x % AGENT;
    __shared__ float ans[49], nas[49];
    int tid = threadIdx.x;
    if (tid < 49) {
        ans[tid] = an[((size_t)h * AGENT + a) * 49 + tid];
        nas[tid] = na[((size_t)h * AGENT + a) * 49 + tid];
    }
    __syncthreads();
    for (int n = tid; n < NTOK; n += 256) {
        int y = n / WW, x = n % WW;
        float fy = (y + 0.5f) * 0.125f - 0.5f;
        float fx = (x + 0.5f) * 0.125f - 0.5f;
        int iy = (int)floorf(fy); float ty = fy - iy;
        int ix = (int)floorf(fx); float tx = fx - ix;
        float wy0 = 1.f - ty, wy1 = ty;
        int y0 = iy, y1 = iy + 1;
        if (y0 < 0) { wy0 = 0.f; y0 = 0; }
        if (y1 > 6) { wy1 = 0.f; y1 = 6; }
        float sy = wy0 + wy1; wy0 /= sy; wy1 /= sy;
        float wx0 = 1.f - tx, wx1 = tx;
        int x0 = ix, x1 = ix + 1;
        if (x0 < 0) { wx0 = 0.f; x0 = 0; }
        if (x1 > 6) { wx1 = 0.f; x1 = 6; }
        float sx = wx0 + wx1; wx0 /= sx; wx1 /= sx;

        float bi_an = wy0 * (wx0 * ans[y0 * 7 + x0] + wx1 * ans[y0 * 7 + x1]) +
                      wy1 * (wx0 * ans[y1 * 7 + x0] + wx1 * ans[y1 * 7 + x1]);
        float bi_na = wy0 * (wx0 * nas[y0 * 7 + x0] + wx1 * nas[y0 * 7 + x1]) +
                      wy1 * (wx0 * nas[y1 * 7 + x0] + wx1 * nas[y1 * 7 + x1]);

        pb[((size_t)h * AGENT + a) * NTOK + n] =
            bi_an + ahb[((size_t)h * AGENT + a) * 56 + y] + awb[((size_t)h * AGENT + a) * 56 + x];
        ab[((size_t)h * NTOK + n) * AGENT + a] =
            bi_na + hab[((size_t)h * 56 + y) * AGENT + a] + wab[((size_t)h * 56 + x) * AGENT + a];
    }
}

// ============ fused agent attention: logits + softmax + attn@V, split over n ============
#define AF_SMEM ((AGENT*HDIM + HDIM*65 + AGENT*NSPL) * 4)

__global__ __launch_bounds__(256) void agent_fused_kernel(
    const float* __restrict__ ag, const float* __restrict__ kmat,
    const float* __restrict__ vmat, const float* __restrict__ pb,
    float* __restrict__ part)
{
    extern __shared__ float smf[];
    float* ahs = smf;                    // [49][64]
    float* kvb = ahs + AGENT * HDIM;     // [64][65] staging (k, then v)
    float* L   = kvb + HDIM * 65;        // [49][448]
    __shared__ float sm_m[AGENT], sm_s[AGENT];

    const int s  = blockIdx.x;
    const int bh = blockIdx.y;
    const int b = bh >> 3, h = bh & 7;
    const int tid = threadIdx.x;
    const int nl = tid & 63, abase = tid >> 6;
    const int n0base = s * NSPL;

    for (int i = tid; i < AGENT * HDIM; i += 256) {
        int a = i >> 6, d = i & 63;
        ahs[i] = ag[((size_t)b * AGENT + a) * CDIM + h * 64 + d] * 0.125f;
    }

    for (int c = 0; c < 7; c++) {
        int n0 = n0base + c * 64;
        __syncthreads();
        for (int i = tid; i < 64 * 16; i += 256) {
            int nn = i >> 4, d4 = (i & 15) * 4;
            float4 v = *(const float4*)&kmat[((size_t)b * NTOK + n0 + nn) * CDIM + h * 64 + d4];
            kvb[nn * 65 + d4] = v.x; kvb[nn * 65 + d4 + 1] = v.y;
            kvb[nn * 65 + d4 + 2] = v.z; kvb[nn * 65 + d4 + 3] = v.w;
        }
        __syncthreads();
        float acc[13];
#pragma unroll
        for (int i = 0; i < 13; i++) acc[i] = 0.f;
#pragma unroll 8
        for (int d = 0; d < 64; d++) {
            float kd = kvb[nl * 65 + d];
            int a = abase;
#pragma unroll
            for (int i = 0; i < 13; i++) { if (a < 49) acc[i] += ahs[a * 64 + d] * kd; a += 4; }
        }
        int a = abase;
#pragma unroll
        for (int i = 0; i < 13; i++) {
            if (a < 49)
                L[a * NSPL + c * 64 + nl] = acc[i] + pb[((size_t)h * AGENT + a) * NTOK + n0 + nl];
            a += 4;
        }
    }
    __syncthreads();

    {
        int w = tid >> 5, lane = tid & 31;
        for (int a = w; a < AGENT; a += 8) {
            float m = -1e30f;
            for (int j = lane; j < NSPL; j += 32) m = fmaxf(m, L[a * NSPL + j]);
#pragma unroll
            for (int o = 16; o > 0; o >>= 1) m = fmaxf(m, __shfl_xor_sync(0xffffffffu, m, o));
            float sum = 0.f;
            for (int j = lane; j < NSPL; j += 32) {
                float e = __expf(L[a * NSPL + j] - m);
                L[a * NSPL + j] = e;
                sum += e;
            }
#pragma unroll
            for (int o = 16; o > 0; o >>= 1) sum += __shfl_xor_sync(0xffffffffu, sum, o);
            if (lane == 0) { sm_m[a] = m; sm_s[a] = sum; }
        }
    }
    __syncthreads();

    float acc[13];
#pragma unroll
    for (int i = 0; i < 13; i++) acc[i] = 0.f;
    const int d = nl;
    for (int c = 0; c < 7; c++) {
        int n0 = n0base + c * 64;
        __syncthreads();
        for (int i = tid; i < 64 * 16; i += 256) {
            int nn = i >> 4, d4 = (i & 15) * 4;
            float4 v = *(const float4*)&vmat[((size_t)b * NTOK + n0 + nn) * CDIM + h * 64 + d4];
            kvb[nn * 65 + d4] = v.x; kvb[nn * 65 + d4 + 1] = v.y;
            kvb[nn * 65 + d4 + 2] = v.z; kvb[nn * 65 + d4 + 3] = v.w;
        }
        __syncthreads();
#pragma unroll 8
        for (int nn = 0; nn < 64; nn++) {
            float vd = kvb[nn * 65 + d];
            int a = abase;
#pragma unroll
            for (int i = 0; i < 13; i++) { if (a < 49) acc[i] += L[a * NSPL + c * 64 + nn] * vd; a += 4; }
        }
    }

    float* pacc = part;
    float* pms  = part + (size_t)SPLITS * 128 * AGENT * HDIM;
    {
        int a = abase;
#pragma unroll
        for (int i = 0; i < 13; i++) {
            if (a < 49) pacc[(((size_t)s * 128 + bh) * AGENT + a) * HDIM + d] = acc[i];
            a += 4;
        }
    }
    if (tid < AGENT) {
        pms[(((size_t)s * 128 + bh) * AGENT + tid) * 2 + 0] = sm_m[tid];
        pms[(((size_t)s * 128 + bh) * AGENT + tid) * 2 + 1] = sm_s[tid];
    }
}

// ---- combine splits ----
__global__ __launch_bounds__(256) void agent_combine_kernel(
    const float* __restrict__ part, float* __restrict__ av)
{
    const int bh = blockIdx.x;
    const int tid = threadIdx.x;
    const int d = tid & 63, abase = tid >> 6;
    const float* pacc = part;
    const float* pms  = part + (size_t)SPLITS * 128 * AGENT * HDIM;

    int a = abase;
#pragma unroll
    for (int i = 0; i < 13; i++) {
        if (a < 49) {
            float mstar = -1e30f;
            float ms[SPLITS], ss[SPLITS];
#pragma unroll
            for (int s = 0; s < SPLITS; s++) {
                ms[s] = pms[(((size_t)s * 128 + bh) * AGENT + a) * 2 + 0];
                ss[s] = pms[(((size_t)s * 128 + bh) * AGENT + a) * 2 + 1];
                mstar = fmaxf(mstar, ms[s]);
            }
            float S = 0.f, o = 0.f;
#pragma unroll
            for (int s = 0; s < SPLITS; s++) {
                float f = __expf(ms[s] - mstar);
                S += ss[s] * f;
                o += pacc[(((size_t)s * 128 + bh) * AGENT + a) * HDIM + d] * f;
            }
            av[((size_t)bh * AGENT + a) * HDIM + d] = o / S;
        }
        a += 4;
    }
}

// ---------------- q attention (fused logits+softmax+out), per token ------------------------
__global__ __launch_bounds__(224) void qattn_kernel(
    const float* __restrict__ qmat, const float* __restrict__ ag,
    const float* __restrict__ av, const float* __restrict__ ab, float* __restrict__ o)
{
    int bh = blockIdx.y; int b = bh >> 3, h = bh & 7;
    int tid = threadIdx.x;
    int n = blockIdx.x * 224 + tid;
    __shared__ __align__(16) float ahs[49][64];
    __shared__ __align__(16) float avs[49][64];
    for (int i = tid; i < 49 * 16; i += 224) {
        int a = i >> 4, d4 = (i & 15) * 4;
        *(float4*)&ahs[a][d4] = *(const float4*)&ag[((size_t)b * AGENT + a) * CDIM + h * 64 + d4];
        *(float4*)&avs[a][d4] = *(const float4*)&av[((size_t)bh * AGENT + a) * HDIM + d4];
    }
    __syncthreads();

    float4 qv[16];
    const float4* qrow = (const float4*)&qmat[((size_t)b * NTOK + n) * CDIM + h * 64];
#pragma unroll
    for (int i = 0; i < 16; i++) qv[i] = qrow[i];

    float l[49];
    const float* abrow = &ab[((size_t)h * NTOK + n) * AGENT];
#pragma unroll
    for (int a = 0; a < 49; a++) {
        float s = 0.f;
#pragma unroll
        for (int i = 0; i < 16; i++) {
            float4 hv = *(const float4*)&ahs[a][i * 4];
            s += qv[i].x * hv.x + qv[i].y * hv.y + qv[i].z * hv.z + qv[i].w * hv.w;
        }
        l[a] = s * 0.125f + abrow[a];
    }
    float m = -1e30f;
#pragma unroll
    for (int a = 0; a < 49; a++) m = fmaxf(m, l[a]);
    float sum = 0.f;
#pragma unroll
    for (int a = 0; a < 49; a++) { l[a] = __expf(l[a] - m); sum += l[a]; }
    float inv = 1.0f / sum;
#pragma unroll
    for (int a = 0; a < 49; a++) l[a] *= inv;

    float* orow = &o[((size_t)b * NTOK + n) * CDIM + h * 64];
#pragma unroll
    for (int i = 0; i < 16; i++) {
        float4 acc = {0.f, 0.f, 0.f, 0.f};
#pragma unroll
        for (int a = 0; a < 49; a++) {
            float4 hv = *(const float4*)&avs[a][i * 4];
            acc.x += l[a] * hv.x; acc.y += l[a] * hv.y;
            acc.z += l[a] * hv.z; acc.w += l[a] * hv.w;
        }
        *(float4*)&orow[i * 4] = acc;
    }
}

// ------- depthwise 3x3 conv on v, add to o, emit tf32-converted proj input -------
__global__ __launch_bounds__(512) void dwc_kernel(
    const float* __restrict__ v, const float* __restrict__ w,
    const float* __restrict__ bias, const float* __restrict__ o,
    float* __restrict__ oc)
{
    int c = threadIdx.x;
    int n = blockIdx.x;
    int b = blockIdx.y;
    int y = n / WW, x = n % WW;
    float acc = bias[c];
#pragma unroll
    for (int dy = -1; dy <= 1; dy++) {
        int yy = y + dy; if (yy < 0 || yy >= HH) continue;
#pragma unroll
        for (int dx = -1; dx <= 1; dx++) {
            int xx = x + dx; if (xx < 0 || xx >= WW) continue;
            acc += v[((size_t)b * NTOK + yy * WW + xx) * CDIM + c] *
                   w[c * 9 + (dy + 1) * 3 + (dx + 1)];
        }
    }
    size_t idx = ((size_t)b * NTOK + n) * CDIM + c;
    oc[idx] = __uint_as_float(f2tf32(o[idx] + acc));
}

// ---------------- launch ----------------
extern "C" void kernel_launch(void* const* d_in, const int* in_sizes, int n_in,
                              void* d_out, int out_size)
{
    const float* x      = (const float*)d_in[0];
    const float* q_w    = (const float*)d_in[3];
    const float* kv_w   = (const float*)d_in[4];
    const float* proj_w = (const float*)d_in[5];
    const float* proj_b = (const float*)d_in[6];
    const float* dwc_w  = (const float*)d_in[7];
    const float* dwc_b  = (const float*)d_in[8];
    const float* an_b   = (const float*)d_in[9];
    const float* na_b   = (const float*)d_in[10];
    const float* ah_b   = (const float*)d_in[11];
    const float* aw_b   = (const float*)d_in[12];
    const float* ha_b   = (const float*)d_in[13];
    const float* wa_b   = (const float*)d_in[14];
    float* out = (float*)d_out;

    float *qp, *kp, *vp, *op, *xc, *oc, *wc, *prt, *agp, *avp, *pbp, *abp;
    cudaGetSymbolAddress((void**)&qp,  g_q);
    cudaGetSymbolAddress((void**)&kp,  g_k);
    cudaGetSymbolAddress((void**)&vp,  g_v);
    cudaGetSymbolAddress((void**)&op,  g_o);
    cudaGetSymbolAddress((void**)&xc,  g_xc);
    cudaGetSymbolAddress((void**)&oc,  g_oc);
    cudaGetSymbolAddress((void**)&wc,  g_wc);
    cudaGetSymbolAddress((void**)&prt, g_part);
    cudaGetSymbolAddress((void**)&agp, g_agent);
    cudaGetSymbolAddress((void**)&avp, g_agentv);
    cudaGetSymbolAddress((void**)&pbp, g_pb);
    cudaGetSymbolAddress((void**)&abp, g_ab);

    cudaFuncSetAttribute(mma_gemm, cudaFuncAttributeMaxDynamicSharedMemorySize, GEMM_SMEM);
    cudaFuncSetAttribute(agent_fused_kernel, cudaFuncAttributeMaxDynamicSharedMemorySize, AF_SMEM);

    // pre-convert x and weights to tf32
    {
        int n4 = MALL * CDIM / 4;
        tf32_conv_kernel<<<(n4 + 255) / 256, 256>>>(x, xc, n4);
        int w4 = CDIM * CDIM / 4;
        tf32_conv_kernel<<<(w4 + 255) / 256, 256>>>(q_w, wc, w4);
        tf32_conv_kernel<<<(2 * w4 + 255) / 256, 256>>>(kv_w, wc + CDIM * CDIM, 2 * w4);
        tf32_conv_kernel<<<(w4 + 255) / 256, 256>>>(proj_w, wc + 3 * CDIM * CDIM, w4);
    }

    dim3 ggrid(CDIM / 128, MALL / 128);   // x = N tiles, y = M tiles
    mma_gemm<<<ggrid, 256, GEMM_SMEM>>>(xc, wc, qp, nullptr);
    pool_kernel<<<BATCH * AGENT, CDIM>>>(qp, agp);
    bias_kernel<<<HEADS * AGENT, 256>>>(an_b, na_b, ah_b, aw_b, ha_b, wa_b, pbp, abp);
    mma_gemm<<<ggrid, 256, GEMM_SMEM>>>(xc, wc + CDIM * CDIM, kp, nullptr);
    mma_gemm<<<ggrid, 256, GEMM_SMEM>>>(xc, wc + 2 * CDIM * CDIM, vp, nullptr);

    agent_fused_kernel<<<dim3(SPLITS, BATCH * HEADS), 256, AF_SMEM>>>(agp, kp, vp, pbp, prt);
    agent_combine_kernel<<<BATCH * HEADS, 256>>>(prt, avp);

    qattn_kernel<<<dim3(NTOK / 224, BATCH * HEADS), 224>>>(qp, agp, avp, abp, op);
    dwc_kernel<<<dim3(NTOK, BATCH), CDIM>>>(vp, dwc_w, dwc_b, op, oc);

    mma_gemm<<<ggrid, 256, GEMM_SMEM>>>(oc, wc + 3 * CDIM * CDIM, out, proj_b);
}

// round 9
// speedup vs baseline: 2.5722x; 1.2004x over previous
#include <cuda_runtime.h>
#include <cuda_bf16.h>
#include <cstdint>

// ---------------- problem constants ----------------
#define BATCH 16
#define CDIM  512
#define HH    56
#define WW    56
#define NTOK  3136          // 56*56
#define HEADS 8
#define HDIM  64
#define AGENT 49
#define MALL  (BATCH*NTOK)  // 50176
#define SPLITS 7
#define NSPL  448           // NTOK / SPLITS

// ---------------- scratch (static device memory; no allocation) ----------------
__device__ float g_q[MALL*CDIM];
__device__ float g_k[MALL*CDIM];
__device__ float g_v[MALL*CDIM];
__device__ float g_o[MALL*CDIM];
__device__ float g_xc[MALL*CDIM];      // x pre-converted to tf32
__device__ float g_oc[MALL*CDIM];      // (o + dwc) pre-converted to tf32
__device__ float g_wc[4*CDIM*CDIM];    // q_w | k_w | v_w | proj_w, tf32
__device__ float g_part[SPLITS*BATCH*HEADS*AGENT*(HDIM+2) + 1024];
__device__ float g_agent[BATCH*AGENT*CDIM];
__device__ float g_agentv[BATCH*HEADS*AGENT*HDIM];
__device__ float g_pb[HEADS*AGENT*NTOK];
__device__ float g_ab[HEADS*NTOK*AGENT];

// ================= helpers =================
__device__ __forceinline__ uint32_t f2tf32(float f) {
    uint32_t u;
    asm("cvt.rna.tf32.f32 %0, %1;" : "=r"(u) : "f"(f));
    return u;
}
__device__ __forceinline__ uint32_t smem_u32(const void* p) {
    uint32_t a;
    asm("{ .reg .u64 t; cvta.to.shared.u64 t, %1; cvt.u32.u64 %0, t; }" : "=r"(a) : "l"(p));
    return a;
}
__device__ __forceinline__ void mma_16x8x8(float* d, const uint32_t* a, const uint32_t* b) {
    asm volatile(
        "mma.sync.aligned.m16n8k8.row.col.f32.tf32.tf32.f32 "
        "{%0,%1,%2,%3}, {%4,%5,%6,%7}, {%8,%9}, {%0,%1,%2,%3};"
        : "+f"(d[0]), "+f"(d[1]), "+f"(d[2]), "+f"(d[3])
        : "r"(a[0]), "r"(a[1]), "r"(a[2]), "r"(a[3]), "r"(b[0]), "r"(b[1]));
}
#define LDSM_X4(r, addr) \
    asm volatile("ldmatrix.sync.aligned.m8n8.x4.shared.b16 {%0,%1,%2,%3}, [%4];" \
        : "=r"((r)[0]), "=r"((r)[1]), "=r"((r)[2]), "=r"((r)[3]) : "r"(addr))
#define CP_ASYNC16(dst, src) \
    asm volatile("cp.async.cg.shared.global [%0], [%1], 16;" :: "r"(dst), "l"(src))

// ---------------- tf32 pre-conversion (elementwise, float4) ----------------
__global__ __launch_bounds__(256) void tf32_conv_kernel(
    const float* __restrict__ in, float* __restrict__ out, int n4)
{
    int i = blockIdx.x * 256 + threadIdx.x;
    if (i < n4) {
        float4 v = ((const float4*)in)[i];
        uint4 u;
        u.x = f2tf32(v.x); u.y = f2tf32(v.y); u.z = f2tf32(v.z); u.w = f2tf32(v.w);
        ((uint4*)out)[i] = u;
    }
}

// ======= tf32 tensor-core GEMM: C[m,n] = sum_k A[m,k]*W[n,k] (+bias[n]) =======
#define GSTG 3
#define TILEW (128*32)
#define STG_WORDS (2*TILEW)
#define GEMM_SMEM (GSTG*STG_WORDS*4)   // 98304 bytes

__global__ void __launch_bounds__(256, 2) mma_gemm(
    const float* __restrict__ A, const float* __restrict__ W,
    float* __restrict__ C, const float* __restrict__ bias)
{
    extern __shared__ float sm[];
    const int tid = threadIdx.x;
    const int wid = tid >> 5, lane = tid & 31;
    const int wm = (wid >> 2) * 64;
    const int wn = (wid & 3) * 32;
    const int g = lane >> 2, tg = lane & 3;
    const int bm = blockIdx.y * 128, bn = blockIdx.x * 128;
    const uint32_t smBase = smem_u32(sm);

    const float* aSrc[4];
    const float* wSrc[4];
    uint32_t dOff[4];
#pragma unroll
    for (int i = 0; i < 4; i++) {
        int id = i * 256 + tid;
        int r = id >> 3, c4 = id & 7;
        aSrc[i] = A + (size_t)(bm + r) * 512 + c4 * 4;
        wSrc[i] = W + (size_t)(bn + r) * 512 + c4 * 4;
        dOff[i] = (uint32_t)(r * 32 + ((c4 ^ (r & 7)) << 2)) * 4;
    }

    const int mA = lane >> 3;
    const int rowA_base = wm + ((mA & 1) << 3) + (lane & 7);
    const int c4bA = mA >> 1;
    const int rowB_base = wn + ((lane >> 4) << 3) + (lane & 7);
    const int c4bB = (lane >> 3) & 1;

    float acc[4][4][4];
#pragma unroll
    for (int mi = 0; mi < 4; mi++)
#pragma unroll
        for (int ni = 0; ni < 4; ni++)
#pragma unroll
            for (int j = 0; j < 4; j++) acc[mi][ni][j] = 0.f;

#pragma unroll
    for (int kc = 0; kc < 2; kc++) {
        uint32_t sA = smBase + (uint32_t)(kc % GSTG) * STG_WORDS * 4;
        uint32_t sB = sA + TILEW * 4;
        int koff = kc * 32;
#pragma unroll
        for (int i = 0; i < 4; i++) {
            CP_ASYNC16(sA + dOff[i], aSrc[i] + koff);
            CP_ASYNC16(sB + dOff[i], wSrc[i] + koff);
        }
        asm volatile("cp.async.commit_group;");
    }

    for (int kc = 0; kc < 16; kc++) {
        if (kc < 15) asm volatile("cp.async.wait_group 1;");
        else         asm volatile("cp.async.wait_group 0;");
        __syncthreads();
        if (kc + 2 < 16) {
            uint32_t sA = smBase + (uint32_t)((kc + 2) % GSTG) * STG_WORDS * 4;
            uint32_t sB = sA + TILEW * 4;
            int koff = (kc + 2) * 32;
#pragma unroll
            for (int i = 0; i < 4; i++) {
                CP_ASYNC16(sA + dOff[i], aSrc[i] + koff);
                CP_ASYNC16(sB + dOff[i], wSrc[i] + koff);
            }
            asm volatile("cp.async.commit_group;");
        }
        const uint32_t sA = smBase + (uint32_t)(kc % GSTG) * STG_WORDS * 4;
        const uint32_t sB = sA + TILEW * 4;
#pragma unroll
        for (int ks = 0; ks < 4; ks++) {
            uint32_t aF[4][4], bF[2][4];
#pragma unroll
            for (int mi = 0; mi < 4; mi++) {
                int row = rowA_base + mi * 16;
                int c4 = (2 * ks) | c4bA;
                uint32_t off = (uint32_t)(row * 32 + ((c4 ^ (row & 7)) << 2)) * 4;
                LDSM_X4(aF[mi], sA + off);
            }
#pragma unroll
            for (int p = 0; p < 2; p++) {
                int row = rowB_base + p * 16;
                int c4 = (2 * ks) | c4bB;
                uint32_t off = (uint32_t)(row * 32 + ((c4 ^ (row & 7)) << 2)) * 4;
                LDSM_X4(bF[p], sB + off);
            }
#pragma unroll
            for (int mi = 0; mi < 4; mi++)
#pragma unroll
                for (int p = 0; p < 2; p++) {
                    mma_16x8x8(acc[mi][2 * p],     aF[mi], &bF[p][0]);
                    mma_16x8x8(acc[mi][2 * p + 1], aF[mi], &bF[p][2]);
                }
        }
    }

#pragma unroll
    for (int mi = 0; mi < 4; mi++) {
        int row = bm + wm + mi * 16 + g;
#pragma unroll
        for (int ni = 0; ni < 4; ni++) {
            int col = bn + wn + ni * 8 + 2 * tg;
            float b0 = 0.f, b1 = 0.f;
            if (bias) { b0 = bias[col]; b1 = bias[col + 1]; }
            float2 v0 = { acc[mi][ni][0] + b0, acc[mi][ni][1] + b1 };
            float2 v1 = { acc[mi][ni][2] + b0, acc[mi][ni][3] + b1 };
            *(float2*)&C[(size_t)row * 512 + col] = v0;
            *(float2*)&C[(size_t)(row + 8) * 512 + col] = v1;
        }
    }
}

// ---------------- agent token pooling ----------------
__global__ __launch_bounds__(512) void pool_kernel(const float* __restrict__ q,
                                                   float* __restrict__ ag)
{
    int c = threadIdx.x;
    int b = blockIdx.x / AGENT;
    int a = blockIdx.x % AGENT;
    int p1 = a / 7, p2 = a % 7;
    float s = 0.f;
#pragma unroll
    for (int i = 0; i < 8; i++)
#pragma unroll
        for (int j = 0; j < 8; j++)
            s += q[((size_t)b * NTOK + (p1 * 8 + i) * WW + (p2 * 8 + j)) * CDIM + c];
    ag[((size_t)b * AGENT + a) * CDIM + c] = s * (1.0f / 64.0f);
}

// ---------------- bias precompute ----------------
__global__ __launch_bounds__(256) void bias_kernel(
    const float* __restrict__ an, const float* __restrict__ na,
    const float* __restrict__ ahb, const float* __restrict__ awb,
    const float* __restrict__ hab, const float* __restrict__ wab,
    float* __restrict__ pb, float* __restrict__ ab)
{
    int h = blockIdx.x / AGENT;
    int a = blockIdx.x % AGENT;
    __shared__ float ans[49], nas[49];
    int tid = threadIdx.x;
    if (tid < 49) {
        ans[tid] = an[((size_t)h * AGENT + a) * 49 + tid];
        nas[tid] = na[((size_t)h * AGENT + a) * 49 + tid];
    }
    __syncthreads();
    for (int n = tid; n < NTOK; n += 256) {
        int y = n / WW, x = n % WW;
        float fy = (y + 0.5f) * 0.125f - 0.5f;
        float fx = (x + 0.5f) * 0.125f - 0.5f;
        int iy = (int)floorf(fy); float ty = fy - iy;
        int ix = (int)floorf(fx); float tx = fx - ix;
        float wy0 = 1.f - ty, wy1 = ty;
        int y0 = iy, y1 = iy + 1;
        if (y0 < 0) { wy0 = 0.f; y0 = 0; }
        if (y1 > 6) { wy1 = 0.f; y1 = 6; }
        float sy = wy0 + wy1; wy0 /= sy; wy1 /= sy;
        float wx0 = 1.f - tx, wx1 = tx;
        int x0 = ix, x1 = ix + 1;
        if (x0 < 0) { wx0 = 0.f; x0 = 0; }
        if (x1 > 6) { wx1 = 0.f; x1 = 6; }
        float sx = wx0 + wx1; wx0 /= sx; wx1 /= sx;

        float bi_an = wy0 * (wx0 * ans[y0 * 7 + x0] + wx1 * ans[y0 * 7 + x1]) +
                      wy1 * (wx0 * ans[y1 * 7 + x0] + wx1 * ans[y1 * 7 + x1]);
        float bi_na = wy0 * (wx0 * nas[y0 * 7 + x0] + wx1 * nas[y0 * 7 + x1]) +
                      wy1 * (wx0 * nas[y1 * 7 + x0] + wx1 * nas[y1 * 7 + x1]);

        pb[((size_t)h * AGENT + a) * NTOK + n] =
            bi_an + ahb[((size_t)h * AGENT + a) * 56 + y] + awb[((size_t)h * AGENT + a) * 56 + x];
        ab[((size_t)h * NTOK + n) * AGENT + a] =
            bi_na + hab[((size_t)h * 56 + y) * AGENT + a] + wab[((size_t)h * 56 + x) * AGENT + a];
    }
}

// ============ fused agent attention (logits + softmax + attn@V), split over n ============
#define AF_SMEM ((AGENT*HDIM + HDIM*65 + AGENT*NSPL) * 4)

__global__ __launch_bounds__(256) void agent_fused_kernel(
    const float* __restrict__ ag, const float* __restrict__ kmat,
    const float* __restrict__ vmat, const float* __restrict__ pb,
    float* __restrict__ part)
{
    extern __shared__ float smf[];
    float* ahs = smf;
    float* kvb = ahs + AGENT * HDIM;
    float* L   = kvb + HDIM * 65;
    __shared__ float sm_m[AGENT], sm_s[AGENT];

    const int s  = blockIdx.x;
    const int bh = blockIdx.y;
    const int b = bh >> 3, h = bh & 7;
    const int tid = threadIdx.x;
    const int nl = tid & 63, abase = tid >> 6;
    const int n0base = s * NSPL;

    for (int i = tid; i < AGENT * HDIM; i += 256) {
        int a = i >> 6, d = i & 63;
        ahs[i] = ag[((size_t)b * AGENT + a) * CDIM + h * 64 + d] * 0.125f;
    }

    for (int c = 0; c < 7; c++) {
        int n0 = n0base + c * 64;
        __syncthreads();
        for (int i = tid; i < 64 * 16; i += 256) {
            int nn = i >> 4, d4 = (i & 15) * 4;
            float4 v = *(const float4*)&kmat[((size_t)b * NTOK + n0 + nn) * CDIM + h * 64 + d4];
            kvb[nn * 65 + d4] = v.x; kvb[nn * 65 + d4 + 1] = v.y;
            kvb[nn * 65 + d4 + 2] = v.z; kvb[nn * 65 + d4 + 3] = v.w;
        }
        __syncthreads();
        float acc[13];
#pragma unroll
        for (int i = 0; i < 13; i++) acc[i] = 0.f;
#pragma unroll 8
        for (int d = 0; d < 64; d++) {
            float kd = kvb[nl * 65 + d];
            int a = abase;
#pragma unroll
            for (int i = 0; i < 13; i++) { if (a < 49) acc[i] += ahs[a * 64 + d] * kd; a += 4; }
        }
        int a = abase;
#pragma unroll
        for (int i = 0; i < 13; i++) {
            if (a < 49)
                L[a * NSPL + c * 64 + nl] = acc[i] + pb[((size_t)h * AGENT + a) * NTOK + n0 + nl];
            a += 4;
        }
    }
    __syncthreads();

    {
        int w = tid >> 5, lane = tid & 31;
        for (int a = w; a < AGENT; a += 8) {
            float m = -1e30f;
            for (int j = lane; j < NSPL; j += 32) m = fmaxf(m, L[a * NSPL + j]);
#pragma unroll
            for (int o = 16; o > 0; o >>= 1) m = fmaxf(m, __shfl_xor_sync(0xffffffffu, m, o));
            float sum = 0.f;
            for (int j = lane; j < NSPL; j += 32) {
                float e = __expf(L[a * NSPL + j] - m);
                L[a * NSPL + j] = e;
                sum += e;
            }
#pragma unroll
            for (int o = 16; o > 0; o >>= 1) sum += __shfl_xor_sync(0xffffffffu, sum, o);
            if (lane == 0) { sm_m[a] = m; sm_s[a] = sum; }
        }
    }
    __syncthreads();

    float acc[13];
#pragma unroll
    for (int i = 0; i < 13; i++) acc[i] = 0.f;
    const int d = nl;
    for (int c = 0; c < 7; c++) {
        int n0 = n0base + c * 64;
        __syncthreads();
        for (int i = tid; i < 64 * 16; i += 256) {
            int nn = i >> 4, d4 = (i & 15) * 4;
            float4 v = *(const float4*)&vmat[((size_t)b * NTOK + n0 + nn) * CDIM + h * 64 + d4];
            kvb[nn * 65 + d4] = v.x; kvb[nn * 65 + d4 + 1] = v.y;
            kvb[nn * 65 + d4 + 2] = v.z; kvb[nn * 65 + d4 + 3] = v.w;
        }
        __syncthreads();
#pragma unroll 8
        for (int nn = 0; nn < 64; nn++) {
            float vd = kvb[nn * 65 + d];
            int a = abase;
#pragma unroll
            for (int i = 0; i < 13; i++) { if (a < 49) acc[i] += L[a * NSPL + c * 64 + nn] * vd; a += 4; }
        }
    }

    float* pacc = part;
    float* pms  = part + (size_t)SPLITS * 128 * AGENT * HDIM;
    {
        int a = abase;
#pragma unroll
        for (int i = 0; i < 13; i++) {
            if (a < 49) pacc[(((size_t)s * 128 + bh) * AGENT + a) * HDIM + d] = acc[i];
            a += 4;
        }
    }
    if (tid < AGENT) {
        pms[(((size_t)s * 128 + bh) * AGENT + tid) * 2 + 0] = sm_m[tid];
        pms[(((size_t)s * 128 + bh) * AGENT + tid) * 2 + 1] = sm_s[tid];
    }
}

// ---- combine splits ----
__global__ __launch_bounds__(256) void agent_combine_kernel(
    const float* __restrict__ part, float* __restrict__ av)
{
    const int bh = blockIdx.x;
    const int tid = threadIdx.x;
    const int d = tid & 63, abase = tid >> 6;
    const float* pacc = part;
    const float* pms  = part + (size_t)SPLITS * 128 * AGENT * HDIM;

    int a = abase;
#pragma unroll
    for (int i = 0; i < 13; i++) {
        if (a < 49) {
            float mstar = -1e30f;
            float ms[SPLITS], ss[SPLITS];
#pragma unroll
            for (int s = 0; s < SPLITS; s++) {
                ms[s] = pms[(((size_t)s * 128 + bh) * AGENT + a) * 2 + 0];
                ss[s] = pms[(((size_t)s * 128 + bh) * AGENT + a) * 2 + 1];
                mstar = fmaxf(mstar, ms[s]);
            }
            float S = 0.f, o = 0.f;
#pragma unroll
            for (int s = 0; s < SPLITS; s++) {
                float f = __expf(ms[s] - mstar);
                S += ss[s] * f;
                o += pacc[(((size_t)s * 128 + bh) * AGENT + a) * HDIM + d] * f;
            }
            av[((size_t)bh * AGENT + a) * HDIM + d] = o / S;
        }
        a += 4;
    }
}

// ======= q attention via tensor cores: logits mma + softmax-in-frag + P@AV mma =======
// grid (28, 128): 112 token-rows per CTA, one (b,h). 7 warps x 16 rows.
// Smem words: Q/P [2][112][32]=7168, AH [2][64][32]=4096, AVt [2][64][32]=4096, ab 112*49=5488
#define QA_SMEM (20848*4)

__global__ void __launch_bounds__(224, 2) qattn_mma(
    const float* __restrict__ qmat, const float* __restrict__ ag,
    const float* __restrict__ av, const float* __restrict__ ab, float* __restrict__ o)
{
    extern __shared__ float sq[];
    const int bh = blockIdx.y, b = bh >> 3, h = bh & 7;
    const int n0 = blockIdx.x * 112;
    const int tid = threadIdx.x, wid = tid >> 5, lane = tid & 31;
    const int g = lane >> 2, tg = lane & 3;
    const uint32_t smBase = smem_u32(sq);

    float* Qs  = sq;            // [2][112][32] swizzled; reused for P
    float* AHs = sq + 7168;     // [2][64][32] swizzled, rows>=49 zero
    float* AVt = sq + 11264;    // [2][64][32] swizzled (rows=d, cols=a), a>=49 zero
    float* ABs = sq + 15360;    // [112][49] linear

    // ---- stage Q (tf32) ----
    for (int i = tid; i < 112 * 16; i += 224) {
        int r = i >> 4, d4 = i & 15;
        int chunk = d4 >> 3, c4 = d4 & 7;
        float4 v = *(const float4*)&qmat[((size_t)b * NTOK + n0 + r) * 512 + h * 64 + d4 * 4];
        uint4 u = { f2tf32(v.x), f2tf32(v.y), f2tf32(v.z), f2tf32(v.w) };
        *(uint4*)&Qs[chunk * 3584 + r * 32 + ((c4 ^ (r & 7)) << 2)] = u;
    }
    // ---- stage AH (scaled, tf32, padded) ----
    for (int i = tid; i < 64 * 16; i += 224) {
        int a = i >> 4, d4 = i & 15;
        int chunk = d4 >> 3, c4 = d4 & 7;
        uint4 u = {0u, 0u, 0u, 0u};
        if (a < 49) {
            float4 v = *(const float4*)&ag[((size_t)b * AGENT + a) * CDIM + h * 64 + d4 * 4];
            u.x = f2tf32(v.x * 0.125f); u.y = f2tf32(v.y * 0.125f);
            u.z = f2tf32(v.z * 0.125f); u.w = f2tf32(v.w * 0.125f);
        }
        *(uint4*)&AHs[chunk * 2048 + a * 32 + ((c4 ^ (a & 7)) << 2)] = u;
    }
    // ---- stage AVt (transposed, tf32, padded) ----
    for (int i = tid; i < 64 * 16; i += 224) {
        int d = i >> 4, a4 = i & 15;
        int chunk = a4 >> 3, c4 = a4 & 7;
        uint32_t uu[4] = {0u, 0u, 0u, 0u};
#pragma unroll
        for (int j = 0; j < 4; j++) {
            int a = a4 * 4 + j;
            if (a < 49) uu[j] = f2tf32(av[((size_t)bh * AGENT + a) * HDIM + d]);
        }
        uint4 u = { uu[0], uu[1], uu[2], uu[3] };
        *(uint4*)&AVt[chunk * 2048 + d * 32 + ((c4 ^ (d & 7)) << 2)] = u;
    }
    // ---- stage ab rows (contiguous 112*49 floats, 64B-aligned base) ----
    {
        const float4* src = (const float4*)(ab + ((size_t)h * NTOK + n0) * 49);
        for (int i = tid; i < 112 * 49 / 4; i += 224) ((float4*)ABs)[i] = src[i];
    }
    __syncthreads();

    const int wm = wid * 16;
    const int mA = lane >> 3;
    const int rA = wm + ((mA & 1) << 3) + (lane & 7);
    const int c4bA = mA >> 1;
    const int rB = ((lane >> 4) << 3) + (lane & 7);
    const int c4bB = (lane >> 3) & 1;

    // ---- logits mma: acc[nt] covers cols nt*8..nt*8+7 for rows (wm+g, wm+g+8) ----
    float acc[7][4];
#pragma unroll
    for (int nt = 0; nt < 7; nt++)
#pragma unroll
        for (int j = 0; j < 4; j++) acc[nt][j] = 0.f;

#pragma unroll
    for (int chunk = 0; chunk < 2; chunk++)
#pragma unroll
        for (int ks = 0; ks < 4; ks++) {
            uint32_t aF[4], bF[4][4];
            {
                int c4 = (2 * ks) | c4bA;
                LDSM_X4(aF, smBase + (uint32_t)(chunk * 3584 + rA * 32 + ((c4 ^ (rA & 7)) << 2)) * 4);
            }
            int c4b = (2 * ks) | c4bB;
#pragma unroll
            for (int p = 0; p < 4; p++) {
                int row = p * 16 + rB;
                LDSM_X4(bF[p], smBase + (uint32_t)(7168 * 4) +
                        (uint32_t)(chunk * 2048 + row * 32 + ((c4b ^ (row & 7)) << 2)) * 4);
            }
#pragma unroll
            for (int nt = 0; nt < 7; nt++)
                mma_16x8x8(acc[nt], aF, &bF[nt >> 1][(nt & 1) * 2]);
        }

    // ---- bias + mask + softmax in fragments (quad reduction over tg lanes) ----
    const int rl0 = wm + g;
    float m0 = -1e30f, m8 = -1e30f;
    float vals[7][4];
#pragma unroll
    for (int nt = 0; nt < 7; nt++) {
        int c0 = nt * 8 + 2 * tg, c1 = c0 + 1;
        float v0 = (c0 < 49) ? acc[nt][0] + ABs[rl0 * 49 + c0]       : -1e30f;
        float v1 = (c1 < 49) ? acc[nt][1] + ABs[rl0 * 49 + c1]       : -1e30f;
        float v2 = (c0 < 49) ? acc[nt][2] + ABs[(rl0 + 8) * 49 + c0] : -1e30f;
        float v3 = (c1 < 49) ? acc[nt][3] + ABs[(rl0 + 8) * 49 + c1] : -1e30f;
        vals[nt][0] = v0; vals[nt][1] = v1; vals[nt][2] = v2; vals[nt][3] = v3;
        m0 = fmaxf(m0, fmaxf(v0, v1));
        m8 = fmaxf(m8, fmaxf(v2, v3));
    }
    m0 = fmaxf(m0, __shfl_xor_sync(0xffffffffu, m0, 1));
    m0 = fmaxf(m0, __shfl_xor_sync(0xffffffffu, m0, 2));
    m8 = fmaxf(m8, __shfl_xor_sync(0xffffffffu, m8, 1));
    m8 = fmaxf(m8, __shfl_xor_sync(0xffffffffu, m8, 2));
    float s0 = 0.f, s8 = 0.f;
#pragma unroll
    for (int nt = 0; nt < 7; nt++) {
        int c0 = nt * 8 + 2 * tg, c1 = c0 + 1;
        float e0 = (c0 < 49) ? __expf(vals[nt][0] - m0) : 0.f;
        float e1 = (c1 < 49) ? __expf(vals[nt][1] - m0) : 0.f;
        float e2 = (c0 < 49) ? __expf(vals[nt][2] - m8) : 0.f;
        float e3 = (c1 < 49) ? __expf(vals[nt][3] - m8) : 0.f;
        vals[nt][0] = e0; vals[nt][1] = e1; vals[nt][2] = e2; vals[nt][3] = e3;
        s0 += e0 + e1; s8 += e2 + e3;
    }
    s0 += __shfl_xor_sync(0xffffffffu, s0, 1);
    s0 += __shfl_xor_sync(0xffffffffu, s0, 2);
    s8 += __shfl_xor_sync(0xffffffffu, s8, 1);
    s8 += __shfl_xor_sync(0xffffffffu, s8, 2);
    const float i0 = 1.0f / s0, i8 = 1.0f / s8;

    // ---- store normalized P (tf32) into Q buffer — warp-local rows only ----
#pragma unroll
    for (int nt = 0; nt < 7; nt++) {
        int c0 = nt * 8 + 2 * tg;
        int chunk = c0 >> 5, cw = c0 & 31, c4 = cw >> 2;
        uint32_t o0 = chunk * 3584 + rl0 * 32 + ((c4 ^ (rl0 & 7)) << 2) + (cw & 3);
        uint32_t o8 = chunk * 3584 + (rl0 + 8) * 32 + ((c4 ^ ((rl0 + 8) & 7)) << 2) + (cw & 3);
        uint2 u0 = { f2tf32(vals[nt][0] * i0), f2tf32(vals[nt][1] * i0) };
        uint2 u8 = { f2tf32(vals[nt][2] * i8), f2tf32(vals[nt][3] * i8) };
        *(uint2*)&Qs[o0] = u0;
        *(uint2*)&Qs[o8] = u8;
    }
    __syncwarp();

    // ---- out mma: P[16,64pad] @ AVt -> out[16,64] ----
    float ao[8][4];
#pragma unroll
    for (int nt = 0; nt < 8; nt++)
#pragma unroll
        for (int j = 0; j < 4; j++) ao[nt][j] = 0.f;

#pragma unroll
    for (int chunk = 0; chunk < 2; chunk++)
#pragma unroll
        for (int ks = 0; ks < 4; ks++) {
            uint32_t aF[4], bF[4][4];
            {
                int c4 = (2 * ks) | c4bA;
                LDSM_X4(aF, smBase + (uint32_t)(chunk * 3584 + rA * 32 + ((c4 ^ (rA & 7)) << 2)) * 4);
            }
            int c4b = (2 * ks) | c4bB;
#pragma unroll
            for (int p = 0; p < 4; p++) {
                int row = p * 16 + rB;
                LDSM_X4(bF[p], smBase + (uint32_t)(11264 * 4) +
                        (uint32_t)(chunk * 2048 + row * 32 + ((c4b ^ (row & 7)) << 2)) * 4);
            }
#pragma unroll
            for (int nt = 0; nt < 8; nt++)
                mma_16x8x8(ao[nt], aF, &bF[nt >> 1][(nt & 1) * 2]);
        }

    // ---- epilogue ----
    const size_t row0 = (size_t)b * NTOK + n0 + rl0;
#pragma unroll
    for (int nt = 0; nt < 8; nt++) {
        int col = nt * 8 + 2 * tg;
        float2 v0 = { ao[nt][0], ao[nt][1] };
        float2 v8 = { ao[nt][2], ao[nt][3] };
        *(float2*)&o[row0 * 512 + h * 64 + col] = v0;
        *(float2*)&o[(row0 + 8) * 512 + h * 64 + col] = v8;
    }
}

// ------- depthwise 3x3 conv on v, add to o, emit tf32-converted proj input -------
__global__ __launch_bounds__(512) void dwc_kernel(
    const float* __restrict__ v, const float* __restrict__ w,
    const float* __restrict__ bias, const float* __restrict__ o,
    float* __restrict__ oc)
{
    int c = threadIdx.x;
    int n = blockIdx.x;
    int b = blockIdx.y;
    int y = n / WW, x = n % WW;
    float acc = bias[c];
#pragma unroll
    for (int dy = -1; dy <= 1; dy++) {
        int yy = y + dy; if (yy < 0 || yy >= HH) continue;
#pragma unroll
        for (int dx = -1; dx <= 1; dx++) {
            int xx = x + dx; if (xx < 0 || xx >= WW) continue;
            acc += v[((size_t)b * NTOK + yy * WW + xx) * CDIM + c] *
                   w[c * 9 + (dy + 1) * 3 + (dx + 1)];
        }
    }
    size_t idx = ((size_t)b * NTOK + n) * CDIM + c;
    oc[idx] = __uint_as_float(f2tf32(o[idx] + acc));
}

// ---------------- launch ----------------
extern "C" void kernel_launch(void* const* d_in, const int* in_sizes, int n_in,
                              void* d_out, int out_size)
{
    const float* x      = (const float*)d_in[0];
    const float* q_w    = (const float*)d_in[3];
    const float* kv_w   = (const float*)d_in[4];
    const float* proj_w = (const float*)d_in[5];
    const float* proj_b = (const float*)d_in[6];
    const float* dwc_w  = (const float*)d_in[7];
    const float* dwc_b  = (const float*)d_in[8];
    const float* an_b   = (const float*)d_in[9];
    const float* na_b   = (const float*)d_in[10];
    const float* ah_b   = (const float*)d_in[11];
    const float* aw_b   = (const float*)d_in[12];
    const float* ha_b   = (const float*)d_in[13];
    const float* wa_b   = (const float*)d_in[14];
    float* out = (float*)d_out;

    float *qp, *kp, *vp, *op, *xc, *oc, *wc, *prt, *agp, *avp, *pbp, *abp;
    cudaGetSymbolAddress((void**)&qp,  g_q);
    cudaGetSymbolAddress((void**)&kp,  g_k);
    cudaGetSymbolAddress((void**)&vp,  g_v);
    cudaGetSymbolAddress((void**)&op,  g_o);
    cudaGetSymbolAddress((void**)&xc,  g_xc);
    cudaGetSymbolAddress((void**)&oc,  g_oc);
    cudaGetSymbolAddress((void**)&wc,  g_wc);
    cudaGetSymbolAddress((void**)&prt, g_part);
    cudaGetSymbolAddress((void**)&agp, g_agent);
    cudaGetSymbolAddress((void**)&avp, g_agentv);
    cudaGetSymbolAddress((void**)&pbp, g_pb);
    cudaGetSymbolAddress((void**)&abp, g_ab);

    cudaFuncSetAttribute(mma_gemm, cudaFuncAttributeMaxDynamicSharedMemorySize, GEMM_SMEM);
    cudaFuncSetAttribute(agent_fused_kernel, cudaFuncAttributeMaxDynamicSharedMemorySize, AF_SMEM);
    cudaFuncSetAttribute(qattn_mma, cudaFuncAttributeMaxDynamicSharedMemorySize, QA_SMEM);

    // pre-convert x and weights to tf32
    {
        int n4 = MALL * CDIM / 4;
        tf32_conv_kernel<<<(n4 + 255) / 256, 256>>>(x, xc, n4);
        int w4 = CDIM * CDIM / 4;
        tf32_conv_kernel<<<(w4 + 255) / 256, 256>>>(q_w, wc, w4);
        tf32_conv_kernel<<<(2 * w4 + 255) / 256, 256>>>(kv_w, wc + CDIM * CDIM, 2 * w4);
        tf32_conv_kernel<<<(w4 + 255) / 256, 256>>>(proj_w, wc + 3 * CDIM * CDIM, w4);
    }

    dim3 ggrid(CDIM / 128, MALL / 128);
    mma_gemm<<<ggrid, 256, GEMM_SMEM>>>(xc, wc, qp, nullptr);
    pool_kernel<<<BATCH * AGENT, CDIM>>>(qp, agp);
    bias_kernel<<<HEADS * AGENT, 256>>>(an_b, na_b, ah_b, aw_b, ha_b, wa_b, pbp, abp);
    mma_gemm<<<ggrid, 256, GEMM_SMEM>>>(xc, wc + CDIM * CDIM, kp, nullptr);
    mma_gemm<<<ggrid, 256, GEMM_SMEM>>>(xc, wc + 2 * CDIM * CDIM, vp, nullptr);

    agent_fused_kernel<<<dim3(SPLITS, BATCH * HEADS), 256, AF_SMEM>>>(agp, kp, vp, pbp, prt);
    agent_combine_kernel<<<BATCH * HEADS, 256>>>(prt, avp);

    qattn_mma<<<dim3(28, BATCH * HEADS), 224, QA_SMEM>>>(qp, agp, avp, abp, op);
    dwc_kernel<<<dim3(NTOK, BATCH), CDIM>>>(vp, dwc_w, dwc_b, op, oc);

    mma_gemm<<<ggrid, 256, GEMM_SMEM>>>(oc, wc + 3 * CDIM * CDIM, out, proj_b);
}

// round 10
// speedup vs baseline: 2.7131x; 1.0548x over previous
#include <cuda_runtime.h>
#include <cuda_bf16.h>
#include <cstdint>

// ---------------- problem constants ----------------
#define BATCH 16
#define CDIM  512
#define HH    56
#define WW    56
#define NTOK  3136          // 56*56
#define HEADS 8
#define HDIM  64
#define AGENT 49
#define MALL  (BATCH*NTOK)  // 50176
#define SPLITS 7
#define NSPL  448           // NTOK / SPLITS
#define QKVD  1536          // merged qkv row stride

// ---------------- scratch (static device memory; no allocation) ----------------
__device__ float g_qkv[(size_t)MALL*QKVD];   // q | k | v interleaved per row
__device__ float g_o[MALL*CDIM];
__device__ float g_xc[MALL*CDIM];      // x pre-converted to tf32
__device__ float g_oc[MALL*CDIM];      // (o + dwc) pre-converted to tf32
__device__ float g_wc[4*CDIM*CDIM];    // q_w | k_w | v_w | proj_w, tf32
__device__ float g_part[SPLITS*BATCH*HEADS*AGENT*(HDIM+2) + 1024];
__device__ float g_agent[BATCH*AGENT*CDIM];
__device__ float g_agentv[BATCH*HEADS*AGENT*HDIM];
__device__ float g_pb[HEADS*AGENT*NTOK];
__device__ float g_ab[HEADS*NTOK*AGENT];

// ================= helpers =================
__device__ __forceinline__ uint32_t f2tf32(float f) {
    uint32_t u;
    asm("cvt.rna.tf32.f32 %0, %1;" : "=r"(u) : "f"(f));
    return u;
}
__device__ __forceinline__ uint32_t smem_u32(const void* p) {
    uint32_t a;
    asm("{ .reg .u64 t; cvta.to.shared.u64 t, %1; cvt.u32.u64 %0, t; }" : "=r"(a) : "l"(p));
    return a;
}
__device__ __forceinline__ void mma_16x8x8(float* d, const uint32_t* a, const uint32_t* b) {
    asm volatile(
        "mma.sync.aligned.m16n8k8.row.col.f32.tf32.tf32.f32 "
        "{%0,%1,%2,%3}, {%4,%5,%6,%7}, {%8,%9}, {%0,%1,%2,%3};"
        : "+f"(d[0]), "+f"(d[1]), "+f"(d[2]), "+f"(d[3])
        : "r"(a[0]), "r"(a[1]), "r"(a[2]), "r"(a[3]), "r"(b[0]), "r"(b[1]));
}
#define LDSM_X4(r, addr) \
    asm volatile("ldmatrix.sync.aligned.m8n8.x4.shared.b16 {%0,%1,%2,%3}, [%4];" \
        : "=r"((r)[0]), "=r"((r)[1]), "=r"((r)[2]), "=r"((r)[3]) : "r"(addr))
#define CP_ASYNC16(dst, src) \
    asm volatile("cp.async.cg.shared.global [%0], [%1], 16;" :: "r"(dst), "l"(src))

// ---------------- tf32 pre-conversion ----------------
__global__ __launch_bounds__(256) void tf32_conv_kernel(
    const float* __restrict__ in, float* __restrict__ out, int n4)
{
    int i = blockIdx.x * 256 + threadIdx.x;
    if (i < n4) {
        float4 v = ((const float4*)in)[i];
        uint4 u;
        u.x = f2tf32(v.x); u.y = f2tf32(v.y); u.z = f2tf32(v.z); u.w = f2tf32(v.w);
        ((uint4*)out)[i] = u;
    }
}

// ======= tf32 tensor-core GEMM: C[m,n] = sum_k A[m,k]*W[n,k] (+bias[n]) =======
// A stride fixed 512 (K=512). C stride = ldc (supports merged N=1536 output).
#define GSTG 3
#define TILEW (128*32)
#define STG_WORDS (2*TILEW)
#define GEMM_SMEM (GSTG*STG_WORDS*4)   // 98304 bytes

__global__ void __launch_bounds__(256, 2) mma_gemm(
    const float* __restrict__ A, const float* __restrict__ W,
    float* __restrict__ C, const float* __restrict__ bias, int ldc)
{
    extern __shared__ float sm[];
    const int tid = threadIdx.x;
    const int wid = tid >> 5, lane = tid & 31;
    const int wm = (wid >> 2) * 64;
    const int wn = (wid & 3) * 32;
    const int g = lane >> 2, tg = lane & 3;
    const int bm = blockIdx.y * 128, bn = blockIdx.x * 128;
    const uint32_t smBase = smem_u32(sm);

    const float* aSrc[4];
    const float* wSrc[4];
    uint32_t dOff[4];
#pragma unroll
    for (int i = 0; i < 4; i++) {
        int id = i * 256 + tid;
        int r = id >> 3, c4 = id & 7;
        aSrc[i] = A + (size_t)(bm + r) * 512 + c4 * 4;
        wSrc[i] = W + (size_t)(bn + r) * 512 + c4 * 4;
        dOff[i] = (uint32_t)(r * 32 + ((c4 ^ (r & 7)) << 2)) * 4;
    }

    const int mA = lane >> 3;
    const int rowA_base = wm + ((mA & 1) << 3) + (lane & 7);
    const int c4bA = mA >> 1;
    const int rowB_base = wn + ((lane >> 4) << 3) + (lane & 7);
    const int c4bB = (lane >> 3) & 1;

    float acc[4][4][4];
#pragma unroll
    for (int mi = 0; mi < 4; mi++)
#pragma unroll
        for (int ni = 0; ni < 4; ni++)
#pragma unroll
            for (int j = 0; j < 4; j++) acc[mi][ni][j] = 0.f;

#pragma unroll
    for (int kc = 0; kc < 2; kc++) {
        uint32_t sA = smBase + (uint32_t)(kc % GSTG) * STG_WORDS * 4;
        uint32_t sB = sA + TILEW * 4;
        int koff = kc * 32;
#pragma unroll
        for (int i = 0; i < 4; i++) {
            CP_ASYNC16(sA + dOff[i], aSrc[i] + koff);
            CP_ASYNC16(sB + dOff[i], wSrc[i] + koff);
        }
        asm volatile("cp.async.commit_group;");
    }

    for (int kc = 0; kc < 16; kc++) {
        if (kc < 15) asm volatile("cp.async.wait_group 1;");
        else         asm volatile("cp.async.wait_group 0;");
        __syncthreads();
        if (kc + 2 < 16) {
            uint32_t sA = smBase + (uint32_t)((kc + 2) % GSTG) * STG_WORDS * 4;
            uint32_t sB = sA + TILEW * 4;
            int koff = (kc + 2) * 32;
#pragma unroll
            for (int i = 0; i < 4; i++) {
                CP_ASYNC16(sA + dOff[i], aSrc[i] + koff);
                CP_ASYNC16(sB + dOff[i], wSrc[i] + koff);
            }
            asm volatile("cp.async.commit_group;");
        }
        const uint32_t sA = smBase + (uint32_t)(kc % GSTG) * STG_WORDS * 4;
        const uint32_t sB = sA + TILEW * 4;
#pragma unroll
        for (int ks = 0; ks < 4; ks++) {
            uint32_t aF[4][4], bF[2][4];
#pragma unroll
            for (int mi = 0; mi < 4; mi++) {
                int row = rowA_base + mi * 16;
                int c4 = (2 * ks) | c4bA;
                uint32_t off = (uint32_t)(row * 32 + ((c4 ^ (row & 7)) << 2)) * 4;
                LDSM_X4(aF[mi], sA + off);
            }
#pragma unroll
            for (int p = 0; p < 2; p++) {
                int row = rowB_base + p * 16;
                int c4 = (2 * ks) | c4bB;
                uint32_t off = (uint32_t)(row * 32 + ((c4 ^ (row & 7)) << 2)) * 4;
                LDSM_X4(bF[p], sB + off);
            }
#pragma unroll
            for (int mi = 0; mi < 4; mi++)
#pragma unroll
                for (int p = 0; p < 2; p++) {
                    mma_16x8x8(acc[mi][2 * p],     aF[mi], &bF[p][0]);
                    mma_16x8x8(acc[mi][2 * p + 1], aF[mi], &bF[p][2]);
                }
        }
    }

#pragma unroll
    for (int mi = 0; mi < 4; mi++) {
        int row = bm + wm + mi * 16 + g;
#pragma unroll
        for (int ni = 0; ni < 4; ni++) {
            int col = bn + wn + ni * 8 + 2 * tg;
            float b0 = 0.f, b1 = 0.f;
            if (bias) { b0 = bias[col]; b1 = bias[col + 1]; }
            float2 v0 = { acc[mi][ni][0] + b0, acc[mi][ni][1] + b1 };
            float2 v1 = { acc[mi][ni][2] + b0, acc[mi][ni][3] + b1 };
            *(float2*)&C[(size_t)row * ldc + col] = v0;
            *(float2*)&C[(size_t)(row + 8) * ldc + col] = v1;
        }
    }
}

// ---------------- agent token pooling (q part of qkv, stride 1536) ----------------
__global__ __launch_bounds__(512) void pool_kernel(const float* __restrict__ qkv,
                                                   float* __restrict__ ag)
{
    int c = threadIdx.x;
    int b = blockIdx.x / AGENT;
    int a = blockIdx.x % AGENT;
    int p1 = a / 7, p2 = a % 7;
    float s = 0.f;
#pragma unroll
    for (int i = 0; i < 8; i++)
#pragma unroll
        for (int j = 0; j < 8; j++)
            s += qkv[((size_t)b * NTOK + (p1 * 8 + i) * WW + (p2 * 8 + j)) * QKVD + c];
    ag[((size_t)b * AGENT + a) * CDIM + c] = s * (1.0f / 64.0f);
}

// ---------------- bias precompute ----------------
__global__ __launch_bounds__(256) void bias_kernel(
    const float* __restrict__ an, const float* __restrict__ na,
    const float* __restrict__ ahb, const float* __restrict__ awb,
    const float* __restrict__ hab, const float* __restrict__ wab,
    float* __restrict__ pb, float* __restrict__ ab)
{
    int h = blockIdx.x / AGENT;
    int a = blockIdx.x % AGENT;
    __shared__ float ans[49], nas[49];
    int tid = threadIdx.x;
    if (tid < 49) {
        ans[tid] = an[((size_t)h * AGENT + a) * 49 + tid];
        nas[tid] = na[((size_t)h * AGENT + a) * 49 + tid];
    }
    __syncthreads();
    for (int n = tid; n < NTOK; n += 256) {
        int y = n / WW, x = n % WW;
        float fy = (y + 0.5f) * 0.125f - 0.5f;
        float fx = (x + 0.5f) * 0.125f - 0.5f;
        int iy = (int)floorf(fy); float ty = fy - iy;
        int ix = (int)floorf(fx); float tx = fx - ix;
        float wy0 = 1.f - ty, wy1 = ty;
        int y0 = iy, y1 = iy + 1;
        if (y0 < 0) { wy0 = 0.f; y0 = 0; }
        if (y1 > 6) { wy1 = 0.f; y1 = 6; }
        float sy = wy0 + wy1; wy0 /= sy; wy1 /= sy;
        float wx0 = 1.f - tx, wx1 = tx;
        int x0 = ix, x1 = ix + 1;
        if (x0 < 0) { wx0 = 0.f; x0 = 0; }
        if (x1 > 6) { wx1 = 0.f; x1 = 6; }
        float sx = wx0 + wx1; wx0 /= sx; wx1 /= sx;

        float bi_an = wy0 * (wx0 * ans[y0 * 7 + x0] + wx1 * ans[y0 * 7 + x1]) +
                      wy1 * (wx0 * ans[y1 * 7 + x0] + wx1 * ans[y1 * 7 + x1]);
        float bi_na = wy0 * (wx0 * nas[y0 * 7 + x0] + wx1 * nas[y0 * 7 + x1]) +
                      wy1 * (wx0 * nas[y1 * 7 + x0] + wx1 * nas[y1 * 7 + x1]);

        pb[((size_t)h * AGENT + a) * NTOK + n] =
            bi_an + ahb[((size_t)h * AGENT + a) * 56 + y] + awb[((size_t)h * AGENT + a) * 56 + x];
        ab[((size_t)h * NTOK + n) * AGENT + a] =
            bi_na + hab[((size_t)h * 56 + y) * AGENT + a] + wab[((size_t)h * 56 + x) * AGENT + a];
    }
}

// ============ fused agent attention: mma logits + softmax + scalar attn@V ============
// smem words: AHs [2][64][32]=4096 | Ks/Vb 4096 (+reuse) | L [49][452]=22148
#define AF_LOFF 8192
#define AF_LSTR 452
#define AF_SMEM ((AF_LOFF + AGENT*AF_LSTR) * 4)   // 121360 bytes

__global__ __launch_bounds__(256) void agent_fused_kernel(
    const float* __restrict__ ag, const float* __restrict__ qkv,
    const float* __restrict__ pb, float* __restrict__ part)
{
    extern __shared__ float smf[];
    float* AHs = smf;                 // [2][64][32] swizzled, agents padded to 64
    float* Ks  = smf + 4096;          // [2][64][32] swizzled token chunk (K); later V staging
    float* L   = smf + AF_LOFF;       // [49][452]
    __shared__ float sm_m[AGENT], sm_s[AGENT];

    const int s  = blockIdx.x;
    const int bh = blockIdx.y;
    const int b = bh >> 3, h = bh & 7;
    const int tid = threadIdx.x;
    const int wid = tid >> 5, lane = tid & 31;
    const int g = lane >> 2, tg = lane & 3;
    const int mA = lane >> 3;
    const int n0base = s * NSPL;
    const uint32_t smBase = smem_u32(smf);

    // stage AH (scaled, tf32, rows >=49 zero)
    for (int i = tid; i < 64 * 16; i += 256) {
        int a = i >> 4, d4 = i & 15;
        int chunk = d4 >> 3, c4 = d4 & 7;
        uint4 u = {0u, 0u, 0u, 0u};
        if (a < 49) {
            float4 v = *(const float4*)&ag[((size_t)b * AGENT + a) * CDIM + h * 64 + d4 * 4];
            u.x = f2tf32(v.x * 0.125f); u.y = f2tf32(v.y * 0.125f);
            u.z = f2tf32(v.z * 0.125f); u.w = f2tf32(v.w * 0.125f);
        }
        *(uint4*)&AHs[chunk * 2048 + a * 32 + ((c4 ^ (a & 7)) << 2)] = u;
    }

    // ---- Phase 1 (mma): logits per 64-token chunk ----
    const int rA = ((mA & 1) << 3) + (lane & 7);   // + mt*16
    const int c4bA = mA >> 1;
    const int rB = ((wid >> 1) * 16) + ((lane >> 4) << 3) + (lane & 7);
    const int c4bB = (lane >> 3) & 1;
    const int sub = wid & 1;

    for (int c = 0; c < 7; c++) {
        int n0 = n0base + c * 64;
        __syncthreads();
        for (int i = tid; i < 64 * 16; i += 256) {
            int nn = i >> 4, d4 = i & 15;
            int chunk = d4 >> 3, c4 = d4 & 7;
            float4 v = *(const float4*)&qkv[((size_t)b * NTOK + n0 + nn) * QKVD + 512 + h * 64 + d4 * 4];
            uint4 u = { f2tf32(v.x), f2tf32(v.y), f2tf32(v.z), f2tf32(v.w) };
            *(uint4*)&Ks[chunk * 2048 + nn * 32 + ((c4 ^ (nn & 7)) << 2)] = u;
        }
        __syncthreads();
        if (wid < 7) {
            float acc[4][4];
#pragma unroll
            for (int mt = 0; mt < 4; mt++)
#pragma unroll
                for (int j = 0; j < 4; j++) acc[mt][j] = 0.f;
#pragma unroll
            for (int chunk = 0; chunk < 2; chunk++)
#pragma unroll
                for (int ks = 0; ks < 4; ks++) {
                    uint32_t bF[4];
                    {
                        int c4 = (2 * ks) | c4bB;
                        LDSM_X4(bF, smBase + (uint32_t)(chunk * 2048 + rB * 32 + ((c4 ^ (rB & 7)) << 2)) * 4);
                    }
#pragma unroll
                    for (int mt = 0; mt < 4; mt++) {
                        uint32_t aF[4];
                        int row = mt * 16 + rA;
                        int c4 = (2 * ks) | c4bA;
                        LDSM_X4(aF, smBase + (uint32_t)(4096 + chunk * 2048 + row * 32 + ((c4 ^ (row & 7)) << 2)) * 4);
                        mma_16x8x8(acc[mt], aF, &bF[sub * 2]);
                    }
                }
            // scatter to L + pb bias
#pragma unroll
            for (int mt = 0; mt < 4; mt++)
#pragma unroll
                for (int j = 0; j < 4; j++) {
                    int a = wid * 8 + 2 * tg + (j & 1);
                    if (a < 49) {
                        int nloc = c * 64 + mt * 16 + g + ((j >> 1) << 3);
                        L[a * AF_LSTR + nloc] =
                            acc[mt][j] + pb[((size_t)h * AGENT + a) * NTOK + n0base + nloc];
                    }
                }
        }
    }
    __syncthreads();

    // ---- Phase 2: per-a max & sum; L <- exp(L - m) ----
    {
        int w = wid, ln = lane;
        for (int a = w; a < AGENT; a += 8) {
            float m = -1e30f;
            for (int j = ln; j < NSPL; j += 32) m = fmaxf(m, L[a * AF_LSTR + j]);
#pragma unroll
            for (int o = 16; o > 0; o >>= 1) m = fmaxf(m, __shfl_xor_sync(0xffffffffu, m, o));
            float sum = 0.f;
            for (int j = ln; j < NSPL; j += 32) {
                float e = __expf(L[a * AF_LSTR + j] - m);
                L[a * AF_LSTR + j] = e;
                sum += e;
            }
#pragma unroll
            for (int o = 16; o > 0; o >>= 1) sum += __shfl_xor_sync(0xffffffffu, sum, o);
            if (ln == 0) { sm_m[a] = m; sm_s[a] = sum; }
        }
    }
    __syncthreads();

    // ---- Phase 3 (scalar): partial acc[a][d] = sum_n expL * v[n][d] ----
    float* Vb = smf;   // reuse AHs+Ks region: [64][65]
    const int nl = tid & 63, abase = tid >> 6;
    float acc[13];
#pragma unroll
    for (int i = 0; i < 13; i++) acc[i] = 0.f;
    const int d = nl;
    for (int c = 0; c < 7; c++) {
        int n0 = n0base + c * 64;
        __syncthreads();
        for (int i = tid; i < 64 * 16; i += 256) {
            int nn = i >> 4, d4 = (i & 15) * 4;
            float4 v = *(const float4*)&qkv[((size_t)b * NTOK + n0 + nn) * QKVD + 1024 + h * 64 + d4];
            Vb[nn * 65 + d4] = v.x; Vb[nn * 65 + d4 + 1] = v.y;
            Vb[nn * 65 + d4 + 2] = v.z; Vb[nn * 65 + d4 + 3] = v.w;
        }
        __syncthreads();
#pragma unroll 8
        for (int nn = 0; nn < 64; nn++) {
            float vd = Vb[nn * 65 + d];
            int a = abase;
#pragma unroll
            for (int i = 0; i < 13; i++) { if (a < 49) acc[i] += L[a * AF_LSTR + c * 64 + nn] * vd; a += 4; }
        }
    }

    float* pacc = part;
    float* pms  = part + (size_t)SPLITS * 128 * AGENT * HDIM;
    {
        int a = abase;
#pragma unroll
        for (int i = 0; i < 13; i++) {
            if (a < 49) pacc[(((size_t)s * 128 + bh) * AGENT + a) * HDIM + d] = acc[i];
            a += 4;
        }
    }
    if (tid < AGENT) {
        pms[(((size_t)s * 128 + bh) * AGENT + tid) * 2 + 0] = sm_m[tid];
        pms[(((size_t)s * 128 + bh) * AGENT + tid) * 2 + 1] = sm_s[tid];
    }
}

// ---- combine splits ----
__global__ __launch_bounds__(256) void agent_combine_kernel(
    const float* __restrict__ part, float* __restrict__ av)
{
    const int bh = blockIdx.x;
    const int tid = threadIdx.x;
    const int d = tid & 63, abase = tid >> 6;
    const float* pacc = part;
    const float* pms  = part + (size_t)SPLITS * 128 * AGENT * HDIM;

    int a = abase;
#pragma unroll
    for (int i = 0; i < 13; i++) {
        if (a < 49) {
            float mstar = -1e30f;
            float ms[SPLITS], ss[SPLITS];
#pragma unroll
            for (int s = 0; s < SPLITS; s++) {
                ms[s] = pms[(((size_t)s * 128 + bh) * AGENT + a) * 2 + 0];
                ss[s] = pms[(((size_t)s * 128 + bh) * AGENT + a) * 2 + 1];
                mstar = fmaxf(mstar, ms[s]);
            }
            float S = 0.f, o = 0.f;
#pragma unroll
            for (int s = 0; s < SPLITS; s++) {
                float f = __expf(ms[s] - mstar);
                S += ss[s] * f;
                o += pacc[(((size_t)s * 128 + bh) * AGENT + a) * HDIM + d] * f;
            }
            av[((size_t)bh * AGENT + a) * HDIM + d] = o / S;
        }
        a += 4;
    }
}

// ======= q attention via tensor cores =======
#define QA_SMEM (20848*4)

__global__ void __launch_bounds__(224, 2) qattn_mma(
    const float* __restrict__ qkv, const float* __restrict__ ag,
    const float* __restrict__ av, const float* __restrict__ ab, float* __restrict__ o)
{
    extern __shared__ float sq[];
    const int bh = blockIdx.y, b = bh >> 3, h = bh & 7;
    const int n0 = blockIdx.x * 112;
    const int tid = threadIdx.x, wid = tid >> 5, lane = tid & 31;
    const int g = lane >> 2, tg = lane & 3;
    const uint32_t smBase = smem_u32(sq);

    float* Qs  = sq;            // [2][112][32] swizzled; reused for P
    float* AHs = sq + 7168;     // [2][64][32]
    float* AVt = sq + 11264;    // [2][64][32]
    float* ABs = sq + 15360;    // [112][49]

    for (int i = tid; i < 112 * 16; i += 224) {
        int r = i >> 4, d4 = i & 15;
        int chunk = d4 >> 3, c4 = d4 & 7;
        float4 v = *(const float4*)&qkv[((size_t)b * NTOK + n0 + r) * QKVD + h * 64 + d4 * 4];
        uint4 u = { f2tf32(v.x), f2tf32(v.y), f2tf32(v.z), f2tf32(v.w) };
        *(uint4*)&Qs[chunk * 3584 + r * 32 + ((c4 ^ (r & 7)) << 2)] = u;
    }
    for (int i = tid; i < 64 * 16; i += 224) {
        int a = i >> 4, d4 = i & 15;
        int chunk = d4 >> 3, c4 = d4 & 7;
        uint4 u = {0u, 0u, 0u, 0u};
        if (a < 49) {
            float4 v = *(const float4*)&ag[((size_t)b * AGENT + a) * CDIM + h * 64 + d4 * 4];
            u.x = f2tf32(v.x * 0.125f); u.y = f2tf32(v.y * 0.125f);
            u.z = f2tf32(v.z * 0.125f); u.w = f2tf32(v.w * 0.125f);
        }
        *(uint4*)&AHs[chunk * 2048 + a * 32 + ((c4 ^ (a & 7)) << 2)] = u;
    }
    for (int i = tid; i < 64 * 16; i += 224) {
        int d = i >> 4, a4 = i & 15;
        int chunk = a4 >> 3, c4 = a4 & 7;
        uint32_t uu[4] = {0u, 0u, 0u, 0u};
#pragma unroll
        for (int j = 0; j < 4; j++) {
            int a = a4 * 4 + j;
            if (a < 49) uu[j] = f2tf32(av[((size_t)bh * AGENT + a) * HDIM + d]);
        }
        uint4 u = { uu[0], uu[1], uu[2], uu[3] };
        *(uint4*)&AVt[chunk * 2048 + d * 32 + ((c4 ^ (d & 7)) << 2)] = u;
    }
    {
        const float4* src = (const float4*)(ab + ((size_t)h * NTOK + n0) * 49);
        for (int i = tid; i < 112 * 49 / 4; i += 224) ((float4*)ABs)[i] = src[i];
    }
    __syncthreads();

    const int wm = wid * 16;
    const int mA = lane >> 3;
    const int rA = wm + ((mA & 1) << 3) + (lane & 7);
    const int c4bA = mA >> 1;
    const int rB = ((lane >> 4) << 3) + (lane & 7);
    const int c4bB = (lane >> 3) & 1;

    float acc[7][4];
#pragma unroll
    for (int nt = 0; nt < 7; nt++)
#pragma unroll
        for (int j = 0; j < 4; j++) acc[nt][j] = 0.f;

#pragma unroll
    for (int chunk = 0; chunk < 2; chunk++)
#pragma unroll
        for (int ks = 0; ks < 4; ks++) {
            uint32_t aF[4], bF[4][4];
            {
                int c4 = (2 * ks) | c4bA;
                LDSM_X4(aF, smBase + (uint32_t)(chunk * 3584 + rA * 32 + ((c4 ^ (rA & 7)) << 2)) * 4);
            }
            int c4b = (2 * ks) | c4bB;
#pragma unroll
            for (int p = 0; p < 4; p++) {
                int row = p * 16 + rB;
                LDSM_X4(bF[p], smBase + (uint32_t)(7168 * 4) +
                        (uint32_t)(chunk * 2048 + row * 32 + ((c4b ^ (row & 7)) << 2)) * 4);
            }
#pragma unroll
            for (int nt = 0; nt < 7; nt++)
                mma_16x8x8(acc[nt], aF, &bF[nt >> 1][(nt & 1) * 2]);
        }

    const int rl0 = wm + g;
    float m0 = -1e30f, m8 = -1e30f;
    float vals[7][4];
#pragma unroll
    for (int nt = 0; nt < 7; nt++) {
        int c0 = nt * 8 + 2 * tg, c1 = c0 + 1;
        float v0 = (c0 < 49) ? acc[nt][0] + ABs[rl0 * 49 + c0]       : -1e30f;
        float v1 = (c1 < 49) ? acc[nt][1] + ABs[rl0 * 49 + c1]       : -1e30f;
        float v2 = (c0 < 49) ? acc[nt][2] + ABs[(rl0 + 8) * 49 + c0] : -1e30f;
        float v3 = (c1 < 49) ? acc[nt][3] + ABs[(rl0 + 8) * 49 + c1] : -1e30f;
        vals[nt][0] = v0; vals[nt][1] = v1; vals[nt][2] = v2; vals[nt][3] = v3;
        m0 = fmaxf(m0, fmaxf(v0, v1));
        m8 = fmaxf(m8, fmaxf(v2, v3));
    }
    m0 = fmaxf(m0, __shfl_xor_sync(0xffffffffu, m0, 1));
    m0 = fmaxf(m0, __shfl_xor_sync(0xffffffffu, m0, 2));
    m8 = fmaxf(m8, __shfl_xor_sync(0xffffffffu, m8, 1));
    m8 = fmaxf(m8, __shfl_xor_sync(0xffffffffu, m8, 2));
    float s0 = 0.f, s8 = 0.f;
#pragma unroll
    for (int nt = 0; nt < 7; nt++) {
        int c0 = nt * 8 + 2 * tg, c1 = c0 + 1;
        float e0 = (c0 < 49) ? __expf(vals[nt][0] - m0) : 0.f;
        float e1 = (c1 < 49) ? __expf(vals[nt][1] - m0) : 0.f;
        float e2 = (c0 < 49) ? __expf(vals[nt][2] - m8) : 0.f;
        float e3 = (c1 < 49) ? __expf(vals[nt][3] - m8) : 0.f;
        vals[nt][0] = e0; vals[nt][1] = e1; vals[nt][2] = e2; vals[nt][3] = e3;
        s0 += e0 + e1; s8 += e2 + e3;
    }
    s0 += __shfl_xor_sync(0xffffffffu, s0, 1);
    s0 += __shfl_xor_sync(0xffffffffu, s0, 2);
    s8 += __shfl_xor_sync(0xffffffffu, s8, 1);
    s8 += __shfl_xor_sync(0xffffffffu, s8, 2);
    const float i0 = 1.0f / s0, i8 = 1.0f / s8;

#pragma unroll
    for (int nt = 0; nt < 7; nt++) {
        int c0 = nt * 8 + 2 * tg;
        int chunk = c0 >> 5, cw = c0 & 31, c4 = cw >> 2;
        uint32_t o0 = chunk * 3584 + rl0 * 32 + ((c4 ^ (rl0 & 7)) << 2) + (cw & 3);
        uint32_t o8 = chunk * 3584 + (rl0 + 8) * 32 + ((c4 ^ ((rl0 + 8) & 7)) << 2) + (cw & 3);
        uint2 u0 = { f2tf32(vals[nt][0] * i0), f2tf32(vals[nt][1] * i0) };
        uint2 u8 = { f2tf32(vals[nt][2] * i8), f2tf32(vals[nt][3] * i8) };
        *(uint2*)&Qs[o0] = u0;
        *(uint2*)&Qs[o8] = u8;
    }
    __syncwarp();

    float ao[8][4];
#pragma unroll
    for (int nt = 0; nt < 8; nt++)
#pragma unroll
        for (int j = 0; j < 4; j++) ao[nt][j] = 0.f;

#pragma unroll
    for (int chunk = 0; chunk < 2; chunk++)
#pragma unroll
        for (int ks = 0; ks < 4; ks++) {
            uint32_t aF[4], bF[4][4];
            {
                int c4 = (2 * ks) | c4bA;
                LDSM_X4(aF, smBase + (uint32_t)(chunk * 3584 + rA * 32 + ((c4 ^ (rA & 7)) << 2)) * 4);
            }
            int c4b = (2 * ks) | c4bB;
#pragma unroll
            for (int p = 0; p < 4; p++) {
                int row = p * 16 + rB;
                LDSM_X4(bF[p], smBase + (uint32_t)(11264 * 4) +
                        (uint32_t)(chunk * 2048 + row * 32 + ((c4b ^ (row & 7)) << 2)) * 4);
            }
#pragma unroll
            for (int nt = 0; nt < 8; nt++)
                mma_16x8x8(ao[nt], aF, &bF[nt >> 1][(nt & 1) * 2]);
        }

    const size_t row0 = (size_t)b * NTOK + n0 + rl0;
#pragma unroll
    for (int nt = 0; nt < 8; nt++) {
        int col = nt * 8 + 2 * tg;
        float2 v0 = { ao[nt][0], ao[nt][1] };
        float2 v8 = { ao[nt][2], ao[nt][3] };
        *(float2*)&o[row0 * 512 + h * 64 + col] = v0;
        *(float2*)&o[(row0 + 8) * 512 + h * 64 + col] = v8;
    }
}

// ------- depthwise 3x3 conv on v (qkv offset 1024), add to o, emit tf32 proj input -------
__global__ __launch_bounds__(512) void dwc_kernel(
    const float* __restrict__ qkv, const float* __restrict__ w,
    const float* __restrict__ bias, const float* __restrict__ o,
    float* __restrict__ oc)
{
    int c = threadIdx.x;
    int n = blockIdx.x;
    int b = blockIdx.y;
    int y = n / WW, x = n % WW;
    float acc = bias[c];
#pragma unroll
    for (int dy = -1; dy <= 1; dy++) {
        int yy = y + dy; if (yy < 0 || yy >= HH) continue;
#pragma unroll
        for (int dx = -1; dx <= 1; dx++) {
            int xx = x + dx; if (xx < 0 || xx >= WW) continue;
            acc += qkv[((size_t)b * NTOK + yy * WW + xx) * QKVD + 1024 + c] *
                   w[c * 9 + (dy + 1) * 3 + (dx + 1)];
        }
    }
    size_t idx = ((size_t)b * NTOK + n) * CDIM + c;
    oc[idx] = __uint_as_float(f2tf32(o[idx] + acc));
}

// ---------------- launch ----------------
extern "C" void kernel_launch(void* const* d_in, const int* in_sizes, int n_in,
                              void* d_out, int out_size)
{
    const float* x      = (const float*)d_in[0];
    const float* q_w    = (const float*)d_in[3];
    const float* kv_w   = (const float*)d_in[4];
    const float* proj_w = (const float*)d_in[5];
    const float* proj_b = (const float*)d_in[6];
    const float* dwc_w  = (const float*)d_in[7];
    const float* dwc_b  = (const float*)d_in[8];
    const float* an_b   = (const float*)d_in[9];
    const float* na_b   = (const float*)d_in[10];
    const float* ah_b   = (const float*)d_in[11];
    const float* aw_b   = (const float*)d_in[12];
    const float* ha_b   = (const float*)d_in[13];
    const float* wa_b   = (const float*)d_in[14];
    float* out = (float*)d_out;

    float *qkv, *op, *xc, *oc, *wc, *prt, *agp, *avp, *pbp, *abp;
    cudaGetSymbolAddress((void**)&qkv, g_qkv);
    cudaGetSymbolAddress((void**)&op,  g_o);
    cudaGetSymbolAddress((void**)&xc,  g_xc);
    cudaGetSymbolAddress((void**)&oc,  g_oc);
    cudaGetSymbolAddress((void**)&wc,  g_wc);
    cudaGetSymbolAddress((void**)&prt, g_part);
    cudaGetSymbolAddress((void**)&agp, g_agent);
    cudaGetSymbolAddress((void**)&avp, g_agentv);
    cudaGetSymbolAddress((void**)&pbp, g_pb);
    cudaGetSymbolAddress((void**)&abp, g_ab);

    cudaFuncSetAttribute(mma_gemm, cudaFuncAttributeMaxDynamicSharedMemorySize, GEMM_SMEM);
    cudaFuncSetAttribute(agent_fused_kernel, cudaFuncAttributeMaxDynamicSharedMemorySize, AF_SMEM);
    cudaFuncSetAttribute(qattn_mma, cudaFuncAttributeMaxDynamicSharedMemorySize, QA_SMEM);

    // pre-convert x and weights to tf32 (wc = q_w | k_w | v_w | proj_w rows)
    {
        int n4 = MALL * CDIM / 4;
        tf32_conv_kernel<<<(n4 + 255) / 256, 256>>>(x, xc, n4);
        int w4 = CDIM * CDIM / 4;
        tf32_conv_kernel<<<(w4 + 255) / 256, 256>>>(q_w, wc, w4);
        tf32_conv_kernel<<<(2 * w4 + 255) / 256, 256>>>(kv_w, wc + CDIM * CDIM, 2 * w4);
        tf32_conv_kernel<<<(w4 + 255) / 256, 256>>>(proj_w, wc + 3 * CDIM * CDIM, w4);
    }

    // merged q|k|v projection: N = 1536
    mma_gemm<<<dim3(QKVD / 128, MALL / 128), 256, GEMM_SMEM>>>(xc, wc, qkv, nullptr, QKVD);

    pool_kernel<<<BATCH * AGENT, CDIM>>>(qkv, agp);
    bias_kernel<<<HEADS * AGENT, 256>>>(an_b, na_b, ah_b, aw_b, ha_b, wa_b, pbp, abp);

    agent_fused_kernel<<<dim3(SPLITS, BATCH * HEADS), 256, AF_SMEM>>>(agp, qkv, pbp, prt);
    agent_combine_kernel<<<BATCH * HEADS, 256>>>(prt, avp);

    qattn_mma<<<dim3(28, BATCH * HEADS), 224, QA_SMEM>>>(qkv, agp, avp, abp, op);
    dwc_kernel<<<dim3(NTOK, BATCH), CDIM>>>(qkv, dwc_w, dwc_b, op, oc);

    mma_gemm<<<dim3(CDIM / 128, MALL / 128), 256, GEMM_SMEM>>>(oc, wc + 3 * CDIM * CDIM, out, proj_b, CDIM);
}

// round 12
// speedup vs baseline: 3.2680x; 1.2045x over previous
#include <cuda_runtime.h>
#include <cuda_bf16.h>
#include <cuda_fp16.h>
#include <cstdint>

// ---------------- problem constants ----------------
#define BATCH 16
#define CDIM  512
#define HH    56
#define WW    56
#define NTOK  3136          // 56*56
#define HEADS 8
#define HDIM  64
#define AGENT 49
#define MALL  (BATCH*NTOK)  // 50176
#define SPLITS 7
#define NSPL  448           // NTOK / SPLITS
#define QKVD  1536          // merged qkv row stride

// ---------------- scratch (static device memory; no allocation) ----------------
__device__ float  g_qkv[(size_t)MALL*QKVD];   // q | k | v per row (fp32)
__device__ float  g_o[MALL*CDIM];
__device__ __half g_xh[(size_t)MALL*CDIM];    // x pre-converted to fp16
__device__ __half g_oh[(size_t)MALL*CDIM];    // (o + dwc) pre-converted to fp16
__device__ __half g_wh[4*CDIM*CDIM];          // q_w | k_w | v_w | proj_w, fp16
__device__ float  g_part[SPLITS*BATCH*HEADS*AGENT*(HDIM+2) + 1024];
__device__ float  g_agent[BATCH*AGENT*CDIM];
__device__ float  g_agentv[BATCH*HEADS*AGENT*HDIM];
__device__ float  g_pb[HEADS*AGENT*NTOK];
__device__ float  g_ab[HEADS*NTOK*AGENT];

// ================= helpers =================
__device__ __forceinline__ uint32_t f2tf32(float f) {
    uint32_t u;
    asm("cvt.rna.tf32.f32 %0, %1;" : "=r"(u) : "f"(f));
    return u;
}
__device__ __forceinline__ uint32_t pack_h2(float lo, float hi) {
    uint32_t u;
    asm("cvt.rn.f16x2.f32 %0, %1, %2;" : "=r"(u) : "f"(hi), "f"(lo));
    return u;
}
__device__ __forceinline__ uint32_t smem_u32(const void* p) {
    uint32_t a;
    asm("{ .reg .u64 t; cvta.to.shared.u64 t, %1; cvt.u32.u64 %0, t; }" : "=r"(a) : "l"(p));
    return a;
}
__device__ __forceinline__ void mma_16x8x8(float* d, const uint32_t* a, const uint32_t* b) {
    asm volatile(
        "mma.sync.aligned.m16n8k8.row.col.f32.tf32.tf32.f32 "
        "{%0,%1,%2,%3}, {%4,%5,%6,%7}, {%8,%9}, {%0,%1,%2,%3};"
        : "+f"(d[0]), "+f"(d[1]), "+f"(d[2]), "+f"(d[3])
        : "r"(a[0]), "r"(a[1]), "r"(a[2]), "r"(a[3]), "r"(b[0]), "r"(b[1]));
}
__device__ __forceinline__ void mma_16x8x16h(float* d, const uint32_t* a, const uint32_t* b) {
    asm volatile(
        "mma.sync.aligned.m16n8k16.row.col.f32.f16.f16.f32 "
        "{%0,%1,%2,%3}, {%4,%5,%6,%7}, {%8,%9}, {%0,%1,%2,%3};"
        : "+f"(d[0]), "+f"(d[1]), "+f"(d[2]), "+f"(d[3])
        : "r"(a[0]), "r"(a[1]), "r"(a[2]), "r"(a[3]), "r"(b[0]), "r"(b[1]));
}
#define LDSM_X4(r, addr) \
    asm volatile("ldmatrix.sync.aligned.m8n8.x4.shared.b16 {%0,%1,%2,%3}, [%4];" \
        : "=r"((r)[0]), "=r"((r)[1]), "=r"((r)[2]), "=r"((r)[3]) : "r"(addr))
#define CP_ASYNC16(dst, src) \
    asm volatile("cp.async.cg.shared.global [%0], [%1], 16;" :: "r"(dst), "l"(src))

// ---------------- fp16 pre-conversion (float4 -> f16x2 pair) ----------------
__global__ __launch_bounds__(256) void f16_conv_kernel(
    const float* __restrict__ in, __half* __restrict__ out, int n4)
{
    int i = blockIdx.x * 256 + threadIdx.x;
    if (i < n4) {
        float4 v = ((const float4*)in)[i];
        uint2 u;
        u.x = pack_h2(v.x, v.y);
        u.y = pack_h2(v.z, v.w);
        ((uint2*)out)[i] = u;
    }
}

// ======= fp16 tensor-core GEMM: C[m,n] = sum_k A[m,k]*W[n,k] (+bias[n]) =======
// A, W pre-converted fp16. K=512, BK=64 halves (128B rows — identical layout math
// to the proven tf32 kernel). 128x128 tile, 256 threads, 8 warps 2x4 (warp 64x32).
#define GSTG 3
#define STG_BYTES 32768                // A tile 16KB + B tile 16KB
#define GEMM_SMEM (GSTG*STG_BYTES)     // 98304 bytes

__global__ void __launch_bounds__(256, 2) mma_gemm(
    const __half* __restrict__ A, const __half* __restrict__ W,
    float* __restrict__ C, const float* __restrict__ bias, int ldc)
{
    extern __shared__ float sm[];
    const int tid = threadIdx.x;
    const int wid = tid >> 5, lane = tid & 31;
    const int wm = (wid >> 2) * 64;
    const int wn = (wid & 3) * 32;
    const int g = lane >> 2, tg = lane & 3;
    const int bm = blockIdx.y * 128, bn = blockIdx.x * 128;
    const uint32_t smBase = smem_u32(sm);

    // cp.async geometry: rows of 128B (64 halves), 8 16B-groups per row
    const __half* aSrc[4];
    const __half* wSrc[4];
    uint32_t dOff[4];
#pragma unroll
    for (int i = 0; i < 4; i++) {
        int id = i * 256 + tid;
        int r = id >> 3, c4 = id & 7;
        aSrc[i] = A + (size_t)(bm + r) * 512 + c4 * 8;
        wSrc[i] = W + (size_t)(bn + r) * 512 + c4 * 8;
        dOff[i] = (uint32_t)(r * 128 + ((c4 ^ (r & 7)) << 4));
    }

    // ldmatrix lane geometry (A: m16k16 frags; B: n16-pair k16 frags)
    const int mA = lane >> 3;
    const int rowA_base = wm + ((mA & 1) << 3) + (lane & 7);
    const int c4bA = mA >> 1;
    const int rowB_base = wn + ((lane >> 4) << 3) + (lane & 7);
    const int c4bB = (lane >> 3) & 1;

    float acc[4][4][4];
#pragma unroll
    for (int mi = 0; mi < 4; mi++)
#pragma unroll
        for (int ni = 0; ni < 4; ni++)
#pragma unroll
            for (int j = 0; j < 4; j++) acc[mi][ni][j] = 0.f;

    // prologue: stage chunks 0,1 (of 8)
#pragma unroll
    for (int kc = 0; kc < 2; kc++) {
        uint32_t sA = smBase + (uint32_t)(kc % GSTG) * STG_BYTES;
        uint32_t sB = sA + 16384;
        int koff = kc * 64;
#pragma unroll
        for (int i = 0; i < 4; i++) {
            CP_ASYNC16(sA + dOff[i], aSrc[i] + koff);
            CP_ASYNC16(sB + dOff[i], wSrc[i] + koff);
        }
        asm volatile("cp.async.commit_group;");
    }

    for (int kc = 0; kc < 8; kc++) {
        if (kc < 7) asm volatile("cp.async.wait_group 1;");
        else        asm volatile("cp.async.wait_group 0;");
        __syncthreads();
        if (kc + 2 < 8) {
            uint32_t sA = smBase + (uint32_t)((kc + 2) % GSTG) * STG_BYTES;
            uint32_t sB = sA + 16384;
            int koff = (kc + 2) * 64;
#pragma unroll
            for (int i = 0; i < 4; i++) {
                CP_ASYNC16(sA + dOff[i], aSrc[i] + koff);
                CP_ASYNC16(sB + dOff[i], wSrc[i] + koff);
            }
            asm volatile("cp.async.commit_group;");
        }
        const uint32_t sA = smBase + (uint32_t)(kc % GSTG) * STG_BYTES;
        const uint32_t sB = sA + 16384;
#pragma unroll
        for (int ks = 0; ks < 4; ks++) {   // 4 x k16 = k64 per chunk
            uint32_t aF[4][4], bF[2][4];
#pragma unroll
            for (int mi = 0; mi < 4; mi++) {
                int row = rowA_base + mi * 16;
                int c4 = (2 * ks) | c4bA;
                LDSM_X4(aF[mi], sA + (uint32_t)(row * 128 + ((c4 ^ (row & 7)) << 4)));
            }
#pragma unroll
            for (int p = 0; p < 2; p++) {
                int row = rowB_base + p * 16;
                int c4 = (2 * ks) | c4bB;
                LDSM_X4(bF[p], sB + (uint32_t)(row * 128 + ((c4 ^ (row & 7)) << 4)));
            }
#pragma unroll
            for (int mi = 0; mi < 4; mi++)
#pragma unroll
                for (int p = 0; p < 2; p++) {
                    mma_16x8x16h(acc[mi][2 * p],     aF[mi], &bF[p][0]);
                    mma_16x8x16h(acc[mi][2 * p + 1], aF[mi], &bF[p][2]);
                }
        }
    }

    // epilogue
#pragma unroll
    for (int mi = 0; mi < 4; mi++) {
        int row = bm + wm + mi * 16 + g;
#pragma unroll
        for (int ni = 0; ni < 4; ni++) {
            int col = bn + wn + ni * 8 + 2 * tg;
            float b0 = 0.f, b1 = 0.f;
            if (bias) { b0 = bias[col]; b1 = bias[col + 1]; }
            float2 v0 = { acc[mi][ni][0] + b0, acc[mi][ni][1] + b1 };
            float2 v1 = { acc[mi][ni][2] + b0, acc[mi][ni][3] + b1 };
            *(float2*)&C[(size_t)row * ldc + col] = v0;
            *(float2*)&C[(size_t)(row + 8) * ldc + col] = v1;
        }
    }
}

// ---------------- agent token pooling (q part of qkv, stride 1536) ----------------
__global__ __launch_bounds__(512) void pool_kernel(const float* __restrict__ qkv,
                                                   float* __restrict__ ag)
{
    int c = threadIdx.x;
    int b = blockIdx.x / AGENT;
    int a = blockIdx.x % AGENT;
    int p1 = a / 7, p2 = a % 7;
    float s = 0.f;
#pragma unroll
    for (int i = 0; i < 8; i++)
#pragma unroll
        for (int j = 0; j < 8; j++)
            s += qkv[((size_t)b * NTOK + (p1 * 8 + i) * WW + (p2 * 8 + j)) * QKVD + c];
    ag[((size_t)b * AGENT + a) * CDIM + c] = s * (1.0f / 64.0f);
}

// ---------------- bias precompute ----------------
__global__ __launch_bounds__(256) void bias_kernel(
    const float* __restrict__ an, const float* __restrict__ na,
    const float* __restrict__ ahb, const float* __restrict__ awb,
    const float* __restrict__ hab, const float* __restrict__ wab,
    float* __restrict__ pb, float* __restrict__ ab)
{
    int h = blockIdx.x / AGENT;
    int a = blockIdx.x % AGENT;
    __shared__ float ans[49], nas[49];
    int tid = threadIdx.x;
    if (tid < 49) {
        ans[tid] = an[((size_t)h * AGENT + a) * 49 + tid];
        nas[tid] = na[((size_t)h * AGENT + a) * 49 + tid];
    }
    __syncthreads();
    for (int n = tid; n < NTOK; n += 256) {
        int y = n / WW, x = n % WW;
        float fy = (y + 0.5f) * 0.125f - 0.5f;
        float fx = (x + 0.5f) * 0.125f - 0.5f;
        int iy = (int)floorf(fy); float ty = fy - iy;
        int ix = (int)floorf(fx); float tx = fx - ix;
        float wy0 = 1.f - ty, wy1 = ty;
        int y0 = iy, y1 = iy + 1;
        if (y0 < 0) { wy0 = 0.f; y0 = 0; }
        if (y1 > 6) { wy1 = 0.f; y1 = 6; }
        float sy = wy0 + wy1; wy0 /= sy; wy1 /= sy;
        float wx0 = 1.f - tx, wx1 = tx;
        int x0 = ix, x1 = ix + 1;
        if (x0 < 0) { wx0 = 0.f; x0 = 0; }
        if (x1 > 6) { wx1 = 0.f; x1 = 6; }
        float sx = wx0 + wx1; wx0 /= sx; wx1 /= sx;

        float bi_an = wy0 * (wx0 * ans[y0 * 7 + x0] + wx1 * ans[y0 * 7 + x1]) +
                      wy1 * (wx0 * ans[y1 * 7 + x0] + wx1 * ans[y1 * 7 + x1]);
        float bi_na = wy0 * (wx0 * nas[y0 * 7 + x0] + wx1 * nas[y0 * 7 + x1]) +
                      wy1 * (wx0 * nas[y1 * 7 + x0] + wx1 * nas[y1 * 7 + x1]);

        pb[((size_t)h * AGENT + a) * NTOK + n] =
            bi_an + ahb[((size_t)h * AGENT + a) * 56 + y] + awb[((size_t)h * AGENT + a) * 56 + x];
        ab[((size_t)h * NTOK + n) * AGENT + a] =
            bi_na + hab[((size_t)h * 56 + y) * AGENT + a] + wab[((size_t)h * 56 + x) * AGENT + a];
    }
}

// ============ fused agent attention: mma logits + softmax + scalar attn@V ============
#define AF_LOFF 8192
#define AF_LSTR 452
#define AF_SMEM ((AF_LOFF + AGENT*AF_LSTR) * 4)   // 121360 bytes

__global__ __launch_bounds__(256) void agent_fused_kernel(
    const float* __restrict__ ag, const float* __restrict__ qkv,
    const float* __restrict__ pb, float* __restrict__ part)
{
    extern __shared__ float smf[];
    float* AHs = smf;                 // [2][64][32] swizzled tf32, agents padded to 64
    float* Ks  = smf + 4096;          // [2][64][32] swizzled token chunk (K); later V staging
    float* L   = smf + AF_LOFF;       // [49][452]
    __shared__ float sm_m[AGENT], sm_s[AGENT];

    const int s  = blockIdx.x;
    const int bh = blockIdx.y;
    const int b = bh >> 3, h = bh & 7;
    const int tid = threadIdx.x;
    const int wid = tid >> 5, lane = tid & 31;
    const int g = lane >> 2, tg = lane & 3;
    const int mA = lane >> 3;
    const int n0base = s * NSPL;
    const uint32_t smBase = smem_u32(smf);

    for (int i = tid; i < 64 * 16; i += 256) {
        int a = i >> 4, d4 = i & 15;
        int chunk = d4 >> 3, c4 = d4 & 7;
        uint4 u = {0u, 0u, 0u, 0u};
        if (a < 49) {
            float4 v = *(const float4*)&ag[((size_t)b * AGENT + a) * CDIM + h * 64 + d4 * 4];
            u.x = f2tf32(v.x * 0.125f); u.y = f2tf32(v.y * 0.125f);
            u.z = f2tf32(v.z * 0.125f); u.w = f2tf32(v.w * 0.125f);
        }
        *(uint4*)&AHs[chunk * 2048 + a * 32 + ((c4 ^ (a & 7)) << 2)] = u;
    }

    const int rA = ((mA & 1) << 3) + (lane & 7);
    const int c4bA = mA >> 1;
    const int rB = ((wid >> 1) * 16) + ((lane >> 4) << 3) + (lane & 7);
    const int c4bB = (lane >> 3) & 1;
    const int sub = wid & 1;

    for (int c = 0; c < 7; c++) {
        int n0 = n0base + c * 64;
        __syncthreads();
        for (int i = tid; i < 64 * 16; i += 256) {
            int nn = i >> 4, d4 = i & 15;
            int chunk = d4 >> 3, c4 = d4 & 7;
            float4 v = *(const float4*)&qkv[((size_t)b * NTOK + n0 + nn) * QKVD + 512 + h * 64 + d4 * 4];
            uint4 u = { f2tf32(v.x), f2tf32(v.y), f2tf32(v.z), f2tf32(v.w) };
            *(uint4*)&Ks[chunk * 2048 + nn * 32 + ((c4 ^ (nn & 7)) << 2)] = u;
        }
        __syncthreads();
        if (wid < 7) {
            float acc[4][4];
#pragma unroll
            for (int mt = 0; mt < 4; mt++)
#pragma unroll
                for (int j = 0; j < 4; j++) acc[mt][j] = 0.f;
#pragma unroll
            for (int chunk = 0; chunk < 2; chunk++)
#pragma unroll
                for (int ks = 0; ks < 4; ks++) {
                    uint32_t bF[4];
                    {
                        int c4 = (2 * ks) | c4bB;
                        LDSM_X4(bF, smBase + (uint32_t)(chunk * 2048 + rB * 32 + ((c4 ^ (rB & 7)) << 2)) * 4);
                    }
#pragma unroll
                    for (int mt = 0; mt < 4; mt++) {
                        uint32_t aF[4];
                        int row = mt * 16 + rA;
                        int c4 = (2 * ks) | c4bA;
                        LDSM_X4(aF, smBase + (uint32_t)(4096 + chunk * 2048 + row * 32 + ((c4 ^ (row & 7)) << 2)) * 4);
                        mma_16x8x8(acc[mt], aF, &bF[sub * 2]);
                    }
                }
#pragma unroll
            for (int mt = 0; mt < 4; mt++)
#pragma unroll
                for (int j = 0; j < 4; j++) {
                    int a = wid * 8 + 2 * tg + (j & 1);
                    if (a < 49) {
                        int nloc = c * 64 + mt * 16 + g + ((j >> 1) << 3);
                        L[a * AF_LSTR + nloc] =
                            acc[mt][j] + pb[((size_t)h * AGENT + a) * NTOK + n0base + nloc];
                    }
                }
        }
    }
    __syncthreads();

    {
        int w = wid, ln = lane;
        for (int a = w; a < AGENT; a += 8) {
            float m = -1e30f;
            for (int j = ln; j < NSPL; j += 32) m = fmaxf(m, L[a * AF_LSTR + j]);
#pragma unroll
            for (int o = 16; o > 0; o >>= 1) m = fmaxf(m, __shfl_xor_sync(0xffffffffu, m, o));
            float sum = 0.f;
            for (int j = ln; j < NSPL; j += 32) {
                float e = __expf(L[a * AF_LSTR + j] - m);
                L[a * AF_LSTR + j] = e;
                sum += e;
            }
#pragma unroll
            for (int o = 16; o > 0; o >>= 1) sum += __shfl_xor_sync(0xffffffffu, sum, o);
            if (ln == 0) { sm_m[a] = m; sm_s[a] = sum; }
        }
    }
    __syncthreads();

    float* Vb = smf;   // reuse: [64][65]
    const int nl = tid & 63, abase = tid >> 6;
    float acc[13];
#pragma unroll
    for (int i = 0; i < 13; i++) acc[i] = 0.f;
    const int d = nl;
    for (int c = 0; c < 7; c++) {
        int n0 = n0base + c * 64;
        __syncthreads();
        for (int i = tid; i < 64 * 16; i += 256) {
            int nn = i >> 4, d4 = (i & 15) * 4;
            float4 v = *(const float4*)&qkv[((size_t)b * NTOK + n0 + nn) * QKVD + 1024 + h * 64 + d4];
            Vb[nn * 65 + d4] = v.x; Vb[nn * 65 + d4 + 1] = v.y;
            Vb[nn * 65 + d4 + 2] = v.z; Vb[nn * 65 + d4 + 3] = v.w;
        }
        __syncthreads();
#pragma unroll 8
        for (int nn = 0; nn < 64; nn++) {
            float vd = Vb[nn * 65 + d];
            int a = abase;
#pragma unroll
            for (int i = 0; i < 13; i++) { if (a < 49) acc[i] += L[a * AF_LSTR + c * 64 + nn] * vd; a += 4; }
        }
    }

    float* pacc = part;
    float* pms  = part + (size_t)SPLITS * 128 * AGENT * HDIM;
    {
        int a = abase;
#pragma unroll
        for (int i = 0; i < 13; i++) {
            if (a < 49) pacc[(((size_t)s * 128 + bh) * AGENT + a) * HDIM + d] = acc[i];
            a += 4;
        }
    }
    if (tid < AGENT) {
        pms[(((size_t)s * 128 + bh) * AGENT + tid) * 2 + 0] = sm_m[tid];
        pms[(((size_t)s * 128 + bh) * AGENT + tid) * 2 + 1] = sm_s[tid];
    }
}

// ---- combine splits ----
__global__ __launch_bounds__(256) void agent_combine_kernel(
    const float* __restrict__ part, float* __restrict__ av)
{
    const int bh = blockIdx.x;
    const int tid = threadIdx.x;
    const int d = tid & 63, abase = tid >> 6;
    const float* pacc = part;
    const float* pms  = part + (size_t)SPLITS * 128 * AGENT * HDIM;

    int a = abase;
#pragma unroll
    for (int i = 0; i < 13; i++) {
        if (a < 49) {
            float mstar = -1e30f;
            float ms[SPLITS], ss[SPLITS];
#pragma unroll
            for (int s = 0; s < SPLITS; s++) {
                ms[s] = pms[(((size_t)s * 128 + bh) * AGENT + a) * 2 + 0];
                ss[s] = pms[(((size_t)s * 128 + bh) * AGENT + a) * 2 + 1];
                mstar = fmaxf(mstar, ms[s]);
            }
            float S = 0.f, o = 0.f;
#pragma unroll
            for (int s = 0; s < SPLITS; s++) {
                float f = __expf(ms[s] - mstar);
                S += ss[s] * f;
                o += pacc[(((size_t)s * 128 + bh) * AGENT + a) * HDIM + d] * f;
            }
            av[((size_t)bh * AGENT + a) * HDIM + d] = o / S;
        }
        a += 4;
    }
}

// ======= q attention via tensor cores (tf32) =======
#define QA_SMEM (20848*4)

__global__ void __launch_bounds__(224, 2) qattn_mma(
    const float* __restrict__ qkv, const float* __restrict__ ag,
    const float* __restrict__ av, const float* __restrict__ ab, float* __restrict__ o)
{
    extern __shared__ float sq[];
    const int bh = blockIdx.y, b = bh >> 3, h = bh & 7;
    const int n0 = blockIdx.x * 112;
    const int tid = threadIdx.x, wid = tid >> 5, lane = tid & 31;
    const int g = lane >> 2, tg = lane & 3;
    const uint32_t smBase = smem_u32(sq);

    float* Qs  = sq;            // [2][112][32] swizzled; reused for P
    float* AHs = sq + 7168;     // [2][64][32]
    float* AVt = sq + 11264;    // [2][64][32]
    float* ABs = sq + 15360;    // [112][49]

    for (int i = tid; i < 112 * 16; i += 224) {
        int r = i >> 4, d4 = i & 15;
        int chunk = d4 >> 3, c4 = d4 & 7;
        float4 v = *(const float4*)&qkv[((size_t)b * NTOK + n0 + r) * QKVD + h * 64 + d4 * 4];
        uint4 u = { f2tf32(v.x), f2tf32(v.y), f2tf32(v.z), f2tf32(v.w) };
        *(uint4*)&Qs[chunk * 3584 + r * 32 + ((c4 ^ (r & 7)) << 2)] = u;
    }
    for (int i = tid; i < 64 * 16; i += 224) {
        int a = i >> 4, d4 = i & 15;
        int chunk = d4 >> 3, c4 = d4 & 7;
        uint4 u = {0u, 0u, 0u, 0u};
        if (a < 49) {
            float4 v = *(const float4*)&ag[((size_t)b * AGENT + a) * CDIM + h * 64 + d4 * 4];
            u.x = f2tf32(v.x * 0.125f); u.y = f2tf32(v.y * 0.125f);
            u.z = f2tf32(v.z * 0.125f); u.w = f2tf32(v.w * 0.125f);
        }
        *(uint4*)&AHs[chunk * 2048 + a * 32 + ((c4 ^ (a & 7)) << 2)] = u;
    }
    for (int i = tid; i < 64 * 16; i += 224) {
        int d = i >> 4, a4 = i & 15;
        int chunk = a4 >> 3, c4 = a4 & 7;
        uint32_t uu[4] = {0u, 0u, 0u, 0u};
#pragma unroll
        for (int j = 0; j < 4; j++) {
            int a = a4 * 4 + j;
            if (a < 49) uu[j] = f2tf32(av[((size_t)bh * AGENT + a) * HDIM + d]);
        }
        uint4 u = { uu[0], uu[1], uu[2], uu[3] };
        *(uint4*)&AVt[chunk * 2048 + d * 32 + ((c4 ^ (d & 7)) << 2)] = u;
    }
    {
        const float4* src = (const float4*)(ab + ((size_t)h * NTOK + n0) * 49);
        for (int i = tid; i < 112 * 49 / 4; i += 224) ((float4*)ABs)[i] = src[i];
    }
    __syncthreads();

    const int wm = wid * 16;
    const int mA = lane >> 3;
    const int rA = wm + ((mA & 1) << 3) + (lane & 7);
    const int c4bA = mA >> 1;
    const int rB = ((lane >> 4) << 3) + (lane & 7);
    const int c4bB = (lane >> 3) & 1;

    float acc[7][4];
#pragma unroll
    for (int nt = 0; nt < 7; nt++)
#pragma unroll
        for (int j = 0; j < 4; j++) acc[nt][j] = 0.f;

#pragma unroll
    for (int chunk = 0; chunk < 2; chunk++)
#pragma unroll
        for (int ks = 0; ks < 4; ks++) {
            uint32_t aF[4], bF[4][4];
            {
                int c4 = (2 * ks) | c4bA;
                LDSM_X4(aF, smBase + (uint32_t)(chunk * 3584 + rA * 32 + ((c4 ^ (rA & 7)) << 2)) * 4);
            }
            int c4b = (2 * ks) | c4bB;
#pragma unroll
            for (int p = 0; p < 4; p++) {
                int row = p * 16 + rB;
                LDSM_X4(bF[p], smBase + (uint32_t)(7168 * 4) +
                        (uint32_t)(chunk * 2048 + row * 32 + ((c4b ^ (row & 7)) << 2)) * 4);
            }
#pragma unroll
            for (int nt = 0; nt < 7; nt++)
                mma_16x8x8(acc[nt], aF, &bF[nt >> 1][(nt & 1) * 2]);
        }

    const int rl0 = wm + g;
    float m0 = -1e30f, m8 = -1e30f;
    float vals[7][4];
#pragma unroll
    for (int nt = 0; nt < 7; nt++) {
        int c0 = nt * 8 + 2 * tg, c1 = c0 + 1;
        float v0 = (c0 < 49) ? acc[nt][0] + ABs[rl0 * 49 + c0]       : -1e30f;
        float v1 = (c1 < 49) ? acc[nt][1] + ABs[rl0 * 49 + c1]       : -1e30f;
        float v2 = (c0 < 49) ? acc[nt][2] + ABs[(rl0 + 8) * 49 + c0] : -1e30f;
        float v3 = (c1 < 49) ? acc[nt][3] + ABs[(rl0 + 8) * 49 + c1] : -1e30f;
        vals[nt][0] = v0; vals[nt][1] = v1; vals[nt][2] = v2; vals[nt][3] = v3;
        m0 = fmaxf(m0, fmaxf(v0, v1));
        m8 = fmaxf(m8, fmaxf(v2, v3));
    }
    m0 = fmaxf(m0, __shfl_xor_sync(0xffffffffu, m0, 1));
    m0 = fmaxf(m0, __shfl_xor_sync(0xffffffffu, m0, 2));
    m8 = fmaxf(m8, __shfl_xor_sync(0xffffffffu, m8, 1));
    m8 = fmaxf(m8, __shfl_xor_sync(0xffffffffu, m8, 2));
    float s0 = 0.f, s8 = 0.f;
#pragma unroll
    for (int nt = 0; nt < 7; nt++) {
        int c0 = nt * 8 + 2 * tg, c1 = c0 + 1;
        float e0 = (c0 < 49) ? __expf(vals[nt][0] - m0) : 0.f;
        float e1 = (c1 < 49) ? __expf(vals[nt][1] - m0) : 0.f;
        float e2 = (c0 < 49) ? __expf(vals[nt][2] - m8) : 0.f;
        float e3 = (c1 < 49) ? __expf(vals[nt][3] - m8) : 0.f;
        vals[nt][0] = e0; vals[nt][1] = e1; vals[nt][2] = e2; vals[nt][3] = e3;
        s0 += e0 + e1; s8 += e2 + e3;
    }
    s0 += __shfl_xor_sync(0xffffffffu, s0, 1);
    s0 += __shfl_xor_sync(0xffffffffu, s0, 2);
    s8 += __shfl_xor_sync(0xffffffffu, s8, 1);
    s8 += __shfl_xor_sync(0xffffffffu, s8, 2);
    const float i0 = 1.0f / s0, i8 = 1.0f / s8;

#pragma unroll
    for (int nt = 0; nt < 7; nt++) {
        int c0 = nt * 8 + 2 * tg;
        int chunk = c0 >> 5, cw = c0 & 31, c4 = cw >> 2;
        uint32_t o0 = chunk * 3584 + rl0 * 32 + ((c4 ^ (rl0 & 7)) << 2) + (cw & 3);
        uint32_t o8 = chunk * 3584 + (rl0 + 8) * 32 + ((c4 ^ ((rl0 + 8) & 7)) << 2) + (cw & 3);
        uint2 u0 = { f2tf32(vals[nt][0] * i0), f2tf32(vals[nt][1] * i0) };
        uint2 u8 = { f2tf32(vals[nt][2] * i8), f2tf32(vals[nt][3] * i8) };
        *(uint2*)&Qs[o0] = u0;
        *(uint2*)&Qs[o8] = u8;
    }
    __syncwarp();

    float ao[8][4];
#pragma unroll
    for (int nt = 0; nt < 8; nt++)
#pragma unroll
        for (int j = 0; j < 4; j++) ao[nt][j] = 0.f;

#pragma unroll
    for (int chunk = 0; chunk < 2; chunk++)
#pragma unroll
        for (int ks = 0; ks < 4; ks++) {
            uint32_t aF[4], bF[4][4];
            {
                int c4 = (2 * ks) | c4bA;
                LDSM_X4(aF, smBase + (uint32_t)(chunk * 3584 + rA * 32 + ((c4 ^ (rA & 7)) << 2)) * 4);
            }
            int c4b = (2 * ks) | c4bB;
#pragma unroll
            for (int p = 0; p < 4; p++) {
                int row = p * 16 + rB;
                LDSM_X4(bF[p], smBase + (uint32_t)(11264 * 4) +
                        (uint32_t)(chunk * 2048 + row * 32 + ((c4b ^ (row & 7)) << 2)) * 4);
            }
#pragma unroll
            for (int nt = 0; nt < 8; nt++)
                mma_16x8x8(ao[nt], aF, &bF[nt >> 1][(nt & 1) * 2]);
        }

    const size_t row0 = (size_t)b * NTOK + n0 + rl0;
#pragma unroll
    for (int nt = 0; nt < 8; nt++) {
        int col = nt * 8 + 2 * tg;
        float2 v0 = { ao[nt][0], ao[nt][1] };
        float2 v8 = { ao[nt][2], ao[nt][3] };
        *(float2*)&o[row0 * 512 + h * 64 + col] = v0;
        *(float2*)&o[(row0 + 8) * 512 + h * 64 + col] = v8;
    }
}

// ------- depthwise 3x3 conv on v (qkv offset 1024), add to o, emit fp16 proj input -------
__global__ __launch_bounds__(512) void dwc_kernel(
    const float* __restrict__ qkv, const float* __restrict__ w,
    const float* __restrict__ bias, const float* __restrict__ o,
    __half* __restrict__ oh)
{
    int c = threadIdx.x;
    int n = blockIdx.x;
    int b = blockIdx.y;
    int y = n / WW, x = n % WW;
    float acc = bias[c];
#pragma unroll
    for (int dy = -1; dy <= 1; dy++) {
        int yy = y + dy; if (yy < 0 || yy >= HH) continue;
#pragma unroll
        for (int dx = -1; dx <= 1; dx++) {
            int xx = x + dx; if (xx < 0 || xx >= WW) continue;
            acc += qkv[((size_t)b * NTOK + yy * WW + xx) * QKVD + 1024 + c] *
                   w[c * 9 + (dy + 1) * 3 + (dx + 1)];
        }
    }
    size_t idx = ((size_t)b * NTOK + n) * CDIM + c;
    oh[idx] = __float2half_rn(o[idx] + acc);
}

// ---------------- launch ----------------
extern "C" void kernel_launch(void* const* d_in, const int* in_sizes, int n_in,
                              void* d_out, int out_size)
{
    const float* x      = (const float*)d_in[0];
    const float* q_w    = (const float*)d_in[3];
    const float* kv_w   = (const float*)d_in[4];
    const float* proj_w = (const float*)d_in[5];
    const float* proj_b = (const float*)d_in[6];
    const float* dwc_w  = (const float*)d_in[7];
    const float* dwc_b  = (const float*)d_in[8];
    const float* an_b   = (const float*)d_in[9];
    const float* na_b   = (const float*)d_in[10];
    const float* ah_b   = (const float*)d_in[11];
    const float* aw_b   = (const float*)d_in[12];
    const float* ha_b   = (const float*)d_in[13];
    const float* wa_b   = (const float*)d_in[14];
    float* out = (float*)d_out;

    float *qkv, *op, *prt, *agp, *avp, *pbp, *abp;
    __half *xh, *oh, *wh;
    cudaGetSymbolAddress((void**)&qkv, g_qkv);
    cudaGetSymbolAddress((void**)&op,  g_o);
    cudaGetSymbolAddress((void**)&xh,  g_xh);
    cudaGetSymbolAddress((void**)&oh,  g_oh);
    cudaGetSymbolAddress((void**)&wh,  g_wh);
    cudaGetSymbolAddress((void**)&prt, g_part);
    cudaGetSymbolAddress((void**)&agp, g_agent);
    cudaGetSymbolAddress((void**)&avp, g_agentv);
    cudaGetSymbolAddress((void**)&pbp, g_pb);
    cudaGetSymbolAddress((void**)&abp, g_ab);

    cudaFuncSetAttribute(mma_gemm, cudaFuncAttributeMaxDynamicSharedMemorySize, GEMM_SMEM);
    cudaFuncSetAttribute(agent_fused_kernel, cudaFuncAttributeMaxDynamicSharedMemorySize, AF_SMEM);
    cudaFuncSetAttribute(qattn_mma, cudaFuncAttributeMaxDynamicSharedMemorySize, QA_SMEM);

    // pre-convert x and weights to fp16 (wh = q_w | k_w | v_w | proj_w rows)
    {
        int n4 = MALL * CDIM / 4;
        f16_conv_kernel<<<(n4 + 255) / 256, 256>>>(x, xh, n4);
        int w4 = CDIM * CDIM / 4;
        f16_conv_kernel<<<(w4 + 255) / 256, 256>>>(q_w, wh, w4);
        f16_conv_kernel<<<(2 * w4 + 255) / 256, 256>>>(kv_w, wh + CDIM * CDIM, 2 * w4);
        f16_conv_kernel<<<(w4 + 255) / 256, 256>>>(proj_w, wh + 3 * CDIM * CDIM, w4);
    }

    // merged q|k|v projection: N = 1536
    mma_gemm<<<dim3(QKVD / 128, MALL / 128), 256, GEMM_SMEM>>>(xh, wh, qkv, nullptr, QKVD);

    pool_kernel<<<BATCH * AGENT, CDIM>>>(qkv, agp);
    bias_kernel<<<HEADS * AGENT, 256>>>(an_b, na_b, ah_b, aw_b, ha_b, wa_b, pbp, abp);

    agent_fused_kernel<<<dim3(SPLITS, BATCH * HEADS), 256, AF_SMEM>>>(agp, qkv, pbp, prt);
    agent_combine_kernel<<<BATCH * HEADS, 256>>>(prt, avp);

    qattn_mma<<<dim3(28, BATCH * HEADS), 224, QA_SMEM>>>(qkv, agp, avp, abp, op);
    dwc_kernel<<<dim3(NTOK, BATCH), CDIM>>>(qkv, dwc_w, dwc_b, op, oh);

    mma_gemm<<<dim3(CDIM / 128, MALL / 128), 256, GEMM_SMEM>>>(oh, wh + 3 * CDIM * CDIM, out, proj_b, CDIM);
}

// round 15
// speedup vs baseline: 4.2527x; 1.3013x over previous
#include <cuda_runtime.h>
#include <cuda_bf16.h>
#include <cuda_fp16.h>
#include <cstdint>

// ---------------- problem constants ----------------
#define BATCH 16
#define CDIM  512
#define HH    56
#define WW    56
#define NTOK  3136          // 56*56
#define HEADS 8
#define HDIM  64
#define AGENT 49
#define MALL  (BATCH*NTOK)  // 50176
#define SPLITS 7
#define NSPL  448           // NTOK / SPLITS
#define QKVD  1536          // merged qkv row stride

// ---------------- scratch (static device memory; no allocation) ----------------
__device__ __half g_qkv[(size_t)MALL*QKVD];   // q | k | v per row (fp16)
__device__ float  g_o[MALL*CDIM];
__device__ __half g_xh[(size_t)MALL*CDIM];    // x pre-converted to fp16
__device__ __half g_oh[(size_t)MALL*CDIM];    // (o + dwc) pre-converted to fp16
__device__ __half g_wh[4*CDIM*CDIM];          // q_w | k_w | v_w | proj_w, fp16
__device__ float  g_part[SPLITS*BATCH*HEADS*AGENT*(HDIM+2) + 1024];
__device__ float  g_agent[BATCH*AGENT*CDIM];
__device__ float  g_agentv[BATCH*HEADS*AGENT*HDIM];
__device__ float  g_pb[HEADS*AGENT*NTOK];
__device__ float  g_ab[HEADS*NTOK*AGENT];

// ================= helpers =================
__device__ __forceinline__ uint32_t pack_h2(float lo, float hi) {
    uint32_t u;
    asm("cvt.rn.f16x2.f32 %0, %1, %2;" : "=r"(u) : "f"(hi), "f"(lo));
    return u;
}
__device__ __forceinline__ uint32_t smem_u32(const void* p) {
    uint32_t a;
    asm("{ .reg .u64 t; cvta.to.shared.u64 t, %1; cvt.u32.u64 %0, t; }" : "=r"(a) : "l"(p));
    return a;
}
__device__ __forceinline__ void mma_16x8x16h(float* d, const uint32_t* a, const uint32_t* b) {
    asm volatile(
        "mma.sync.aligned.m16n8k16.row.col.f32.f16.f16.f32 "
        "{%0,%1,%2,%3}, {%4,%5,%6,%7}, {%8,%9}, {%0,%1,%2,%3};"
        : "+f"(d[0]), "+f"(d[1]), "+f"(d[2]), "+f"(d[3])
        : "r"(a[0]), "r"(a[1]), "r"(a[2]), "r"(a[3]), "r"(b[0]), "r"(b[1]));
}
#define LDSM_X4(r, addr) \
    asm volatile("ldmatrix.sync.aligned.m8n8.x4.shared.b16 {%0,%1,%2,%3}, [%4];" \
        : "=r"((r)[0]), "=r"((r)[1]), "=r"((r)[2]), "=r"((r)[3]) : "r"(addr))
#define CP_ASYNC16(dst, src) \
    asm volatile("cp.async.cg.shared.global [%0], [%1], 16;" :: "r"(dst), "l"(src))

// ---------------- fp16 pre-conversion (float4 -> f16x2 pair) ----------------
__global__ __launch_bounds__(256) void f16_conv_kernel(
    const float* __restrict__ in, __half* __restrict__ out, int n4)
{
    int i = blockIdx.x * 256 + threadIdx.x;
    if (i < n4) {
        float4 v = ((const float4*)in)[i];
        uint2 u;
        u.x = pack_h2(v.x, v.y);
        u.y = pack_h2(v.z, v.w);
        ((uint2*)out)[i] = u;
    }
}

// ======= fp16 tensor-core GEMM: C[m,n] = sum_k A[m,k]*W[n,k] =======
// Writes fp16 (Ch) when Ch != nullptr, else fp32 C (+bias).
#define GSTG 3
#define STG_BYTES 32768                // A tile 16KB + B tile 16KB
#define GEMM_SMEM (GSTG*STG_BYTES)     // 98304 bytes

__global__ void __launch_bounds__(256, 2) mma_gemm(
    const __half* __restrict__ A, const __half* __restrict__ W,
    float* __restrict__ C, __half* __restrict__ Ch,
    const float* __restrict__ bias, int ldc)
{
    extern __shared__ float sm[];
    const int tid = threadIdx.x;
    const int wid = tid >> 5, lane = tid & 31;
    const int wm = (wid >> 2) * 64;
    const int wn = (wid & 3) * 32;
    const int g = lane >> 2, tg = lane & 3;
    const int bm = blockIdx.y * 128, bn = blockIdx.x * 128;
    const uint32_t smBase = smem_u32(sm);

    const __half* aSrc[4];
    const __half* wSrc[4];
    uint32_t dOff[4];
#pragma unroll
    for (int i = 0; i < 4; i++) {
        int id = i * 256 + tid;
        int r = id >> 3, c4 = id & 7;
        aSrc[i] = A + (size_t)(bm + r) * 512 + c4 * 8;
        wSrc[i] = W + (size_t)(bn + r) * 512 + c4 * 8;
        dOff[i] = (uint32_t)(r * 128 + ((c4 ^ (r & 7)) << 4));
    }

    const int mA = lane >> 3;
    const int rowA_base = wm + ((mA & 1) << 3) + (lane & 7);
    const int c4bA = mA >> 1;
    const int rowB_base = wn + ((lane >> 4) << 3) + (lane & 7);
    const int c4bB = (lane >> 3) & 1;

    float acc[4][4][4];
#pragma unroll
    for (int mi = 0; mi < 4; mi++)
#pragma unroll
        for (int ni = 0; ni < 4; ni++)
#pragma unroll
            for (int j = 0; j < 4; j++) acc[mi][ni][j] = 0.f;

#pragma unroll
    for (int kc = 0; kc < 2; kc++) {
        uint32_t sA = smBase + (uint32_t)(kc % GSTG) * STG_BYTES;
        uint32_t sB = sA + 16384;
        int koff = kc * 64;
#pragma unroll
        for (int i = 0; i < 4; i++) {
            CP_ASYNC16(sA + dOff[i], aSrc[i] + koff);
            CP_ASYNC16(sB + dOff[i], wSrc[i] + koff);
        }
        asm volatile("cp.async.commit_group;");
    }

    for (int kc = 0; kc < 8; kc++) {
        if (kc < 7) asm volatile("cp.async.wait_group 1;");
        else        asm volatile("cp.async.wait_group 0;");
        __syncthreads();
        if (kc + 2 < 8) {
            uint32_t sA = smBase + (uint32_t)((kc + 2) % GSTG) * STG_BYTES;
            uint32_t sB = sA + 16384;
            int koff = (kc + 2) * 64;
#pragma unroll
            for (int i = 0; i < 4; i++) {
                CP_ASYNC16(sA + dOff[i], aSrc[i] + koff);
                CP_ASYNC16(sB + dOff[i], wSrc[i] + koff);
            }
            asm volatile("cp.async.commit_group;");
        }
        const uint32_t sA = smBase + (uint32_t)(kc % GSTG) * STG_BYTES;
        const uint32_t sB = sA + 16384;
#pragma unroll
        for (int ks = 0; ks < 4; ks++) {
            uint32_t aF[4][4], bF[2][4];
#pragma unroll
            for (int mi = 0; mi < 4; mi++) {
                int row = rowA_base + mi * 16;
                int c4 = (2 * ks) | c4bA;
                LDSM_X4(aF[mi], sA + (uint32_t)(row * 128 + ((c4 ^ (row & 7)) << 4)));
            }
#pragma unroll
            for (int p = 0; p < 2; p++) {
                int row = rowB_base + p * 16;
                int c4 = (2 * ks) | c4bB;
                LDSM_X4(bF[p], sB + (uint32_t)(row * 128 + ((c4 ^ (row & 7)) << 4)));
            }
#pragma unroll
            for (int mi = 0; mi < 4; mi++)
#pragma unroll
                for (int p = 0; p < 2; p++) {
                    mma_16x8x16h(acc[mi][2 * p],     aF[mi], &bF[p][0]);
                    mma_16x8x16h(acc[mi][2 * p + 1], aF[mi], &bF[p][2]);
                }
        }
    }

#pragma unroll
    for (int mi = 0; mi < 4; mi++) {
        int row = bm + wm + mi * 16 + g;
#pragma unroll
        for (int ni = 0; ni < 4; ni++) {
            int col = bn + wn + ni * 8 + 2 * tg;
            if (Ch) {
                *(uint32_t*)&Ch[(size_t)row * ldc + col] = pack_h2(acc[mi][ni][0], acc[mi][ni][1]);
                *(uint32_t*)&Ch[(size_t)(row + 8) * ldc + col] = pack_h2(acc[mi][ni][2], acc[mi][ni][3]);
            } else {
                float b0 = 0.f, b1 = 0.f;
                if (bias) { b0 = bias[col]; b1 = bias[col + 1]; }
                float2 v0 = { acc[mi][ni][0] + b0, acc[mi][ni][1] + b1 };
                float2 v1 = { acc[mi][ni][2] + b0, acc[mi][ni][3] + b1 };
                *(float2*)&C[(size_t)row * ldc + col] = v0;
                *(float2*)&C[(size_t)(row + 8) * ldc + col] = v1;
            }
        }
    }
}

// ---------------- agent token pooling (q part of fp16 qkv) ----------------
__global__ __launch_bounds__(512) void pool_kernel(const __half* __restrict__ qkv,
                                                   float* __restrict__ ag)
{
    int c = threadIdx.x;
    int b = blockIdx.x / AGENT;
    int a = blockIdx.x % AGENT;
    int p1 = a / 7, p2 = a % 7;
    float s = 0.f;
#pragma unroll
    for (int i = 0; i < 8; i++)
#pragma unroll
        for (int j = 0; j < 8; j++)
            s += __half2float(qkv[((size_t)b * NTOK + (p1 * 8 + i) * WW + (p2 * 8 + j)) * QKVD + c]);
    ag[((size_t)b * AGENT + a) * CDIM + c] = s * (1.0f / 64.0f);
}

// ---------------- bias precompute ----------------
__global__ __launch_bounds__(256) void bias_kernel(
    const float* __restrict__ an, const float* __restrict__ na,
    const float* __restrict__ ahb, const float* __restrict__ awb,
    const float* __restrict__ hab, const float* __restrict__ wab,
    float* __restrict__ pb, float* __restrict__ ab)
{
    int h = blockIdx.x / AGENT;
    int a = blockIdx.x % AGENT;
    __shared__ float ans[49], nas[49];
    int tid = threadIdx.x;
    if (tid < 49) {
        ans[tid] = an[((size_t)h * AGENT + a) * 49 + tid];
        nas[tid] = na[((size_t)h * AGENT + a) * 49 + tid];
    }
    __syncthreads();
    for (int n = tid; n < NTOK; n += 256) {
        int y = n / WW, x = n % WW;
        float fy = (y + 0.5f) * 0.125f - 0.5f;
        float fx = (x + 0.5f) * 0.125f - 0.5f;
        int iy = (int)floorf(fy); float ty = fy - iy;
        int ix = (int)floorf(fx); float tx = fx - ix;
        float wy0 = 1.f - ty, wy1 = ty;
        int y0 = iy, y1 = iy + 1;
        if (y0 < 0) { wy0 = 0.f; y0 = 0; }
        if (y1 > 6) { wy1 = 0.f; y1 = 6; }
        float sy = wy0 + wy1; wy0 /= sy; wy1 /= sy;
        float wx0 = 1.f - tx, wx1 = tx;
        int x0 = ix, x1 = ix + 1;
        if (x0 < 0) { wx0 = 0.f; x0 = 0; }
        if (x1 > 6) { wx1 = 0.f; x1 = 6; }
        float sx = wx0 + wx1; wx0 /= sx; wx1 /= sx;

        float bi_an = wy0 * (wx0 * ans[y0 * 7 + x0] + wx1 * ans[y0 * 7 + x1]) +
                      wy1 * (wx0 * ans[y1 * 7 + x0] + wx1 * ans[y1 * 7 + x1]);
        float bi_na = wy0 * (wx0 * nas[y0 * 7 + x0] + wx1 * nas[y0 * 7 + x1]) +
                      wy1 * (wx0 * nas[y1 * 7 + x0] + wx1 * nas[y1 * 7 + x1]);

        pb[((size_t)h * AGENT + a) * NTOK + n] =
            bi_an + ahb[((size_t)h * AGENT + a) * 56 + y] + awb[((size_t)h * AGENT + a) * 56 + x];
        ab[((size_t)h * NTOK + n) * AGENT + a] =
            bi_na + hab[((size_t)h * 56 + y) * AGENT + a] + wab[((size_t)h * 56 + x) * AGENT + a];
    }
}

// ============ fused agent attention: fp16 mma logits + softmax + scalar attn@V ============
// bytes: AHs [0,8192) fp16 [64a][64d], Ks [8192,16384) fp16 [64n][64d],
//        Vb fp32 reuse [0,16640), L fp32 at 16896: [49][452]
#define AF_LBYTE 16896
#define AF_LSTR 452
#define AF_SMEM (AF_LBYTE + AGENT*AF_LSTR*4)   // 105488 bytes

__global__ __launch_bounds__(256) void agent_fused_kernel(
    const float* __restrict__ ag, const __half* __restrict__ qkv,
    const float* __restrict__ pb, float* __restrict__ part)
{
    extern __shared__ char smc[];
    float* L = (float*)(smc + AF_LBYTE);
    __shared__ float sm_m[AGENT], sm_s[AGENT];

    const int s  = blockIdx.x;
    const int bh = blockIdx.y;
    const int b = bh >> 3, h = bh & 7;
    const int tid = threadIdx.x;
    const int wid = tid >> 5, lane = tid & 31;
    const int g = lane >> 2, tg = lane & 3;
    const int mA = lane >> 3;
    const int n0base = s * NSPL;
    const uint32_t smBase = smem_u32(smc);

    // stage AH fp16 (scaled, rows >=49 zero): [64][64 halves]
    for (int i = tid; i < 64 * 8; i += 256) {
        int a = i >> 3, gq = i & 7;
        uint4 u = {0u, 0u, 0u, 0u};
        if (a < 49) {
            const float* src = &ag[((size_t)b * AGENT + a) * CDIM + h * 64 + gq * 8];
            float4 v0 = *(const float4*)src;
            float4 v1 = *(const float4*)(src + 4);
            u.x = pack_h2(v0.x * 0.125f, v0.y * 0.125f);
            u.y = pack_h2(v0.z * 0.125f, v0.w * 0.125f);
            u.z = pack_h2(v1.x * 0.125f, v1.y * 0.125f);
            u.w = pack_h2(v1.z * 0.125f, v1.w * 0.125f);
        }
        *(uint4*)(smc + a * 128 + ((gq ^ (a & 7)) << 4)) = u;
    }

    // ---- Phase 1 (fp16 mma): logits per 64-token chunk ----
    const int rA = ((mA & 1) << 3) + (lane & 7);   // + mt*16 (tokens = A)
    const int c4bA = mA >> 1;
    const int rB = ((wid >> 1) * 16) + ((lane >> 4) << 3) + (lane & 7);  // agents = B
    const int c4bB = (lane >> 3) & 1;
    const int sub = wid & 1;

    for (int c = 0; c < 7; c++) {
        int n0 = n0base + c * 64;
        __syncthreads();
        for (int i = tid; i < 64 * 8; i += 256) {   // K tokens: straight fp16 copy
            int nn = i >> 3, gq = i & 7;
            uint4 u = *(const uint4*)&qkv[((size_t)b * NTOK + n0 + nn) * QKVD + 512 + h * 64 + gq * 8];
            *(uint4*)(smc + 8192 + nn * 128 + ((gq ^ (nn & 7)) << 4)) = u;
        }
        __syncthreads();
        if (wid < 7) {
            float acc[4][4];
#pragma unroll
            for (int mt = 0; mt < 4; mt++)
#pragma unroll
                for (int j = 0; j < 4; j++) acc[mt][j] = 0.f;
#pragma unroll
            for (int ks = 0; ks < 4; ks++) {
                uint32_t bF[4];
                {
                    int c4 = (2 * ks) | c4bB;
                    LDSM_X4(bF, smBase + (uint32_t)(rB * 128 + ((c4 ^ (rB & 7)) << 4)));
                }
#pragma unroll
                for (int mt = 0; mt < 4; mt++) {
                    uint32_t aF[4];
                    int row = mt * 16 + rA;
                    int c4 = (2 * ks) | c4bA;
                    LDSM_X4(aF, smBase + (uint32_t)(8192 + row * 128 + ((c4 ^ (row & 7)) << 4)));
                    mma_16x8x16h(acc[mt], aF, &bF[sub * 2]);
                }
            }
#pragma unroll
            for (int mt = 0; mt < 4; mt++)
#pragma unroll
                for (int j = 0; j < 4; j++) {
                    int a = wid * 8 + 2 * tg + (j & 1);
                    if (a < 49) {
                        int nloc = c * 64 + mt * 16 + g + ((j >> 1) << 3);
                        L[a * AF_LSTR + nloc] =
                            acc[mt][j] + pb[((size_t)h * AGENT + a) * NTOK + n0base + nloc];
                    }
                }
        }
    }
    __syncthreads();

    // ---- Phase 2: per-a max & sum; L <- exp(L - m) ----
    {
        for (int a = wid; a < AGENT; a += 8) {
            float m = -1e30f;
            for (int j = lane; j < NSPL; j += 32) m = fmaxf(m, L[a * AF_LSTR + j]);
#pragma unroll
            for (int o = 16; o > 0; o >>= 1) m = fmaxf(m, __shfl_xor_sync(0xffffffffu, m, o));
            float sum = 0.f;
            for (int j = lane; j < NSPL; j += 32) {
                float e = __expf(L[a * AF_LSTR + j] - m);
                L[a * AF_LSTR + j] = e;
                sum += e;
            }
#pragma unroll
            for (int o = 16; o > 0; o >>= 1) sum += __shfl_xor_sync(0xffffffffu, sum, o);
            if (lane == 0) { sm_m[a] = m; sm_s[a] = sum; }
        }
    }
    __syncthreads();

    // ---- Phase 3 (scalar): partial acc[a][d] = sum_n expL * v[n][d] ----
    float* Vb = (float*)smc;   // [64][65] fp32
    const int nl = tid & 63, abase = tid >> 6;
    float acc[13];
#pragma unroll
    for (int i = 0; i < 13; i++) acc[i] = 0.f;
    const int d = nl;
    for (int c = 0; c < 7; c++) {
        int n0 = n0base + c * 64;
        __syncthreads();
        for (int i = tid; i < 64 * 8; i += 256) {
            int nn = i >> 3, gq = i & 7;
            uint4 u = *(const uint4*)&qkv[((size_t)b * NTOK + n0 + nn) * QKVD + 1024 + h * 64 + gq * 8];
            const __half2* hp = (const __half2*)&u;
            int base = nn * 65 + gq * 8;
            float2 f0 = __half22float2(hp[0]);
            float2 f1 = __half22float2(hp[1]);
            float2 f2 = __half22float2(hp[2]);
            float2 f3 = __half22float2(hp[3]);
            Vb[base + 0] = f0.x; Vb[base + 1] = f0.y;
            Vb[base + 2] = f1.x; Vb[base + 3] = f1.y;
            Vb[base + 4] = f2.x; Vb[base + 5] = f2.y;
            Vb[base + 6] = f3.x; Vb[base + 7] = f3.y;
        }
        __syncthreads();
#pragma unroll 8
        for (int nn = 0; nn < 64; nn++) {
            float vd = Vb[nn * 65 + d];
            int a = abase;
#pragma unroll
            for (int i = 0; i < 13; i++) { if (a < 49) acc[i] += L[a * AF_LSTR + c * 64 + nn] * vd; a += 4; }
        }
    }

    float* pacc = part;
    float* pms  = part + (size_t)SPLITS * 128 * AGENT * HDIM;
    {
        int a = abase;
#pragma unroll
        for (int i = 0; i < 13; i++) {
            if (a < 49) pacc[(((size_t)s * 128 + bh) * AGENT + a) * HDIM + d] = acc[i];
            a += 4;
        }
    }
    if (tid < AGENT) {
        pms[(((size_t)s * 128 + bh) * AGENT + tid) * 2 + 0] = sm_m[tid];
        pms[(((size_t)s * 128 + bh) * AGENT + tid) * 2 + 1] = sm_s[tid];
    }
}

// ---- combine splits ----
__global__ __launch_bounds__(256) void agent_combine_kernel(
    const float* __restrict__ part, float* __restrict__ av)
{
    const int bh = blockIdx.x;
    const int tid = threadIdx.x;
    const int d = tid & 63, abase = tid >> 6;
    const float* pacc = part;
    const float* pms  = part + (size_t)SPLITS * 128 * AGENT * HDIM;

    int a = abase;
#pragma unroll
    for (int i = 0; i < 13; i++) {
        if (a < 49) {
            float mstar = -1e30f;
            float ms[SPLITS], ss[SPLITS];
#pragma unroll
            for (int s = 0; s < SPLITS; s++) {
                ms[s] = pms[(((size_t)s * 128 + bh) * AGENT + a) * 2 + 0];
                ss[s] = pms[(((size_t)s * 128 + bh) * AGENT + a) * 2 + 1];
                mstar = fmaxf(mstar, ms[s]);
            }
            float S = 0.f, o = 0.f;
#pragma unroll
            for (int s = 0; s < SPLITS; s++) {
                float f = __expf(ms[s] - mstar);
                S += ss[s] * f;
                o += pacc[(((size_t)s * 128 + bh) * AGENT + a) * HDIM + d] * f;
            }
            av[((size_t)bh * AGENT + a) * HDIM + d] = o / S;
        }
        a += 4;
    }
}

// ======= q attention via fp16 tensor cores =======
// bytes: Qs/P [0,14336) [112][64h], AHs [14336,22528), AVt [22528,30720), ABs fp32 [30720,52672)
#define QA_SMEM 52672

__global__ void __launch_bounds__(224, 2) qattn_mma(
    const __half* __restrict__ qkv, const float* __restrict__ ag,
    const float* __restrict__ av, const float* __restrict__ ab, float* __restrict__ o)
{
    extern __shared__ char sqc[];
    const int bh = blockIdx.y, b = bh >> 3, h = bh & 7;
    const int n0 = blockIdx.x * 112;
    const int tid = threadIdx.x, wid = tid >> 5, lane = tid & 31;
    const int g = lane >> 2, tg = lane & 3;
    const uint32_t smBase = smem_u32(sqc);
    float* ABs = (float*)(sqc + 30720);

    // stage Q fp16 (straight copy)
    for (int i = tid; i < 112 * 8; i += 224) {
        int r = i >> 3, gq = i & 7;
        uint4 u = *(const uint4*)&qkv[((size_t)b * NTOK + n0 + r) * QKVD + h * 64 + gq * 8];
        *(uint4*)(sqc + r * 128 + ((gq ^ (r & 7)) << 4)) = u;
    }
    // stage AH fp16 (scaled, padded)
    for (int i = tid; i < 64 * 8; i += 224) {
        int a = i >> 3, gq = i & 7;
        uint4 u = {0u, 0u, 0u, 0u};
        if (a < 49) {
            const float* src = &ag[((size_t)b * AGENT + a) * CDIM + h * 64 + gq * 8];
            float4 v0 = *(const float4*)src;
            float4 v1 = *(const float4*)(src + 4);
            u.x = pack_h2(v0.x * 0.125f, v0.y * 0.125f);
            u.y = pack_h2(v0.z * 0.125f, v0.w * 0.125f);
            u.z = pack_h2(v1.x * 0.125f, v1.y * 0.125f);
            u.w = pack_h2(v1.z * 0.125f, v1.w * 0.125f);
        }
        *(uint4*)(sqc + 14336 + a * 128 + ((gq ^ (a & 7)) << 4)) = u;
    }
    // stage AVt fp16 (rows = d, cols = agents, padded)
    for (int i = tid; i < 64 * 8; i += 224) {
        int d = i >> 3, gq = i & 7;
        uint32_t uu[4];
#pragma unroll
        for (int j = 0; j < 4; j++) {
            int a0 = gq * 8 + 2 * j, a1 = a0 + 1;
            float f0 = (a0 < 49) ? av[((size_t)bh * AGENT + a0) * HDIM + d] : 0.f;
            float f1 = (a1 < 49) ? av[((size_t)bh * AGENT + a1) * HDIM + d] : 0.f;
            uu[j] = pack_h2(f0, f1);
        }
        uint4 u = { uu[0], uu[1], uu[2], uu[3] };
        *(uint4*)(sqc + 22528 + d * 128 + ((gq ^ (d & 7)) << 4)) = u;
    }
    {
        const float4* src = (const float4*)(ab + ((size_t)h * NTOK + n0) * 49);
        for (int i = tid; i < 112 * 49 / 4; i += 224) ((float4*)ABs)[i] = src[i];
    }
    __syncthreads();

    const int wm = wid * 16;
    const int mA = lane >> 3;
    const int rA = wm + ((mA & 1) << 3) + (lane & 7);
    const int c4bA = mA >> 1;
    const int rB = ((lane >> 4) << 3) + (lane & 7);
    const int c4bB = (lane >> 3) & 1;

    // ---- logits mma (K = 64 halves, 4 k16 steps) ----
    float acc[7][4];
#pragma unroll
    for (int nt = 0; nt < 7; nt++)
#pragma unroll
        for (int j = 0; j < 4; j++) acc[nt][j] = 0.f;

#pragma unroll
    for (int ks = 0; ks < 4; ks++) {
        uint32_t aF[4], bF[4][4];
        {
            int c4 = (2 * ks) | c4bA;
            LDSM_X4(aF, smBase + (uint32_t)(rA * 128 + ((c4 ^ (rA & 7)) << 4)));
        }
        int c4b = (2 * ks) | c4bB;
#pragma unroll
        for (int p = 0; p < 4; p++) {
            int row = p * 16 + rB;
            LDSM_X4(bF[p], smBase + (uint32_t)(14336 + row * 128 + ((c4b ^ (row & 7)) << 4)));
        }
#pragma unroll
        for (int nt = 0; nt < 7; nt++)
            mma_16x8x16h(acc[nt], aF, &bF[nt >> 1][(nt & 1) * 2]);
    }

    // ---- bias + mask + softmax in fragments ----
    const int rl0 = wm + g;
    float m0 = -1e30f, m8 = -1e30f;
    float vals[7][4];
#pragma unroll
    for (int nt = 0; nt < 7; nt++) {
        int c0 = nt * 8 + 2 * tg, c1 = c0 + 1;
        float v0 = (c0 < 49) ? acc[nt][0] + ABs[rl0 * 49 + c0]       : -1e30f;
        float v1 = (c1 < 49) ? acc[nt][1] + ABs[rl0 * 49 + c1]       : -1e30f;
        float v2 = (c0 < 49) ? acc[nt][2] + ABs[(rl0 + 8) * 49 + c0] : -1e30f;
        float v3 = (c1 < 49) ? acc[nt][3] + ABs[(rl0 + 8) * 49 + c1] : -1e30f;
        vals[nt][0] = v0; vals[nt][1] = v1; vals[nt][2] = v2; vals[nt][3] = v3;
        m0 = fmaxf(m0, fmaxf(v0, v1));
        m8 = fmaxf(m8, fmaxf(v2, v3));
    }
    m0 = fmaxf(m0, __shfl_xor_sync(0xffffffffu, m0, 1));
    m0 = fmaxf(m0, __shfl_xor_sync(0xffffffffu, m0, 2));
    m8 = fmaxf(m8, __shfl_xor_sync(0xffffffffu, m8, 1));
    m8 = fmaxf(m8, __shfl_xor_sync(0xffffffffu, m8, 2));
    float s0 = 0.f, s8 = 0.f;
#pragma unroll
    for (int nt = 0; nt < 7; nt++) {
        int c0 = nt * 8 + 2 * tg, c1 = c0 + 1;
        float e0 = (c0 < 49) ? __expf(vals[nt][0] - m0) : 0.f;
        float e1 = (c1 < 49) ? __expf(vals[nt][1] - m0) : 0.f;
        float e2 = (c0 < 49) ? __expf(vals[nt][2] - m8) : 0.f;
        float e3 = (c1 < 49) ? __expf(vals[nt][3] - m8) : 0.f;
        vals[nt][0] = e0; vals[nt][1] = e1; vals[nt][2] = e2; vals[nt][3] = e3;
        s0 += e0 + e1; s8 += e2 + e3;
    }
    s0 += __shfl_xor_sync(0xffffffffu, s0, 1);
    s0 += __shfl_xor_sync(0xffffffffu, s0, 2);
    s8 += __shfl_xor_sync(0xffffffffu, s8, 1);
    s8 += __shfl_xor_sync(0xffffffffu, s8, 2);
    const float i0 = 1.0f / s0, i8 = 1.0f / s8;

    // ---- store normalized P (fp16) into Q buffer; stale cols >=56 killed by AVt zeros ----
#pragma unroll
    for (int nt = 0; nt < 7; nt++) {
        int c0 = nt * 8 + 2 * tg;
        int gq = c0 >> 3, byt = (c0 & 7) * 2;
        uint32_t o0 = rl0 * 128 + ((gq ^ (rl0 & 7)) << 4) + byt;
        uint32_t o8 = (rl0 + 8) * 128 + ((gq ^ ((rl0 + 8) & 7)) << 4) + byt;
        *(uint32_t*)(sqc + o0) = pack_h2(vals[nt][0] * i0, vals[nt][1] * i0);
        *(uint32_t*)(sqc + o8) = pack_h2(vals[nt][2] * i8, vals[nt][3] * i8);
    }
    __syncwarp();

    // ---- out mma: P @ AVt (K = 64 agents pad) ----
    float ao[8][4];
#pragma unroll
    for (int nt = 0; nt < 8; nt++)
#pragma unroll
        for (int j = 0; j < 4; j++) ao[nt][j] = 0.f;

#pragma unroll
    for (int ks = 0; ks < 4; ks++) {
        uint32_t aF[4], bF[4][4];
        {
            int c4 = (2 * ks) | c4bA;
            LDSM_X4(aF, smBase + (uint32_t)(rA * 128 + ((c4 ^ (rA & 7)) << 4)));
        }
        int c4b = (2 * ks) | c4bB;
#pragma unroll
        for (int p = 0; p < 4; p++) {
            int row = p * 16 + rB;
            LDSM_X4(bF[p], smBase + (uint32_t)(22528 + row * 128 + ((c4b ^ (row & 7)) << 4)));
        }
#pragma unroll
        for (int nt = 0; nt < 8; nt++)
            mma_16x8x16h(ao[nt], aF, &bF[nt >> 1][(nt & 1) * 2]);
    }

    const size_t row0 = (size_t)b * NTOK + n0 + rl0;
#pragma unroll
    for (int nt = 0; nt < 8; nt++) {
        int col = nt * 8 + 2 * tg;
        float2 v0 = { ao[nt][0], ao[nt][1] };
        float2 v8 = { ao[nt][2], ao[nt][3] };
        *(float2*)&o[row0 * 512 + h * 64 + col] = v0;
        *(float2*)&o[(row0 + 8) * 512 + h * 64 + col] = v8;
    }
}

// ------- depthwise 3x3 conv on fp16 v, add to o, emit fp16 proj input -------
__global__ __launch_bounds__(512) void dwc_kernel(
    const __half* __restrict__ qkv, const float* __restrict__ w,
    const float* __restrict__ bias, const float* __restrict__ o,
    __half* __restrict__ oh)
{
    int c = threadIdx.x;
    int n = blockIdx.x;
    int b = blockIdx.y;
    int y = n / WW, x = n % WW;
    float acc = bias[c];
#pragma unroll
    for (int dy = -1; dy <= 1; dy++) {
        int yy = y + dy; if (yy < 0 || yy >= HH) continue;
#pragma unroll
        for (int dx = -1; dx <= 1; dx++) {
            int xx = x + dx; if (xx < 0 || xx >= WW) continue;
            acc += __half2float(qkv[((size_t)b * NTOK + yy * WW + xx) * QKVD + 1024 + c]) *
                   w[c * 9 + (dy + 1) * 3 + (dx + 1)];
        }
    }
    size_t idx = ((size_t)b * NTOK + n) * CDIM + c;
    oh[idx] = __float2half_rn(o[idx] + acc);
}

// ---------------- launch ----------------
extern "C" void kernel_launch(void* const* d_in, const int* in_sizes, int n_in,
                              void* d_out, int out_size)
{
    const float* x      = (const float*)d_in[0];
    const float* q_w    = (const float*)d_in[3];
    const float* kv_w   = (const float*)d_in[4];
    const float* proj_w = (const float*)d_in[5];
    const float* proj_b = (const float*)d_in[6];
    const float* dwc_w  = (const float*)d_in[7];
    const float* dwc_b  = (const float*)d_in[8];
    const float* an_b   = (const float*)d_in[9];
    const float* na_b   = (const float*)d_in[10];
    const float* ah_b   = (const float*)d_in[11];
    const float* aw_b   = (const float*)d_in[12];
    const float* ha_b   = (const float*)d_in[13];
    const float* wa_b   = (const float*)d_in[14];
    float* out = (float*)d_out;

    float *op, *prt, *agp, *avp, *pbp, *abp;
    __half *qkvh, *xh, *oh, *wh;
    cudaGetSymbolAddress((void**)&qkvh, g_qkv);
    cudaGetSymbolAddress((void**)&op,  g_o);
    cudaGetSymbolAddress((void**)&xh,  g_xh);
    cudaGetSymbolAddress((void**)&oh,  g_oh);
    cudaGetSymbolAddress((void**)&wh,  g_wh);
    cudaGetSymbolAddress((void**)&prt, g_part);
    cudaGetSymbolAddress((void**)&agp, g_agent);
    cudaGetSymbolAddress((void**)&avp, g_agentv);
    cudaGetSymbolAddress((void**)&pbp, g_pb);
    cudaGetSymbolAddress((void**)&abp, g_ab);

    cudaFuncSetAttribute(mma_gemm, cudaFuncAttributeMaxDynamicSharedMemorySize, GEMM_SMEM);
    cudaFuncSetAttribute(agent_fused_kernel, cudaFuncAttributeMaxDynamicSharedMemorySize, AF_SMEM);
    cudaFuncSetAttribute(qattn_mma, cudaFuncAttributeMaxDynamicSharedMemorySize, QA_SMEM);

    // pre-convert x and weights to fp16
    {
        int n4 = MALL * CDIM / 4;
        f16_conv_kernel<<<(n4 + 255) / 256, 256>>>(x, xh, n4);
        int w4 = CDIM * CDIM / 4;
        f16_conv_kernel<<<(w4 + 255) / 256, 256>>>(q_w, wh, w4);
        f16_conv_kernel<<<(2 * w4 + 255) / 256, 256>>>(kv_w, wh + CDIM * CDIM, 2 * w4);
        f16_conv_kernel<<<(w4 + 255) / 256, 256>>>(proj_w, wh + 3 * CDIM * CDIM, w4);
    }

    // merged q|k|v projection: N = 1536, fp16 output
    mma_gemm<<<dim3(QKVD / 128, MALL / 128), 256, GEMM_SMEM>>>(xh, wh, nullptr, qkvh, nullptr, QKVD);

    pool_kernel<<<BATCH * AGENT, CDIM>>>(qkvh, agp);
    bias_kernel<<<HEADS * AGENT, 256>>>(an_b, na_b, ah_b, aw_b, ha_b, wa_b, pbp, abp);

    agent_fused_kernel<<<dim3(SPLITS, BATCH * HEADS), 256, AF_SMEM>>>(agp, qkvh, pbp, prt);
    agent_combine_kernel<<<BATCH * HEADS, 256>>>(prt, avp);

    qattn_mma<<<dim3(28, BATCH * HEADS), 224, QA_SMEM>>>(qkvh, agp, avp, abp, op);
    dwc_kernel<<<dim3(NTOK, BATCH), CDIM>>>(qkvh, dwc_w, dwc_b, op, oh);

    // final projection: fp32 output + bias
    mma_gemm<<<dim3(CDIM / 128, MALL / 128), 256, GEMM_SMEM>>>(oh, wh + 3 * CDIM * CDIM, out, nullptr, proj_b, CDIM);
}

// round 16
// speedup vs baseline: 4.6088x; 1.0837x over previous
#include <cuda_runtime.h>
#include <cuda_bf16.h>
#include <cuda_fp16.h>
#include <cstdint>

// ---------------- problem constants ----------------
#define BATCH 16
#define CDIM  512
#define HH    56
#define WW    56
#define NTOK  3136          // 56*56
#define HEADS 8
#define HDIM  64
#define AGENT 49
#define MALL  (BATCH*NTOK)  // 50176
#define SPLITS 7
#define NSPL  448           // NTOK / SPLITS
#define QKVD  1536          // merged qkv row stride

// ---------------- scratch (static device memory; no allocation) ----------------
__device__ __half g_qkv[(size_t)MALL*QKVD];   // q | k | v per row (fp16)
__device__ __half g_xh[(size_t)MALL*CDIM];    // x pre-converted to fp16
__device__ __half g_oh[(size_t)MALL*CDIM];    // attention out -> (+dwc) proj input, fp16
__device__ __half g_wh[4*CDIM*CDIM];          // q_w | k_w | v_w | proj_w, fp16
__device__ float  g_part[SPLITS*BATCH*HEADS*AGENT*(HDIM+2) + 1024];
__device__ float  g_agent[BATCH*AGENT*CDIM];
__device__ float  g_agentv[BATCH*HEADS*AGENT*HDIM];
__device__ float  g_pb[HEADS*AGENT*NTOK];
__device__ float  g_ab[HEADS*NTOK*AGENT];

// ================= helpers =================
__device__ __forceinline__ uint32_t pack_h2(float lo, float hi) {
    uint32_t u;
    asm("cvt.rn.f16x2.f32 %0, %1, %2;" : "=r"(u) : "f"(hi), "f"(lo));
    return u;
}
__device__ __forceinline__ uint32_t smem_u32(const void* p) {
    uint32_t a;
    asm("{ .reg .u64 t; cvta.to.shared.u64 t, %1; cvt.u32.u64 %0, t; }" : "=r"(a) : "l"(p));
    return a;
}
__device__ __forceinline__ void mma_16x8x16h(float* d, const uint32_t* a, const uint32_t* b) {
    asm volatile(
        "mma.sync.aligned.m16n8k16.row.col.f32.f16.f16.f32 "
        "{%0,%1,%2,%3}, {%4,%5,%6,%7}, {%8,%9}, {%0,%1,%2,%3};"
        : "+f"(d[0]), "+f"(d[1]), "+f"(d[2]), "+f"(d[3])
        : "r"(a[0]), "r"(a[1]), "r"(a[2]), "r"(a[3]), "r"(b[0]), "r"(b[1]));
}
#define LDSM_X4(r, addr) \
    asm volatile("ldmatrix.sync.aligned.m8n8.x4.shared.b16 {%0,%1,%2,%3}, [%4];" \
        : "=r"((r)[0]), "=r"((r)[1]), "=r"((r)[2]), "=r"((r)[3]) : "r"(addr))
#define CP_ASYNC16(dst, src) \
    asm volatile("cp.async.cg.shared.global [%0], [%1], 16;" :: "r"(dst), "l"(src))

// ---------------- fp16 pre-conversion (float4 -> f16x2 pair) ----------------
__global__ __launch_bounds__(256) void f16_conv_kernel(
    const float* __restrict__ in, __half* __restrict__ out, int n4)
{
    int i = blockIdx.x * 256 + threadIdx.x;
    if (i < n4) {
        float4 v = ((const float4*)in)[i];
        uint2 u;
        u.x = pack_h2(v.x, v.y);
        u.y = pack_h2(v.z, v.w);
        ((uint2*)out)[i] = u;
    }
}

// ======= fp16 tensor-core GEMM: C[m,n] = sum_k A[m,k]*W[n,k] =======
// Writes fp16 (Ch) when Ch != nullptr, else fp32 C (+bias).
#define GSTG 3
#define STG_BYTES 32768
#define GEMM_SMEM (GSTG*STG_BYTES)     // 98304 bytes

__global__ void __launch_bounds__(256, 2) mma_gemm(
    const __half* __restrict__ A, const __half* __restrict__ W,
    float* __restrict__ C, __half* __restrict__ Ch,
    const float* __restrict__ bias, int ldc)
{
    extern __shared__ float sm[];
    const int tid = threadIdx.x;
    const int wid = tid >> 5, lane = tid & 31;
    const int wm = (wid >> 2) * 64;
    const int wn = (wid & 3) * 32;
    const int g = lane >> 2, tg = lane & 3;
    const int bm = blockIdx.y * 128, bn = blockIdx.x * 128;
    const uint32_t smBase = smem_u32(sm);

    const __half* aSrc[4];
    const __half* wSrc[4];
    uint32_t dOff[4];
#pragma unroll
    for (int i = 0; i < 4; i++) {
        int id = i * 256 + tid;
        int r = id >> 3, c4 = id & 7;
        aSrc[i] = A + (size_t)(bm + r) * 512 + c4 * 8;
        wSrc[i] = W + (size_t)(bn + r) * 512 + c4 * 8;
        dOff[i] = (uint32_t)(r * 128 + ((c4 ^ (r & 7)) << 4));
    }

    const int mA = lane >> 3;
    const int rowA_base = wm + ((mA & 1) << 3) + (lane & 7);
    const int c4bA = mA >> 1;
    const int rowB_base = wn + ((lane >> 4) << 3) + (lane & 7);
    const int c4bB = (lane >> 3) & 1;

    float acc[4][4][4];
#pragma unroll
    for (int mi = 0; mi < 4; mi++)
#pragma unroll
        for (int ni = 0; ni < 4; ni++)
#pragma unroll
            for (int j = 0; j < 4; j++) acc[mi][ni][j] = 0.f;

#pragma unroll
    for (int kc = 0; kc < 2; kc++) {
        uint32_t sA = smBase + (uint32_t)(kc % GSTG) * STG_BYTES;
        uint32_t sB = sA + 16384;
        int koff = kc * 64;
#pragma unroll
        for (int i = 0; i < 4; i++) {
            CP_ASYNC16(sA + dOff[i], aSrc[i] + koff);
            CP_ASYNC16(sB + dOff[i], wSrc[i] + koff);
        }
        asm volatile("cp.async.commit_group;");
    }

    for (int kc = 0; kc < 8; kc++) {
        if (kc < 7) asm volatile("cp.async.wait_group 1;");
        else        asm volatile("cp.async.wait_group 0;");
        __syncthreads();
        if (kc + 2 < 8) {
            uint32_t sA = smBase + (uint32_t)((kc + 2) % GSTG) * STG_BYTES;
            uint32_t sB = sA + 16384;
            int koff = (kc + 2) * 64;
#pragma unroll
            for (int i = 0; i < 4; i++) {
                CP_ASYNC16(sA + dOff[i], aSrc[i] + koff);
                CP_ASYNC16(sB + dOff[i], wSrc[i] + koff);
            }
            asm volatile("cp.async.commit_group;");
        }
        const uint32_t sA = smBase + (uint32_t)(kc % GSTG) * STG_BYTES;
        const uint32_t sB = sA + 16384;
#pragma unroll
        for (int ks = 0; ks < 4; ks++) {
            uint32_t aF[4][4], bF[2][4];
#pragma unroll
            for (int mi = 0; mi < 4; mi++) {
                int row = rowA_base + mi * 16;
                int c4 = (2 * ks) | c4bA;
                LDSM_X4(aF[mi], sA + (uint32_t)(row * 128 + ((c4 ^ (row & 7)) << 4)));
            }
#pragma unroll
            for (int p = 0; p < 2; p++) {
                int row = rowB_base + p * 16;
                int c4 = (2 * ks) | c4bB;
                LDSM_X4(bF[p], sB + (uint32_t)(row * 128 + ((c4 ^ (row & 7)) << 4)));
            }
#pragma unroll
            for (int mi = 0; mi < 4; mi++)
#pragma unroll
                for (int p = 0; p < 2; p++) {
                    mma_16x8x16h(acc[mi][2 * p],     aF[mi], &bF[p][0]);
                    mma_16x8x16h(acc[mi][2 * p + 1], aF[mi], &bF[p][2]);
                }
        }
    }

#pragma unroll
    for (int mi = 0; mi < 4; mi++) {
        int row = bm + wm + mi * 16 + g;
#pragma unroll
        for (int ni = 0; ni < 4; ni++) {
            int col = bn + wn + ni * 8 + 2 * tg;
            if (Ch) {
                *(uint32_t*)&Ch[(size_t)row * ldc + col] = pack_h2(acc[mi][ni][0], acc[mi][ni][1]);
                *(uint32_t*)&Ch[(size_t)(row + 8) * ldc + col] = pack_h2(acc[mi][ni][2], acc[mi][ni][3]);
            } else {
                float b0 = 0.f, b1 = 0.f;
                if (bias) { b0 = bias[col]; b1 = bias[col + 1]; }
                float2 v0 = { acc[mi][ni][0] + b0, acc[mi][ni][1] + b1 };
                float2 v1 = { acc[mi][ni][2] + b0, acc[mi][ni][3] + b1 };
                *(float2*)&C[(size_t)row * ldc + col] = v0;
                *(float2*)&C[(size_t)(row + 8) * ldc + col] = v1;
            }
        }
    }
}

// ---------------- agent token pooling (q part of fp16 qkv) ----------------
__global__ __launch_bounds__(512) void pool_kernel(const __half* __restrict__ qkv,
                                                   float* __restrict__ ag)
{
    int c = threadIdx.x;
    int b = blockIdx.x / AGENT;
    int a = blockIdx.x % AGENT;
    int p1 = a / 7, p2 = a % 7;
    float s = 0.f;
#pragma unroll
    for (int i = 0; i < 8; i++)
#pragma unroll
        for (int j = 0; j < 8; j++)
            s += __half2float(qkv[((size_t)b * NTOK + (p1 * 8 + i) * WW + (p2 * 8 + j)) * QKVD + c]);
    ag[((size_t)b * AGENT + a) * CDIM + c] = s * (1.0f / 64.0f);
}

// ---------------- bias precompute ----------------
__global__ __launch_bounds__(256) void bias_kernel(
    const float* __restrict__ an, const float* __restrict__ na,
    const float* __restrict__ ahb, const float* __restrict__ awb,
    const float* __restrict__ hab, const float* __restrict__ wab,
    float* __restrict__ pb, float* __restrict__ ab)
{
    int h = blockIdx.x / AGENT;
    int a = blockIdx.x % AGENT;
    __shared__ float ans[49], nas[49];
    int tid = threadIdx.x;
    if (tid < 49) {
        ans[tid] = an[((size_t)h * AGENT + a) * 49 + tid];
        nas[tid] = na[((size_t)h * AGENT + a) * 49 + tid];
    }
    __syncthreads();
    for (int n = tid; n < NTOK; n += 256) {
        int y = n / WW, x = n % WW;
        float fy = (y + 0.5f) * 0.125f - 0.5f;
        float fx = (x + 0.5f) * 0.125f - 0.5f;
        int iy = (int)floorf(fy); float ty = fy - iy;
        int ix = (int)floorf(fx); float tx = fx - ix;
        float wy0 = 1.f - ty, wy1 = ty;
        int y0 = iy, y1 = iy + 1;
        if (y0 < 0) { wy0 = 0.f; y0 = 0; }
        if (y1 > 6) { wy1 = 0.f; y1 = 6; }
        float sy = wy0 + wy1; wy0 /= sy; wy1 /= sy;
        float wx0 = 1.f - tx, wx1 = tx;
        int x0 = ix, x1 = ix + 1;
        if (x0 < 0) { wx0 = 0.f; x0 = 0; }
        if (x1 > 6) { wx1 = 0.f; x1 = 6; }
        float sx = wx0 + wx1; wx0 /= sx; wx1 /= sx;

        float bi_an = wy0 * (wx0 * ans[y0 * 7 + x0] + wx1 * ans[y0 * 7 + x1]) +
                      wy1 * (wx0 * ans[y1 * 7 + x0] + wx1 * ans[y1 * 7 + x1]);
        float bi_na = wy0 * (wx0 * nas[y0 * 7 + x0] + wx1 * nas[y0 * 7 + x1]) +
                      wy1 * (wx0 * nas[y1 * 7 + x0] + wx1 * nas[y1 * 7 + x1]);

        pb[((size_t)h * AGENT + a) * NTOK + n] =
            bi_an + ahb[((size_t)h * AGENT + a) * 56 + y] + awb[((size_t)h * AGENT + a) * 56 + x];
        ab[((size_t)h * NTOK + n) * AGENT + a] =
            bi_na + hab[((size_t)h * 56 + y) * AGENT + a] + wab[((size_t)h * 56 + x) * AGENT + a];
    }
}

// ============ fused agent attention: fp16 mma logits + softmax + fp16 mma attn@V ============
// bytes: [0,8192) AHs fp16 -> later PH fp16 | [8192,16384) Ks fp16 -> later Vt fp16
//        [16896, +49*452*4) L fp32
#define AF_LBYTE 16896
#define AF_LSTR 452
#define AF_SMEM (AF_LBYTE + AGENT*AF_LSTR*4)   // 105488 bytes

__global__ __launch_bounds__(256) void agent_fused_kernel(
    const float* __restrict__ ag, const __half* __restrict__ qkv,
    const float* __restrict__ pb, float* __restrict__ part)
{
    extern __shared__ char smc[];
    float* L = (float*)(smc + AF_LBYTE);
    __shared__ float sm_m[AGENT], sm_s[AGENT];

    const int s  = blockIdx.x;
    const int bh = blockIdx.y;
    const int b = bh >> 3, h = bh & 7;
    const int tid = threadIdx.x;
    const int wid = tid >> 5, lane = tid & 31;
    const int g = lane >> 2, tg = lane & 3;
    const int mA = lane >> 3;
    const int n0base = s * NSPL;
    const uint32_t smBase = smem_u32(smc);

    // stage AH fp16 (scaled, rows >=49 zero): [64][64 halves]
    for (int i = tid; i < 64 * 8; i += 256) {
        int a = i >> 3, gq = i & 7;
        uint4 u = {0u, 0u, 0u, 0u};
        if (a < 49) {
            const float* src = &ag[((size_t)b * AGENT + a) * CDIM + h * 64 + gq * 8];
            float4 v0 = *(const float4*)src;
            float4 v1 = *(const float4*)(src + 4);
            u.x = pack_h2(v0.x * 0.125f, v0.y * 0.125f);
            u.y = pack_h2(v0.z * 0.125f, v0.w * 0.125f);
            u.z = pack_h2(v1.x * 0.125f, v1.y * 0.125f);
            u.w = pack_h2(v1.z * 0.125f, v1.w * 0.125f);
        }
        *(uint4*)(smc + a * 128 + ((gq ^ (a & 7)) << 4)) = u;
    }

    // ---- Phase 1 (fp16 mma): logits per 64-token chunk ----
    const int rA = ((mA & 1) << 3) + (lane & 7);   // + mt*16 (tokens = A)
    const int c4bA = mA >> 1;
    const int rB = ((wid >> 1) * 16) + ((lane >> 4) << 3) + (lane & 7);  // agents = B
    const int c4bB = (lane >> 3) & 1;
    const int sub = wid & 1;

    for (int c = 0; c < 7; c++) {
        int n0 = n0base + c * 64;
        __syncthreads();
        for (int i = tid; i < 64 * 8; i += 256) {   // K tokens: straight fp16 copy
            int nn = i >> 3, gq = i & 7;
            uint4 u = *(const uint4*)&qkv[((size_t)b * NTOK + n0 + nn) * QKVD + 512 + h * 64 + gq * 8];
            *(uint4*)(smc + 8192 + nn * 128 + ((gq ^ (nn & 7)) << 4)) = u;
        }
        __syncthreads();
        if (wid < 7) {
            float acc[4][4];
#pragma unroll
            for (int mt = 0; mt < 4; mt++)
#pragma unroll
                for (int j = 0; j < 4; j++) acc[mt][j] = 0.f;
#pragma unroll
            for (int ks = 0; ks < 4; ks++) {
                uint32_t bF[4];
                {
                    int c4 = (2 * ks) | c4bB;
                    LDSM_X4(bF, smBase + (uint32_t)(rB * 128 + ((c4 ^ (rB & 7)) << 4)));
                }
#pragma unroll
                for (int mt = 0; mt < 4; mt++) {
                    uint32_t aF[4];
                    int row = mt * 16 + rA;
                    int c4 = (2 * ks) | c4bA;
                    LDSM_X4(aF, smBase + (uint32_t)(8192 + row * 128 + ((c4 ^ (row & 7)) << 4)));
                    mma_16x8x16h(acc[mt], aF, &bF[sub * 2]);
                }
            }
#pragma unroll
            for (int mt = 0; mt < 4; mt++)
#pragma unroll
                for (int j = 0; j < 4; j++) {
                    int a = wid * 8 + 2 * tg + (j & 1);
                    if (a < 49) {
                        int nloc = c * 64 + mt * 16 + g + ((j >> 1) << 3);
                        L[a * AF_LSTR + nloc] =
                            acc[mt][j] + pb[((size_t)h * AGENT + a) * NTOK + n0base + nloc];
                    }
                }
        }
    }
    __syncthreads();

    // ---- Phase 2: per-a max & sum; L <- exp(L - m) ----
    {
        for (int a = wid; a < AGENT; a += 8) {
            float m = -1e30f;
            for (int j = lane; j < NSPL; j += 32) m = fmaxf(m, L[a * AF_LSTR + j]);
#pragma unroll
            for (int o = 16; o > 0; o >>= 1) m = fmaxf(m, __shfl_xor_sync(0xffffffffu, m, o));
            float sum = 0.f;
            for (int j = lane; j < NSPL; j += 32) {
                float e = __expf(L[a * AF_LSTR + j] - m);
                L[a * AF_LSTR + j] = e;
                sum += e;
            }
#pragma unroll
            for (int o = 16; o > 0; o >>= 1) sum += __shfl_xor_sync(0xffffffffu, sum, o);
            if (lane == 0) { sm_m[a] = m; sm_s[a] = sum; }
        }
    }

    // ---- Phase 3 (fp16 mma): D[a][d] = sum_chunks P_chunk @ Vt_chunk ----
    // PH [64a][64n] at smc+0 (reuses AHs), Vt [64d][64n] at smc+8192 (reuses Ks).
    const int mT = wid & 3;              // agent 16-tile
    const int dH = wid >> 2;             // d 32-half
    const int rA3 = mT * 16 + ((mA & 1) << 3) + (lane & 7);
    const int rB3 = dH * 32 + ((lane >> 4) << 3) + (lane & 7);
    float dacc[4][4];
#pragma unroll
    for (int nt = 0; nt < 4; nt++)
#pragma unroll
        for (int j = 0; j < 4; j++) dacc[nt][j] = 0.f;

    for (int c = 0; c < 7; c++) {
        int n0 = n0base + c * 64;
        __syncthreads();
        // stage PH: L fp32 -> fp16, agents >= 49 zero
        for (int i = tid; i < 64 * 8; i += 256) {
            int a = i >> 3, gq = i & 7;
            uint4 u = {0u, 0u, 0u, 0u};
            if (a < 49) {
                const float* lp = &L[a * AF_LSTR + c * 64 + gq * 8];
                float4 v0 = *(const float4*)lp;
                float4 v1 = *(const float4*)(lp + 4);
                u.x = pack_h2(v0.x, v0.y); u.y = pack_h2(v0.z, v0.w);
                u.z = pack_h2(v1.x, v1.y); u.w = pack_h2(v1.z, v1.w);
            }
            *(uint4*)(smc + a * 128 + ((gq ^ (a & 7)) << 4)) = u;
        }
        // stage Vt transposed from qkv v: [64d][64n]
        for (int i = tid; i < 64 * 8; i += 256) {
            int nn = i >> 3, dg = i & 7;
            uint4 u = *(const uint4*)&qkv[((size_t)b * NTOK + n0 + nn) * QKVD + 1024 + h * 64 + dg * 8];
            const __half* hp = (const __half*)&u;
            int gq2 = nn >> 3, byt = (nn & 7) * 2;
#pragma unroll
            for (int j = 0; j < 8; j++) {
                int d = dg * 8 + j;
                *(__half*)(smc + 8192 + d * 128 + ((gq2 ^ (d & 7)) << 4) + byt) = hp[j];
            }
        }
        __syncthreads();
#pragma unroll
        for (int ks = 0; ks < 4; ks++) {
            uint32_t aF[4], bF[2][4];
            {
                int c4 = (2 * ks) | c4bA;
                LDSM_X4(aF, smBase + (uint32_t)(rA3 * 128 + ((c4 ^ (rA3 & 7)) << 4)));
            }
#pragma unroll
            for (int p = 0; p < 2; p++) {
                int row = rB3 + p * 16;
                int c4 = (2 * ks) | c4bB;
                LDSM_X4(bF[p], smBase + (uint32_t)(8192 + row * 128 + ((c4 ^ (row & 7)) << 4)));
            }
#pragma unroll
            for (int p = 0; p < 2; p++) {
                mma_16x8x16h(dacc[2 * p],     aF, &bF[p][0]);
                mma_16x8x16h(dacc[2 * p + 1], aF, &bF[p][2]);
            }
        }
    }

    // ---- write partials ----
    float* pacc = part;
    float* pms  = part + (size_t)SPLITS * 128 * AGENT * HDIM;
    {
        int a0 = mT * 16 + g;
#pragma unroll
        for (int nt = 0; nt < 4; nt++) {
            int d0 = dH * 32 + nt * 8 + 2 * tg;
            if (a0 < 49) {
                float2 v = { dacc[nt][0], dacc[nt][1] };
                *(float2*)&pacc[(((size_t)s * 128 + bh) * AGENT + a0) * HDIM + d0] = v;
            }
            if (a0 + 8 < 49) {
                float2 v = { dacc[nt][2], dacc[nt][3] };
                *(float2*)&pacc[(((size_t)s * 128 + bh) * AGENT + a0 + 8) * HDIM + d0] = v;
            }
        }
    }
    if (tid < AGENT) {
        pms[(((size_t)s * 128 + bh) * AGENT + tid) * 2 + 0] = sm_m[tid];
        pms[(((size_t)s * 128 + bh) * AGENT + tid) * 2 + 1] = sm_s[tid];
    }
}

// ---- combine splits ----
__global__ __launch_bounds__(256) void agent_combine_kernel(
    const float* __restrict__ part, float* __restrict__ av)
{
    const int bh = blockIdx.x;
    const int tid = threadIdx.x;
    const int d = tid & 63, abase = tid >> 6;
    const float* pacc = part;
    const float* pms  = part + (size_t)SPLITS * 128 * AGENT * HDIM;

    int a = abase;
#pragma unroll
    for (int i = 0; i < 13; i++) {
        if (a < 49) {
            float mstar = -1e30f;
            float ms[SPLITS], ss[SPLITS];
#pragma unroll
            for (int s = 0; s < SPLITS; s++) {
                ms[s] = pms[(((size_t)s * 128 + bh) * AGENT + a) * 2 + 0];
                ss[s] = pms[(((size_t)s * 128 + bh) * AGENT + a) * 2 + 1];
                mstar = fmaxf(mstar, ms[s]);
            }
            float S = 0.f, o = 0.f;
#pragma unroll
            for (int s = 0; s < SPLITS; s++) {
                float f = __expf(ms[s] - mstar);
                S += ss[s] * f;
                o += pacc[(((size_t)s * 128 + bh) * AGENT + a) * HDIM + d] * f;
            }
            av[((size_t)bh * AGENT + a) * HDIM + d] = o / S;
        }
        a += 4;
    }
}

// ======= q attention via fp16 tensor cores; writes fp16 into oh =======
#define QA_SMEM 52672

__global__ void __launch_bounds__(224, 2) qattn_mma(
    const __half* __restrict__ qkv, const float* __restrict__ ag,
    const float* __restrict__ av, const float* __restrict__ ab, __half* __restrict__ oh)
{
    extern __shared__ char sqc[];
    const int bh = blockIdx.y, b = bh >> 3, h = bh & 7;
    const int n0 = blockIdx.x * 112;
    const int tid = threadIdx.x, wid = tid >> 5, lane = tid & 31;
    const int g = lane >> 2, tg = lane & 3;
    const uint32_t smBase = smem_u32(sqc);
    float* ABs = (float*)(sqc + 30720);

    for (int i = tid; i < 112 * 8; i += 224) {
        int r = i >> 3, gq = i & 7;
        uint4 u = *(const uint4*)&qkv[((size_t)b * NTOK + n0 + r) * QKVD + h * 64 + gq * 8];
        *(uint4*)(sqc + r * 128 + ((gq ^ (r & 7)) << 4)) = u;
    }
    for (int i = tid; i < 64 * 8; i += 224) {
        int a = i >> 3, gq = i & 7;
        uint4 u = {0u, 0u, 0u, 0u};
        if (a < 49) {
            const float* src = &ag[((size_t)b * AGENT + a) * CDIM + h * 64 + gq * 8];
            float4 v0 = *(const float4*)src;
            float4 v1 = *(const float4*)(src + 4);
            u.x = pack_h2(v0.x * 0.125f, v0.y * 0.125f);
            u.y = pack_h2(v0.z * 0.125f, v0.w * 0.125f);
            u.z = pack_h2(v1.x * 0.125f, v1.y * 0.125f);
            u.w = pack_h2(v1.z * 0.125f, v1.w * 0.125f);
        }
        *(uint4*)(sqc + 14336 + a * 128 + ((gq ^ (a & 7)) << 4)) = u;
    }
    for (int i = tid; i < 64 * 8; i += 224) {
        int d = i >> 3, gq = i & 7;
        uint32_t uu[4];
#pragma unroll
        for (int j = 0; j < 4; j++) {
            int a0 = gq * 8 + 2 * j, a1 = a0 + 1;
            float f0 = (a0 < 49) ? av[((size_t)bh * AGENT + a0) * HDIM + d] : 0.f;
            float f1 = (a1 < 49) ? av[((size_t)bh * AGENT + a1) * HDIM + d] : 0.f;
            uu[j] = pack_h2(f0, f1);
        }
        uint4 u = { uu[0], uu[1], uu[2], uu[3] };
        *(uint4*)(sqc + 22528 + d * 128 + ((gq ^ (d & 7)) << 4)) = u;
    }
    {
        const float4* src = (const float4*)(ab + ((size_t)h * NTOK + n0) * 49);
        for (int i = tid; i < 112 * 49 / 4; i += 224) ((float4*)ABs)[i] = src[i];
    }
    __syncthreads();

    const int wm = wid * 16;
    const int mA = lane >> 3;
    const int rA = wm + ((mA & 1) << 3) + (lane & 7);
    const int c4bA = mA >> 1;
    const int rB = ((lane >> 4) << 3) + (lane & 7);
    const int c4bB = (lane >> 3) & 1;

    float acc[7][4];
#pragma unroll
    for (int nt = 0; nt < 7; nt++)
#pragma unroll
        for (int j = 0; j < 4; j++) acc[nt][j] = 0.f;

#pragma unroll
    for (int ks = 0; ks < 4; ks++) {
        uint32_t aF[4], bF[4][4];
        {
            int c4 = (2 * ks) | c4bA;
            LDSM_X4(aF, smBase + (uint32_t)(rA * 128 + ((c4 ^ (rA & 7)) << 4)));
        }
        int c4b = (2 * ks) | c4bB;
#pragma unroll
        for (int p = 0; p < 4; p++) {
            int row = p * 16 + rB;
            LDSM_X4(bF[p], smBase + (uint32_t)(14336 + row * 128 + ((c4b ^ (row & 7)) << 4)));
        }
#pragma unroll
        for (int nt = 0; nt < 7; nt++)
            mma_16x8x16h(acc[nt], aF, &bF[nt >> 1][(nt & 1) * 2]);
    }

    const int rl0 = wm + g;
    float m0 = -1e30f, m8 = -1e30f;
    float vals[7][4];
#pragma unroll
    for (int nt = 0; nt < 7; nt++) {
        int c0 = nt * 8 + 2 * tg, c1 = c0 + 1;
        float v0 = (c0 < 49) ? acc[nt][0] + ABs[rl0 * 49 + c0]       : -1e30f;
        float v1 = (c1 < 49) ? acc[nt][1] + ABs[rl0 * 49 + c1]       : -1e30f;
        float v2 = (c0 < 49) ? acc[nt][2] + ABs[(rl0 + 8) * 49 + c0] : -1e30f;
        float v3 = (c1 < 49) ? acc[nt][3] + ABs[(rl0 + 8) * 49 + c1] : -1e30f;
        vals[nt][0] = v0; vals[nt][1] = v1; vals[nt][2] = v2; vals[nt][3] = v3;
        m0 = fmaxf(m0, fmaxf(v0, v1));
        m8 = fmaxf(m8, fmaxf(v2, v3));
    }
    m0 = fmaxf(m0, __shfl_xor_sync(0xffffffffu, m0, 1));
    m0 = fmaxf(m0, __shfl_xor_sync(0xffffffffu, m0, 2));
    m8 = fmaxf(m8, __shfl_xor_sync(0xffffffffu, m8, 1));
    m8 = fmaxf(m8, __shfl_xor_sync(0xffffffffu, m8, 2));
    float s0 = 0.f, s8 = 0.f;
#pragma unroll
    for (int nt = 0; nt < 7; nt++) {
        int c0 = nt * 8 + 2 * tg, c1 = c0 + 1;
        float e0 = (c0 < 49) ? __expf(vals[nt][0] - m0) : 0.f;
        float e1 = (c1 < 49) ? __expf(vals[nt][1] - m0) : 0.f;
        float e2 = (c0 < 49) ? __expf(vals[nt][2] - m8) : 0.f;
        float e3 = (c1 < 49) ? __expf(vals[nt][3] - m8) : 0.f;
        vals[nt][0] = e0; vals[nt][1] = e1; vals[nt][2] = e2; vals[nt][3] = e3;
        s0 += e0 + e1; s8 += e2 + e3;
    }
    s0 += __shfl_xor_sync(0xffffffffu, s0, 1);
    s0 += __shfl_xor_sync(0xffffffffu, s0, 2);
    s8 += __shfl_xor_sync(0xffffffffu, s8, 1);
    s8 += __shfl_xor_sync(0xffffffffu, s8, 2);
    const float i0 = 1.0f / s0, i8 = 1.0f / s8;

#pragma unroll
    for (int nt = 0; nt < 7; nt++) {
        int c0 = nt * 8 + 2 * tg;
        int gq = c0 >> 3, byt = (c0 & 7) * 2;
        uint32_t o0 = rl0 * 128 + ((gq ^ (rl0 & 7)) << 4) + byt;
        uint32_t o8 = (rl0 + 8) * 128 + ((gq ^ ((rl0 + 8) & 7)) << 4) + byt;
        *(uint32_t*)(sqc + o0) = pack_h2(vals[nt][0] * i0, vals[nt][1] * i0);
        *(uint32_t*)(sqc + o8) = pack_h2(vals[nt][2] * i8, vals[nt][3] * i8);
    }
    __syncwarp();

    float ao[8][4];
#pragma unroll
    for (int nt = 0; nt < 8; nt++)
#pragma unroll
        for (int j = 0; j < 4; j++) ao[nt][j] = 0.f;

#pragma unroll
    for (int ks = 0; ks < 4; ks++) {
        uint32_t aF[4], bF[4][4];
        {
            int c4 = (2 * ks) | c4bA;
            LDSM_X4(aF, smBase + (uint32_t)(rA * 128 + ((c4 ^ (rA & 7)) << 4)));
        }
        int c4b = (2 * ks) | c4bB;
#pragma unroll
        for (int p = 0; p < 4; p++) {
            int row = p * 16 + rB;
            LDSM_X4(bF[p], smBase + (uint32_t)(22528 + row * 128 + ((c4b ^ (row & 7)) << 4)));
        }
#pragma unroll
        for (int nt = 0; nt < 8; nt++)
            mma_16x8x16h(ao[nt], aF, &bF[nt >> 1][(nt & 1) * 2]);
    }

    const size_t row0 = (size_t)b * NTOK + n0 + rl0;
#pragma unroll
    for (int nt = 0; nt < 8; nt++) {
        int col = nt * 8 + 2 * tg;
        *(uint32_t*)&oh[row0 * 512 + h * 64 + col] = pack_h2(ao[nt][0], ao[nt][1]);
        *(uint32_t*)&oh[(row0 + 8) * 512 + h * 64 + col] = pack_h2(ao[nt][2], ao[nt][3]);
    }
}

// ------- depthwise 3x3 conv on fp16 v; oh += conv + bias (in place) -------
__global__ __launch_bounds__(512) void dwc_kernel(
    const __half* __restrict__ qkv, const float* __restrict__ w,
    const float* __restrict__ bias, __half* __restrict__ oh)
{
    int c = threadIdx.x;
    int n = blockIdx.x;
    int b = blockIdx.y;
    int y = n / WW, x = n % WW;
    float acc = bias[c];
#pragma unroll
    for (int dy = -1; dy <= 1; dy++) {
        int yy = y + dy; if (yy < 0 || yy >= HH) continue;
#pragma unroll
        for (int dx = -1; dx <= 1; dx++) {
            int xx = x + dx; if (xx < 0 || xx >= WW) continue;
            acc += __half2float(qkv[((size_t)b * NTOK + yy * WW + xx) * QKVD + 1024 + c]) *
                   w[c * 9 + (dy + 1) * 3 + (dx + 1)];
        }
    }
    size_t idx = ((size_t)b * NTOK + n) * CDIM + c;
    oh[idx] = __float2half_rn(__half2float(oh[idx]) + acc);
}

// ---------------- launch ----------------
extern "C" void kernel_launch(void* const* d_in, const int* in_sizes, int n_in,
                              void* d_out, int out_size)
{
    const float* x      = (const float*)d_in[0];
    const float* q_w    = (const float*)d_in[3];
    const float* kv_w   = (const float*)d_in[4];
    const float* proj_w = (const float*)d_in[5];
    const float* proj_b = (const float*)d_in[6];
    const float* dwc_w  = (const float*)d_in[7];
    const float* dwc_b  = (const float*)d_in[8];
    const float* an_b   = (const float*)d_in[9];
    const float* na_b   = (const float*)d_in[10];
    const float* ah_b   = (const float*)d_in[11];
    const float* aw_b   = (const float*)d_in[12];
    const float* ha_b   = (const float*)d_in[13];
    const float* wa_b   = (const float*)d_in[14];
    float* out = (float*)d_out;

    float *prt, *agp, *avp, *pbp, *abp;
    __half *qkvh, *xh, *oh, *wh;
    cudaGetSymbolAddress((void**)&qkvh, g_qkv);
    cudaGetSymbolAddress((void**)&xh,  g_xh);
    cudaGetSymbolAddress((void**)&oh,  g_oh);
    cudaGetSymbolAddress((void**)&wh,  g_wh);
    cudaGetSymbolAddress((void**)&prt, g_part);
    cudaGetSymbolAddress((void**)&agp, g_agent);
    cudaGetSymbolAddress((void**)&avp, g_agentv);
    cudaGetSymbolAddress((void**)&pbp, g_pb);
    cudaGetSymbolAddress((void**)&abp, g_ab);

    cudaFuncSetAttribute(mma_gemm, cudaFuncAttributeMaxDynamicSharedMemorySize, GEMM_SMEM);
    cudaFuncSetAttribute(agent_fused_kernel, cudaFuncAttributeMaxDynamicSharedMemorySize, AF_SMEM);
    cudaFuncSetAttribute(qattn_mma, cudaFuncAttributeMaxDynamicSharedMemorySize, QA_SMEM);

    // pre-convert x and weights to fp16
    {
        int n4 = MALL * CDIM / 4;
        f16_conv_kernel<<<(n4 + 255) / 256, 256>>>(x, xh, n4);
        int w4 = CDIM * CDIM / 4;
        f16_conv_kernel<<<(w4 + 255) / 256, 256>>>(q_w, wh, w4);
        f16_conv_kernel<<<(2 * w4 + 255) / 256, 256>>>(kv_w, wh + CDIM * CDIM, 2 * w4);
        f16_conv_kernel<<<(w4 + 255) / 256, 256>>>(proj_w, wh + 3 * CDIM * CDIM, w4);
    }

    // merged q|k|v projection: N = 1536, fp16 output
    mma_gemm<<<dim3(QKVD / 128, MALL / 128), 256, GEMM_SMEM>>>(xh, wh, nullptr, qkvh, nullptr, QKVD);

    pool_kernel<<<BATCH * AGENT, CDIM>>>(qkvh, agp);
    bias_kernel<<<HEADS * AGENT, 256>>>(an_b, na_b, ah_b, aw_b, ha_b, wa_b, pbp, abp);

    agent_fused_kernel<<<dim3(SPLITS, BATCH * HEADS), 256, AF_SMEM>>>(agp, qkvh, pbp, prt);
    agent_combine_kernel<<<BATCH * HEADS, 256>>>(prt, avp);

    qattn_mma<<<dim3(28, BATCH * HEADS), 224, QA_SMEM>>>(qkvh, agp, avp, abp, oh);
    dwc_kernel<<<dim3(NTOK, BATCH), CDIM>>>(qkvh, dwc_w, dwc_b, oh);

    // final projection: fp32 output + bias
    mma_gemm<<<dim3(CDIM / 128, MALL / 128), 256, GEMM_SMEM>>>(oh, wh + 3 * CDIM * CDIM, out, nullptr, proj_b, CDIM);
}

// round 17
// speedup vs baseline: 4.9613x; 1.0765x over previous
#include <cuda_runtime.h>
#include <cuda_bf16.h>
#include <cuda_fp16.h>
#include <cstdint>

// ---------------- problem constants ----------------
#define BATCH 16
#define CDIM  512
#define HH    56
#define WW    56
#define NTOK  3136          // 56*56
#define HEADS 8
#define HDIM  64
#define AGENT 49
#define MALL  (BATCH*NTOK)  // 50176
#define SPLITS 7
#define NSPL  448           // NTOK / SPLITS
#define QKVD  1536          // merged qkv row stride

// ---------------- scratch (static device memory; no allocation) ----------------
__device__ __half g_qkv[(size_t)MALL*QKVD];   // q | k | v per row (fp16)
__device__ __half g_xh[(size_t)MALL*CDIM];    // x pre-converted to fp16
__device__ __half g_oh[(size_t)MALL*CDIM];    // attention out -> (+dwc) proj input, fp16
__device__ __half g_wh[4*CDIM*CDIM];          // q_w | k_w | v_w | proj_w, fp16
__device__ float  g_part[SPLITS*BATCH*HEADS*AGENT*(HDIM+2) + 1024];
__device__ float  g_agent[BATCH*AGENT*CDIM];
__device__ float  g_agentv[BATCH*HEADS*AGENT*HDIM];
__device__ float  g_pb[HEADS*AGENT*NTOK];
__device__ float  g_ab[HEADS*NTOK*AGENT];

// ================= helpers =================
__device__ __forceinline__ uint32_t pack_h2(float lo, float hi) {
    uint32_t u;
    asm("cvt.rn.f16x2.f32 %0, %1, %2;" : "=r"(u) : "f"(hi), "f"(lo));
    return u;
}
__device__ __forceinline__ uint32_t smem_u32(const void* p) {
    uint32_t a;
    asm("{ .reg .u64 t; cvta.to.shared.u64 t, %1; cvt.u32.u64 %0, t; }" : "=r"(a) : "l"(p));
    return a;
}
__device__ __forceinline__ void mma_16x8x16h(float* d, const uint32_t* a, const uint32_t* b) {
    asm volatile(
        "mma.sync.aligned.m16n8k16.row.col.f32.f16.f16.f32 "
        "{%0,%1,%2,%3}, {%4,%5,%6,%7}, {%8,%9}, {%0,%1,%2,%3};"
        : "+f"(d[0]), "+f"(d[1]), "+f"(d[2]), "+f"(d[3])
        : "r"(a[0]), "r"(a[1]), "r"(a[2]), "r"(a[3]), "r"(b[0]), "r"(b[1]));
}
#define LDSM_X4(r, addr) \
    asm volatile("ldmatrix.sync.aligned.m8n8.x4.shared.b16 {%0,%1,%2,%3}, [%4];" \
        : "=r"((r)[0]), "=r"((r)[1]), "=r"((r)[2]), "=r"((r)[3]) : "r"(addr))
#define CP_ASYNC16(dst, src) \
    asm volatile("cp.async.cg.shared.global [%0], [%1], 16;" :: "r"(dst), "l"(src))

// ---------------- fp16 pre-conversion: x ----------------
__global__ __launch_bounds__(256) void f16_conv_kernel(
    const float* __restrict__ in, __half* __restrict__ out, int n4)
{
    int i = blockIdx.x * 256 + threadIdx.x;
    if (i < n4) {
        float4 v = ((const float4*)in)[i];
        uint2 u;
        u.x = pack_h2(v.x, v.y);
        u.y = pack_h2(v.z, v.w);
        ((uint2*)out)[i] = u;
    }
}

// ---------------- fp16 pre-conversion: all weights in ONE launch ----------------
// segments: [0, 64K4) q_w | [64K4, 192K4) kv_w | [192K4, 256K4) proj_w   (units of float4)
__global__ __launch_bounds__(256) void f16_conv_w_kernel(
    const float* __restrict__ q_w, const float* __restrict__ kv_w,
    const float* __restrict__ proj_w, __half* __restrict__ out)
{
    const int W4 = CDIM * CDIM / 4;       // 65536
    int i = blockIdx.x * 256 + threadIdx.x;
    if (i >= 4 * W4) return;
    const float* src;
    int off;
    if (i < W4)            { src = q_w;    off = i; }
    else if (i < 3 * W4)   { src = kv_w;   off = i - W4; }
    else                   { src = proj_w; off = i - 3 * W4; }
    float4 v = ((const float4*)src)[off];
    uint2 u;
    u.x = pack_h2(v.x, v.y);
    u.y = pack_h2(v.z, v.w);
    ((uint2*)out)[i] = u;
}

// ======= fp16 tensor-core GEMM: C[m,n] = sum_k A[m,k]*W[n,k] =======
#define GSTG 3
#define STG_BYTES 32768
#define GEMM_SMEM (GSTG*STG_BYTES)     // 98304 bytes

__global__ void __launch_bounds__(256, 2) mma_gemm(
    const __half* __restrict__ A, const __half* __restrict__ W,
    float* __restrict__ C, __half* __restrict__ Ch,
    const float* __restrict__ bias, int ldc)
{
    extern __shared__ float sm[];
    const int tid = threadIdx.x;
    const int wid = tid >> 5, lane = tid & 31;
    const int wm = (wid >> 2) * 64;
    const int wn = (wid & 3) * 32;
    const int g = lane >> 2, tg = lane & 3;
    const int bm = blockIdx.y * 128, bn = blockIdx.x * 128;
    const uint32_t smBase = smem_u32(sm);

    const __half* aSrc[4];
    const __half* wSrc[4];
    uint32_t dOff[4];
#pragma unroll
    for (int i = 0; i < 4; i++) {
        int id = i * 256 + tid;
        int r = id >> 3, c4 = id & 7;
        aSrc[i] = A + (size_t)(bm + r) * 512 + c4 * 8;
        wSrc[i] = W + (size_t)(bn + r) * 512 + c4 * 8;
        dOff[i] = (uint32_t)(r * 128 + ((c4 ^ (r & 7)) << 4));
    }

    const int mA = lane >> 3;
    const int rowA_base = wm + ((mA & 1) << 3) + (lane & 7);
    const int c4bA = mA >> 1;
    const int rowB_base = wn + ((lane >> 4) << 3) + (lane & 7);
    const int c4bB = (lane >> 3) & 1;

    float acc[4][4][4];
#pragma unroll
    for (int mi = 0; mi < 4; mi++)
#pragma unroll
        for (int ni = 0; ni < 4; ni++)
#pragma unroll
            for (int j = 0; j < 4; j++) acc[mi][ni][j] = 0.f;

#pragma unroll
    for (int kc = 0; kc < 2; kc++) {
        uint32_t sA = smBase + (uint32_t)(kc % GSTG) * STG_BYTES;
        uint32_t sB = sA + 16384;
        int koff = kc * 64;
#pragma unroll
        for (int i = 0; i < 4; i++) {
            CP_ASYNC16(sA + dOff[i], aSrc[i] + koff);
            CP_ASYNC16(sB + dOff[i], wSrc[i] + koff);
        }
        asm volatile("cp.async.commit_group;");
    }

    for (int kc = 0; kc < 8; kc++) {
        if (kc < 7) asm volatile("cp.async.wait_group 1;");
        else        asm volatile("cp.async.wait_group 0;");
        __syncthreads();
        if (kc + 2 < 8) {
            uint32_t sA = smBase + (uint32_t)((kc + 2) % GSTG) * STG_BYTES;
            uint32_t sB = sA + 16384;
            int koff = (kc + 2) * 64;
#pragma unroll
            for (int i = 0; i < 4; i++) {
                CP_ASYNC16(sA + dOff[i], aSrc[i] + koff);
                CP_ASYNC16(sB + dOff[i], wSrc[i] + koff);
            }
            asm volatile("cp.async.commit_group;");
        }
        const uint32_t sA = smBase + (uint32_t)(kc % GSTG) * STG_BYTES;
        const uint32_t sB = sA + 16384;
#pragma unroll
        for (int ks = 0; ks < 4; ks++) {
            uint32_t aF[4][4], bF[2][4];
#pragma unroll
            for (int mi = 0; mi < 4; mi++) {
                int row = rowA_base + mi * 16;
                int c4 = (2 * ks) | c4bA;
                LDSM_X4(aF[mi], sA + (uint32_t)(row * 128 + ((c4 ^ (row & 7)) << 4)));
            }
#pragma unroll
            for (int p = 0; p < 2; p++) {
                int row = rowB_base + p * 16;
                int c4 = (2 * ks) | c4bB;
                LDSM_X4(bF[p], sB + (uint32_t)(row * 128 + ((c4 ^ (row & 7)) << 4)));
            }
#pragma unroll
            for (int mi = 0; mi < 4; mi++)
#pragma unroll
                for (int p = 0; p < 2; p++) {
                    mma_16x8x16h(acc[mi][2 * p],     aF[mi], &bF[p][0]);
                    mma_16x8x16h(acc[mi][2 * p + 1], aF[mi], &bF[p][2]);
                }
        }
    }

#pragma unroll
    for (int mi = 0; mi < 4; mi++) {
        int row = bm + wm + mi * 16 + g;
#pragma unroll
        for (int ni = 0; ni < 4; ni++) {
            int col = bn + wn + ni * 8 + 2 * tg;
            if (Ch) {
                *(uint32_t*)&Ch[(size_t)row * ldc + col] = pack_h2(acc[mi][ni][0], acc[mi][ni][1]);
                *(uint32_t*)&Ch[(size_t)(row + 8) * ldc + col] = pack_h2(acc[mi][ni][2], acc[mi][ni][3]);
            } else {
                float b0 = 0.f, b1 = 0.f;
                if (bias) { b0 = bias[col]; b1 = bias[col + 1]; }
                float2 v0 = { acc[mi][ni][0] + b0, acc[mi][ni][1] + b1 };
                float2 v1 = { acc[mi][ni][2] + b0, acc[mi][ni][3] + b1 };
                *(float2*)&C[(size_t)row * ldc + col] = v0;
                *(float2*)&C[(size_t)(row + 8) * ldc + col] = v1;
            }
        }
    }
}

// ---------------- agent token pooling (q part of fp16 qkv) ----------------
__global__ __launch_bounds__(512) void pool_kernel(const __half* __restrict__ qkv,
                                                   float* __restrict__ ag)
{
    int c = threadIdx.x;
    int b = blockIdx.x / AGENT;
    int a = blockIdx.x % AGENT;
    int p1 = a / 7, p2 = a % 7;
    float s = 0.f;
#pragma unroll
    for (int i = 0; i < 8; i++)
#pragma unroll
        for (int j = 0; j < 8; j++)
            s += __half2float(qkv[((size_t)b * NTOK + (p1 * 8 + i) * WW + (p2 * 8 + j)) * QKVD + c]);
    ag[((size_t)b * AGENT + a) * CDIM + c] = s * (1.0f / 64.0f);
}

// ---------------- bias precompute ----------------
__global__ __launch_bounds__(256) void bias_kernel(
    const float* __restrict__ an, const float* __restrict__ na,
    const float* __restrict__ ahb, const float* __restrict__ awb,
    const float* __restrict__ hab, const float* __restrict__ wab,
    float* __restrict__ pb, float* __restrict__ ab)
{
    int h = blockIdx.x / AGENT;
    int a = blockIdx.x % AGENT;
    __shared__ float ans[49], nas[49];
    int tid = threadIdx.x;
    if (tid < 49) {
        ans[tid] = an[((size_t)h * AGENT + a) * 49 + tid];
        nas[tid] = na[((size_t)h * AGENT + a) * 49 + tid];
    }
    __syncthreads();
    for (int n = tid; n < NTOK; n += 256) {
        int y = n / WW, x = n % WW;
        float fy = (y + 0.5f) * 0.125f - 0.5f;
        float fx = (x + 0.5f) * 0.125f - 0.5f;
        int iy = (int)floorf(fy); float ty = fy - iy;
        int ix = (int)floorf(fx); float tx = fx - ix;
        float wy0 = 1.f - ty, wy1 = ty;
        int y0 = iy, y1 = iy + 1;
        if (y0 < 0) { wy0 = 0.f; y0 = 0; }
        if (y1 > 6) { wy1 = 0.f; y1 = 6; }
        float sy = wy0 + wy1; wy0 /= sy; wy1 /= sy;
        float wx0 = 1.f - tx, wx1 = tx;
        int x0 = ix, x1 = ix + 1;
        if (x0 < 0) { wx0 = 0.f; x0 = 0; }
        if (x1 > 6) { wx1 = 0.f; x1 = 6; }
        float sx = wx0 + wx1; wx0 /= sx; wx1 /= sx;

        float bi_an = wy0 * (wx0 * ans[y0 * 7 + x0] + wx1 * ans[y0 * 7 + x1]) +
                      wy1 * (wx0 * ans[y1 * 7 + x0] + wx1 * ans[y1 * 7 + x1]);
        float bi_na = wy0 * (wx0 * nas[y0 * 7 + x0] + wx1 * nas[y0 * 7 + x1]) +
                      wy1 * (wx0 * nas[y1 * 7 + x0] + wx1 * nas[y1 * 7 + x1]);

        pb[((size_t)h * AGENT + a) * NTOK + n] =
            bi_an + ahb[((size_t)h * AGENT + a) * 56 + y] + awb[((size_t)h * AGENT + a) * 56 + x];
        ab[((size_t)h * NTOK + n) * AGENT + a] =
            bi_na + hab[((size_t)h * 56 + y) * AGENT + a] + wab[((size_t)h * 56 + x) * AGENT + a];
    }
}

// ============ fused agent attention: fp16 mma logits + softmax + fp16 mma attn@V ============
#define AF_LBYTE 16896
#define AF_LSTR 452
#define AF_SMEM (AF_LBYTE + AGENT*AF_LSTR*4)   // 105488 bytes

__global__ __launch_bounds__(256) void agent_fused_kernel(
    const float* __restrict__ ag, const __half* __restrict__ qkv,
    const float* __restrict__ pb, float* __restrict__ part)
{
    extern __shared__ char smc[];
    float* L = (float*)(smc + AF_LBYTE);
    __shared__ float sm_m[AGENT], sm_s[AGENT];

    const int s  = blockIdx.x;
    const int bh = blockIdx.y;
    const int b = bh >> 3, h = bh & 7;
    const int tid = threadIdx.x;
    const int wid = tid >> 5, lane = tid & 31;
    const int g = lane >> 2, tg = lane & 3;
    const int mA = lane >> 3;
    const int n0base = s * NSPL;
    const uint32_t smBase = smem_u32(smc);

    for (int i = tid; i < 64 * 8; i += 256) {
        int a = i >> 3, gq = i & 7;
        uint4 u = {0u, 0u, 0u, 0u};
        if (a < 49) {
            const float* src = &ag[((size_t)b * AGENT + a) * CDIM + h * 64 + gq * 8];
            float4 v0 = *(const float4*)src;
            float4 v1 = *(const float4*)(src + 4);
            u.x = pack_h2(v0.x * 0.125f, v0.y * 0.125f);
            u.y = pack_h2(v0.z * 0.125f, v0.w * 0.125f);
            u.z = pack_h2(v1.x * 0.125f, v1.y * 0.125f);
            u.w = pack_h2(v1.z * 0.125f, v1.w * 0.125f);
        }
        *(uint4*)(smc + a * 128 + ((gq ^ (a & 7)) << 4)) = u;
    }

    const int rA = ((mA & 1) << 3) + (lane & 7);
    const int c4bA = mA >> 1;
    const int rB = ((wid >> 1) * 16) + ((lane >> 4) << 3) + (lane & 7);
    const int c4bB = (lane >> 3) & 1;
    const int sub = wid & 1;

    for (int c = 0; c < 7; c++) {
        int n0 = n0base + c * 64;
        __syncthreads();
        for (int i = tid; i < 64 * 8; i += 256) {
            int nn = i >> 3, gq = i & 7;
            uint4 u = *(const uint4*)&qkv[((size_t)b * NTOK + n0 + nn) * QKVD + 512 + h * 64 + gq * 8];
            *(uint4*)(smc + 8192 + nn * 128 + ((gq ^ (nn & 7)) << 4)) = u;
        }
        __syncthreads();
        if (wid < 7) {
            float acc[4][4];
#pragma unroll
            for (int mt = 0; mt < 4; mt++)
#pragma unroll
                for (int j = 0; j < 4; j++) acc[mt][j] = 0.f;
#pragma unroll
            for (int ks = 0; ks < 4; ks++) {
                uint32_t bF[4];
                {
                    int c4 = (2 * ks) | c4bB;
                    LDSM_X4(bF, smBase + (uint32_t)(rB * 128 + ((c4 ^ (rB & 7)) << 4)));
                }
#pragma unroll
                for (int mt = 0; mt < 4; mt++) {
                    uint32_t aF[4];
                    int row = mt * 16 + rA;
                    int c4 = (2 * ks) | c4bA;
                    LDSM_X4(aF, smBase + (uint32_t)(8192 + row * 128 + ((c4 ^ (row & 7)) << 4)));
                    mma_16x8x16h(acc[mt], aF, &bF[sub * 2]);
                }
            }
#pragma unroll
            for (int mt = 0; mt < 4; mt++)
#pragma unroll
                for (int j = 0; j < 4; j++) {
                    int a = wid * 8 + 2 * tg + (j & 1);
                    if (a < 49) {
                        int nloc = c * 64 + mt * 16 + g + ((j >> 1) << 3);
                        L[a * AF_LSTR + nloc] =
                            acc[mt][j] + pb[((size_t)h * AGENT + a) * NTOK + n0base + nloc];
                    }
                }
        }
    }
    __syncthreads();

    {
        for (int a = wid; a < AGENT; a += 8) {
            float m = -1e30f;
            for (int j = lane; j < NSPL; j += 32) m = fmaxf(m, L[a * AF_LSTR + j]);
#pragma unroll
            for (int o = 16; o > 0; o >>= 1) m = fmaxf(m, __shfl_xor_sync(0xffffffffu, m, o));
            float sum = 0.f;
            for (int j = lane; j < NSPL; j += 32) {
                float e = __expf(L[a * AF_LSTR + j] - m);
                L[a * AF_LSTR + j] = e;
                sum += e;
            }
#pragma unroll
            for (int o = 16; o > 0; o >>= 1) sum += __shfl_xor_sync(0xffffffffu, sum, o);
            if (lane == 0) { sm_m[a] = m; sm_s[a] = sum; }
        }
    }

    // ---- Phase 3 (fp16 mma): D[a][d] = sum_chunks P_chunk @ Vt_chunk ----
    const int mT = wid & 3;
    const int dH = wid >> 2;
    const int rA3 = mT * 16 + ((mA & 1) << 3) + (lane & 7);
    const int rB3 = dH * 32 + ((lane >> 4) << 3) + (lane & 7);
    float dacc[4][4];
#pragma unroll
    for (int nt = 0; nt < 4; nt++)
#pragma unroll
        for (int j = 0; j < 4; j++) dacc[nt][j] = 0.f;

    for (int c = 0; c < 7; c++) {
        int n0 = n0base + c * 64;
        __syncthreads();
        for (int i = tid; i < 64 * 8; i += 256) {
            int a = i >> 3, gq = i & 7;
            uint4 u = {0u, 0u, 0u, 0u};
            if (a < 49) {
                const float* lp = &L[a * AF_LSTR + c * 64 + gq * 8];
                float4 v0 = *(const float4*)lp;
                float4 v1 = *(const float4*)(lp + 4);
                u.x = pack_h2(v0.x, v0.y); u.y = pack_h2(v0.z, v0.w);
                u.z = pack_h2(v1.x, v1.y); u.w = pack_h2(v1.z, v1.w);
            }
            *(uint4*)(smc + a * 128 + ((gq ^ (a & 7)) << 4)) = u;
        }
        for (int i = tid; i < 64 * 8; i += 256) {
            int nn = i >> 3, dg = i & 7;
            uint4 u = *(const uint4*)&qkv[((size_t)b * NTOK + n0 + nn) * QKVD + 1024 + h * 64 + dg * 8];
            const __half* hp = (const __half*)&u;
            int gq2 = nn >> 3, byt = (nn & 7) * 2;
#pragma unroll
            for (int j = 0; j < 8; j++) {
                int d = dg * 8 + j;
                *(__half*)(smc + 8192 + d * 128 + ((gq2 ^ (d & 7)) << 4) + byt) = hp[j];
            }
        }
        __syncthreads();
#pragma unroll
        for (int ks = 0; ks < 4; ks++) {
            uint32_t aF[4], bF[2][4];
            {
                int c4 = (2 * ks) | c4bA;
                LDSM_X4(aF, smBase + (uint32_t)(rA3 * 128 + ((c4 ^ (rA3 & 7)) << 4)));
            }
#pragma unroll
            for (int p = 0; p < 2; p++) {
                int row = rB3 + p * 16;
                int c4 = (2 * ks) | c4bB;
                LDSM_X4(bF[p], smBase + (uint32_t)(8192 + row * 128 + ((c4 ^ (row & 7)) << 4)));
            }
#pragma unroll
            for (int p = 0; p < 2; p++) {
                mma_16x8x16h(dacc[2 * p],     aF, &bF[p][0]);
                mma_16x8x16h(dacc[2 * p + 1], aF, &bF[p][2]);
            }
        }
    }

    float* pacc = part;
    float* pms  = part + (size_t)SPLITS * 128 * AGENT * HDIM;
    {
        int a0 = mT * 16 + g;
#pragma unroll
        for (int nt = 0; nt < 4; nt++) {
            int d0 = dH * 32 + nt * 8 + 2 * tg;
            if (a0 < 49) {
                float2 v = { dacc[nt][0], dacc[nt][1] };
                *(float2*)&pacc[(((size_t)s * 128 + bh) * AGENT + a0) * HDIM + d0] = v;
            }
            if (a0 + 8 < 49) {
                float2 v = { dacc[nt][2], dacc[nt][3] };
                *(float2*)&pacc[(((size_t)s * 128 + bh) * AGENT + a0 + 8) * HDIM + d0] = v;
            }
        }
    }
    if (tid < AGENT) {
        pms[(((size_t)s * 128 + bh) * AGENT + tid) * 2 + 0] = sm_m[tid];
        pms[(((size_t)s * 128 + bh) * AGENT + tid) * 2 + 1] = sm_s[tid];
    }
}

// ---- combine splits ----
__global__ __launch_bounds__(256) void agent_combine_kernel(
    const float* __restrict__ part, float* __restrict__ av)
{
    const int bh = blockIdx.x;
    const int tid = threadIdx.x;
    const int d = tid & 63, abase = tid >> 6;
    const float* pacc = part;
    const float* pms  = part + (size_t)SPLITS * 128 * AGENT * HDIM;

    int a = abase;
#pragma unroll
    for (int i = 0; i < 13; i++) {
        if (a < 49) {
            float mstar = -1e30f;
            float ms[SPLITS], ss[SPLITS];
#pragma unroll
            for (int s = 0; s < SPLITS; s++) {
                ms[s] = pms[(((size_t)s * 128 + bh) * AGENT + a) * 2 + 0];
                ss[s] = pms[(((size_t)s * 128 + bh) * AGENT + a) * 2 + 1];
                mstar = fmaxf(mstar, ms[s]);
            }
            float S = 0.f, o = 0.f;
#pragma unroll
            for (int s = 0; s < SPLITS; s++) {
                float f = __expf(ms[s] - mstar);
                S += ss[s] * f;
                o += pacc[(((size_t)s * 128 + bh) * AGENT + a) * HDIM + d] * f;
            }
            av[((size_t)bh * AGENT + a) * HDIM + d] = o / S;
        }
        a += 4;
    }
}

// ======= q attention via fp16 tensor cores; writes fp16 into oh =======
#define QA_SMEM 52672

__global__ void __launch_bounds__(224, 2) qattn_mma(
    const __half* __restrict__ qkv, const float* __restrict__ ag,
    const float* __restrict__ av, const float* __restrict__ ab, __half* __restrict__ oh)
{
    extern __shared__ char sqc[];
    const int bh = blockIdx.y, b = bh >> 3, h = bh & 7;
    const int n0 = blockIdx.x * 112;
    const int tid = threadIdx.x, wid = tid >> 5, lane = tid & 31;
    const int g = lane >> 2, tg = lane & 3;
    const uint32_t smBase = smem_u32(sqc);
    float* ABs = (float*)(sqc + 30720);

    for (int i = tid; i < 112 * 8; i += 224) {
        int r = i >> 3, gq = i & 7;
        uint4 u = *(const uint4*)&qkv[((size_t)b * NTOK + n0 + r) * QKVD + h * 64 + gq * 8];
        *(uint4*)(sqc + r * 128 + ((gq ^ (r & 7)) << 4)) = u;
    }
    for (int i = tid; i < 64 * 8; i += 224) {
        int a = i >> 3, gq = i & 7;
        uint4 u = {0u, 0u, 0u, 0u};
        if (a < 49) {
            const float* src = &ag[((size_t)b * AGENT + a) * CDIM + h * 64 + gq * 8];
            float4 v0 = *(const float4*)src;
            float4 v1 = *(const float4*)(src + 4);
            u.x = pack_h2(v0.x * 0.125f, v0.y * 0.125f);
            u.y = pack_h2(v0.z * 0.125f, v0.w * 0.125f);
            u.z = pack_h2(v1.x * 0.125f, v1.y * 0.125f);
            u.w = pack_h2(v1.z * 0.125f, v1.w * 0.125f);
        }
        *(uint4*)(sqc + 14336 + a * 128 + ((gq ^ (a & 7)) << 4)) = u;
    }
    for (int i = tid; i < 64 * 8; i += 224) {
        int d = i >> 3, gq = i & 7;
        uint32_t uu[4];
#pragma unroll
        for (int j = 0; j < 4; j++) {
            int a0 = gq * 8 + 2 * j, a1 = a0 + 1;
            float f0 = (a0 < 49) ? av[((size_t)bh * AGENT + a0) * HDIM + d] : 0.f;
            float f1 = (a1 < 49) ? av[((size_t)bh * AGENT + a1) * HDIM + d] : 0.f;
            uu[j] = pack_h2(f0, f1);
        }
        uint4 u = { uu[0], uu[1], uu[2], uu[3] };
        *(uint4*)(sqc + 22528 + d * 128 + ((gq ^ (d & 7)) << 4)) = u;
    }
    {
        const float4* src = (const float4*)(ab + ((size_t)h * NTOK + n0) * 49);
        for (int i = tid; i < 112 * 49 / 4; i += 224) ((float4*)ABs)[i] = src[i];
    }
    __syncthreads();

    const int wm = wid * 16;
    const int mA = lane >> 3;
    const int rA = wm + ((mA & 1) << 3) + (lane & 7);
    const int c4bA = mA >> 1;
    const int rB = ((lane >> 4) << 3) + (lane & 7);
    const int c4bB = (lane >> 3) & 1;

    float acc[7][4];
#pragma unroll
    for (int nt = 0; nt < 7; nt++)
#pragma unroll
        for (int j = 0; j < 4; j++) acc[nt][j] = 0.f;

#pragma unroll
    for (int ks = 0; ks < 4; ks++) {
        uint32_t aF[4], bF[4][4];
        {
            int c4 = (2 * ks) | c4bA;
            LDSM_X4(aF, smBase + (uint32_t)(rA * 128 + ((c4 ^ (rA & 7)) << 4)));
        }
        int c4b = (2 * ks) | c4bB;
#pragma unroll
        for (int p = 0; p < 4; p++) {
            int row = p * 16 + rB;
            LDSM_X4(bF[p], smBase + (uint32_t)(14336 + row * 128 + ((c4b ^ (row & 7)) << 4)));
        }
#pragma unroll
        for (int nt = 0; nt < 7; nt++)
            mma_16x8x16h(acc[nt], aF, &bF[nt >> 1][(nt & 1) * 2]);
    }

    const int rl0 = wm + g;
    float m0 = -1e30f, m8 = -1e30f;
    float vals[7][4];
#pragma unroll
    for (int nt = 0; nt < 7; nt++) {
        int c0 = nt * 8 + 2 * tg, c1 = c0 + 1;
        float v0 = (c0 < 49) ? acc[nt][0] + ABs[rl0 * 49 + c0]       : -1e30f;
        float v1 = (c1 < 49) ? acc[nt][1] + ABs[rl0 * 49 + c1]       : -1e30f;
        float v2 = (c0 < 49) ? acc[nt][2] + ABs[(rl0 + 8) * 49 + c0] : -1e30f;
        float v3 = (c1 < 49) ? acc[nt][3] + ABs[(rl0 + 8) * 49 + c1] : -1e30f;
        vals[nt][0] = v0; vals[nt][1] = v1; vals[nt][2] = v2; vals[nt][3] = v3;
        m0 = fmaxf(m0, fmaxf(v0, v1));
        m8 = fmaxf(m8, fmaxf(v2, v3));
    }
    m0 = fmaxf(m0, __shfl_xor_sync(0xffffffffu, m0, 1));
    m0 = fmaxf(m0, __shfl_xor_sync(0xffffffffu, m0, 2));
    m8 = fmaxf(m8, __shfl_xor_sync(0xffffffffu, m8, 1));
    m8 = fmaxf(m8, __shfl_xor_sync(0xffffffffu, m8, 2));
    float s0 = 0.f, s8 = 0.f;
#pragma unroll
    for (int nt = 0; nt < 7; nt++) {
        int c0 = nt * 8 + 2 * tg, c1 = c0 + 1;
        float e0 = (c0 < 49) ? __expf(vals[nt][0] - m0) : 0.f;
        float e1 = (c1 < 49) ? __expf(vals[nt][1] - m0) : 0.f;
        float e2 = (c0 < 49) ? __expf(vals[nt][2] - m8) : 0.f;
        float e3 = (c1 < 49) ? __expf(vals[nt][3] - m8) : 0.f;
        vals[nt][0] = e0; vals[nt][1] = e1; vals[nt][2] = e2; vals[nt][3] = e3;
        s0 += e0 + e1; s8 += e2 + e3;
    }
    s0 += __shfl_xor_sync(0xffffffffu, s0, 1);
    s0 += __shfl_xor_sync(0xffffffffu, s0, 2);
    s8 += __shfl_xor_sync(0xffffffffu, s8, 1);
    s8 += __shfl_xor_sync(0xffffffffu, s8, 2);
    const float i0 = 1.0f / s0, i8 = 1.0f / s8;

#pragma unroll
    for (int nt = 0; nt < 7; nt++) {
        int c0 = nt * 8 + 2 * tg;
        int gq = c0 >> 3, byt = (c0 & 7) * 2;
        uint32_t o0 = rl0 * 128 + ((gq ^ (rl0 & 7)) << 4) + byt;
        uint32_t o8 = (rl0 + 8) * 128 + ((gq ^ ((rl0 + 8) & 7)) << 4) + byt;
        *(uint32_t*)(sqc + o0) = pack_h2(vals[nt][0] * i0, vals[nt][1] * i0);
        *(uint32_t*)(sqc + o8) = pack_h2(vals[nt][2] * i8, vals[nt][3] * i8);
    }
    __syncwarp();

    float ao[8][4];
#pragma unroll
    for (int nt = 0; nt < 8; nt++)
#pragma unroll
        for (int j = 0; j < 4; j++) ao[nt][j] = 0.f;

#pragma unroll
    for (int ks = 0; ks < 4; ks++) {
        uint32_t aF[4], bF[4][4];
        {
            int c4 = (2 * ks) | c4bA;
            LDSM_X4(aF, smBase + (uint32_t)(rA * 128 + ((c4 ^ (rA & 7)) << 4)));
        }
        int c4b = (2 * ks) | c4bB;
#pragma unroll
        for (int p = 0; p < 4; p++) {
            int row = p * 16 + rB;
            LDSM_X4(bF[p], smBase + (uint32_t)(22528 + row * 128 + ((c4b ^ (row & 7)) << 4)));
        }
#pragma unroll
        for (int nt = 0; nt < 8; nt++)
            mma_16x8x16h(ao[nt], aF, &bF[nt >> 1][(nt & 1) * 2]);
    }

    const size_t row0 = (size_t)b * NTOK + n0 + rl0;
#pragma unroll
    for (int nt = 0; nt < 8; nt++) {
        int col = nt * 8 + 2 * tg;
        *(uint32_t*)&oh[row0 * 512 + h * 64 + col] = pack_h2(ao[nt][0], ao[nt][1]);
        *(uint32_t*)&oh[(row0 + 8) * 512 + h * 64 + col] = pack_h2(ao[nt][2], ao[nt][3]);
    }
}

// ------- depthwise 3x3 conv, rolling-column: thread owns (b, x, c), walks y -------
// grid (WW, BATCH), 512 threads (c). 3 new LDG per output instead of 9.
__global__ __launch_bounds__(512) void dwc_kernel(
    const __half* __restrict__ qkv, const float* __restrict__ w,
    const float* __restrict__ bias, __half* __restrict__ oh)
{
    const int c = threadIdx.x;
    const int x = blockIdx.x;
    const int b = blockIdx.y;
    const float bz = bias[c];
    float w00 = w[c * 9 + 0], w01 = w[c * 9 + 1], w02 = w[c * 9 + 2];
    float w10 = w[c * 9 + 3], w11 = w[c * 9 + 4], w12 = w[c * 9 + 5];
    float w20 = w[c * 9 + 6], w21 = w[c * 9 + 7], w22 = w[c * 9 + 8];
    const bool xm = (x > 0), xp = (x < WW - 1);

    const __half* vb = qkv + (size_t)b * NTOK * QKVD + 1024 + c;
    __half* ob = oh + (size_t)b * NTOK * CDIM + c;

    // rolling rows: r0 = y-1, r1 = y, r2 = y+1 (each 3 taps: x-1, x, x+1)
    float r0l = 0.f, r0c = 0.f, r0r = 0.f;
    float r1l, r1c, r1r, r2l, r2c, r2r;
    // y = 0 row
    r1c = __half2float(vb[(size_t)(0 * WW + x) * QKVD]);
    r1l = xm ? __half2float(vb[(size_t)(0 * WW + x - 1) * QKVD]) : 0.f;
    r1r = xp ? __half2float(vb[(size_t)(0 * WW + x + 1) * QKVD]) : 0.f;

    for (int y = 0; y < HH; y++) {
        if (y + 1 < HH) {
            r2c = __half2float(vb[(size_t)((y + 1) * WW + x) * QKVD]);
            r2l = xm ? __half2float(vb[(size_t)((y + 1) * WW + x - 1) * QKVD]) : 0.f;
            r2r = xp ? __half2float(vb[(size_t)((y + 1) * WW + x + 1) * QKVD]) : 0.f;
        } else { r2l = r2c = r2r = 0.f; }

        float acc = bz
            + w00 * r0l + w01 * r0c + w02 * r0r
            + w10 * r1l + w11 * r1c + w12 * r1r
            + w20 * r2l + w21 * r2c + w22 * r2r;

        size_t idx = (size_t)(y * WW + x) * CDIM;
        ob[idx] = __float2half_rn(__half2float(ob[idx]) + acc);

        r0l = r1l; r0c = r1c; r0r = r1r;
        r1l = r2l; r1c = r2c; r1r = r2r;
    }
}

// ---------------- launch ----------------
extern "C" void kernel_launch(void* const* d_in, const int* in_sizes, int n_in,
                              void* d_out, int out_size)
{
    const float* x      = (const float*)d_in[0];
    const float* q_w    = (const float*)d_in[3];
    const float* kv_w   = (const float*)d_in[4];
    const float* proj_w = (const float*)d_in[5];
    const float* proj_b = (const float*)d_in[6];
    const float* dwc_w  = (const float*)d_in[7];
    const float* dwc_b  = (const float*)d_in[8];
    const float* an_b   = (const float*)d_in[9];
    const float* na_b   = (const float*)d_in[10];
    const float* ah_b   = (const float*)d_in[11];
    const float* aw_b   = (const float*)d_in[12];
    const float* ha_b   = (const float*)d_in[13];
    const float* wa_b   = (const float*)d_in[14];
    float* out = (float*)d_out;

    float *prt, *agp, *avp, *pbp, *abp;
    __half *qkvh, *xh, *oh, *wh;
    cudaGetSymbolAddress((void**)&qkvh, g_qkv);
    cudaGetSymbolAddress((void**)&xh,  g_xh);
    cudaGetSymbolAddress((void**)&oh,  g_oh);
    cudaGetSymbolAddress((void**)&wh,  g_wh);
    cudaGetSymbolAddress((void**)&prt, g_part);
    cudaGetSymbolAddress((void**)&agp, g_agent);
    cudaGetSymbolAddress((void**)&avp, g_agentv);
    cudaGetSymbolAddress((void**)&pbp, g_pb);
    cudaGetSymbolAddress((void**)&abp, g_ab);

    cudaFuncSetAttribute(mma_gemm, cudaFuncAttributeMaxDynamicSharedMemorySize, GEMM_SMEM);
    cudaFuncSetAttribute(agent_fused_kernel, cudaFuncAttributeMaxDynamicSharedMemorySize, AF_SMEM);
    cudaFuncSetAttribute(qattn_mma, cudaFuncAttributeMaxDynamicSharedMemorySize, QA_SMEM);

    // launch 0: x -> fp16
    {
        int n4 = MALL * CDIM / 4;
        f16_conv_kernel<<<(n4 + 255) / 256, 256>>>(x, xh, n4);
    }
    // launch 1: all weights -> fp16 (single launch)
    {
        int w4tot = 4 * CDIM * CDIM / 4;
        f16_conv_w_kernel<<<(w4tot + 255) / 256, 256>>>(q_w, kv_w, proj_w, wh);
    }
    // launch 2: bias precompute (independent of GEMM)
    bias_kernel<<<HEADS * AGENT, 256>>>(an_b, na_b, ah_b, aw_b, ha_b, wa_b, pbp, abp);

    // launch 3 (profiled): merged q|k|v projection, N = 1536, fp16 output
    mma_gemm<<<dim3(QKVD / 128, MALL / 128), 256, GEMM_SMEM>>>(xh, wh, nullptr, qkvh, nullptr, QKVD);

    pool_kernel<<<BATCH * AGENT, CDIM>>>(qkvh, agp);

    agent_fused_kernel<<<dim3(SPLITS, BATCH * HEADS), 256, AF_SMEM>>>(agp, qkvh, pbp, prt);
    agent_combine_kernel<<<BATCH * HEADS, 256>>>(prt, avp);

    qattn_mma<<<dim3(28, BATCH * HEADS), 224, QA_SMEM>>>(qkvh, agp, avp, abp, oh);
    dwc_kernel<<<dim3(WW, BATCH), CDIM>>>(qkvh, dwc_w, dwc_b, oh);

    // final projection: fp32 output + bias
    mma_gemm<<<dim3(CDIM / 128, MALL / 128), 256, GEMM_SMEM>>>(oh, wh + 3 * CDIM * CDIM, out, nullptr, proj_b, CDIM);
}